// round 1
// baseline (speedup 1.0000x reference)
#include <cuda_runtime.h>
#include <math.h>

// Problem constants
#define BB 16
#define CC 512
#define HW 4096
#define KK 64
#define SPLIT 8   // M-step split-K factor

// ---------------------------------------------------------------------------
// Scratch (device globals: allocation-guard safe)
// ---------------------------------------------------------------------------
__device__ float g_buf1[BB * CC * HW];          // xf (conv1 out), later x2 (conv2 out)
__device__ float g_buf2[BB * CC * HW];          // xr (reconstruction)
__device__ float g_z[BB * HW * KK];             // z  [b][n][k]
__device__ float g_mu[BB * CC * KK];            // mu [b][c][k]
__device__ float g_mu_part[BB * SPLIT * CC * KK]; // split-K partials [b][s][c][k]
__device__ float g_scale[CC];
__device__ float g_shift[CC];

// ---------------------------------------------------------------------------
// Replicate initial mu (1,C,K) -> (B,C,K)
// ---------------------------------------------------------------------------
__global__ void copymu_kernel(const float* __restrict__ mu_in) {
    int b = blockIdx.y;
    int i = blockIdx.x * 256 + threadIdx.x;     // i < C*K = 32768
    g_mu[(size_t)b * CC * KK + i] = mu_in[i];
}

// ---------------------------------------------------------------------------
// conv GEMM: Y[b,m,n] = sum_c W[m,c] * X[b,c,n] (+ bias[m])
// BM=BN=128, BK=16, 256 threads, 8x8 per thread.
// use_internal_src: X = g_buf2 (conv2), else external x (conv1). Y = g_buf1.
// ---------------------------------------------------------------------------
__global__ __launch_bounds__(256) void conv_gemm_kernel(
    const float* __restrict__ W, const float* __restrict__ Xext,
    const float* __restrict__ bias, int use_internal_src)
{
    const int b  = blockIdx.z;
    const int m0 = blockIdx.y * 128;
    const int n0 = blockIdx.x * 128;
    const int tid = threadIdx.x;
    const int ty = tid >> 4, tx = tid & 15;

    __shared__ float As[16][129];   // [k][m], padded
    __shared__ float Bs[16][128];   // [k][n]

    const float* Xb = (use_internal_src ? g_buf2 : Xext) + (size_t)b * CC * HW;
    float acc[8][8];
#pragma unroll
    for (int i = 0; i < 8; i++)
#pragma unroll
        for (int j = 0; j < 8; j++) acc[i][j] = 0.f;

    for (int k0 = 0; k0 < CC; k0 += 16) {
        // load A tile 128x16 (transposed into As[k][m])
        {
            int row  = tid >> 2;            // 0..63
            int col4 = (tid & 3) * 4;       // 0,4,8,12
#pragma unroll
            for (int p = 0; p < 2; p++) {
                int m = row + p * 64;
                float4 v = *reinterpret_cast<const float4*>(&W[(size_t)(m0 + m) * CC + k0 + col4]);
                As[col4 + 0][m] = v.x; As[col4 + 1][m] = v.y;
                As[col4 + 2][m] = v.z; As[col4 + 3][m] = v.w;
            }
        }
        // load B tile 16x128
        {
            int row  = tid >> 5;            // 0..7
            int col4 = (tid & 31) * 4;
#pragma unroll
            for (int p = 0; p < 2; p++) {
                int kk = row + p * 8;
                *reinterpret_cast<float4*>(&Bs[kk][col4]) =
                    *reinterpret_cast<const float4*>(&Xb[(size_t)(k0 + kk) * HW + n0 + col4]);
            }
        }
        __syncthreads();
#pragma unroll
        for (int kk = 0; kk < 16; kk++) {
            float a[8], bb[8];
#pragma unroll
            for (int i = 0; i < 8; i++) a[i]  = As[kk][ty * 8 + i];
#pragma unroll
            for (int j = 0; j < 8; j++) bb[j] = Bs[kk][tx * 8 + j];
#pragma unroll
            for (int i = 0; i < 8; i++)
#pragma unroll
                for (int j = 0; j < 8; j++) acc[i][j] = fmaf(a[i], bb[j], acc[i][j]);
        }
        __syncthreads();
    }

    float* Yb = g_buf1 + (size_t)b * CC * HW;
#pragma unroll
    for (int i = 0; i < 8; i++) {
        int m = m0 + ty * 8 + i;
        float bv = bias ? bias[m] : 0.f;
#pragma unroll
        for (int j = 0; j < 8; j += 4) {
            float4 v;
            v.x = acc[i][j + 0] + bv; v.y = acc[i][j + 1] + bv;
            v.z = acc[i][j + 2] + bv; v.w = acc[i][j + 3] + bv;
            *reinterpret_cast<float4*>(&Yb[(size_t)m * HW + n0 + tx * 8 + j]) = v;
        }
    }
}

// ---------------------------------------------------------------------------
// E-step: logits[n,k] = sum_c xf[c,n]*mu[c,k]; z = softmax_k(logits)
// One block: 64 n-rows x 64 k for one batch. 256 threads, 4x4 per thread.
// ---------------------------------------------------------------------------
__global__ __launch_bounds__(256) void estep_kernel() {
    const int b  = blockIdx.y;
    const int n0 = blockIdx.x * 64;
    const int tid = threadIdx.x;
    const int ty = tid >> 4, tx = tid & 15;

    __shared__ float xs_s[32][64];
    __shared__ float mu_s[32][64];
    __shared__ float L[64][65];

    const float* xfb = g_buf1 + (size_t)b * CC * HW;
    const float* mub = g_mu  + (size_t)b * CC * KK;

    float acc[4][4];
#pragma unroll
    for (int i = 0; i < 4; i++)
#pragma unroll
        for (int j = 0; j < 4; j++) acc[i][j] = 0.f;

    for (int c0 = 0; c0 < CC; c0 += 32) {
        int row  = tid >> 4;          // 0..15
        int col4 = (tid & 15) * 4;
#pragma unroll
        for (int p = 0; p < 2; p++) {
            int r = row + p * 16;
            *reinterpret_cast<float4*>(&xs_s[r][col4]) =
                *reinterpret_cast<const float4*>(&xfb[(size_t)(c0 + r) * HW + n0 + col4]);
            *reinterpret_cast<float4*>(&mu_s[r][col4]) =
                *reinterpret_cast<const float4*>(&mub[(size_t)(c0 + r) * KK + col4]);
        }
        __syncthreads();
#pragma unroll
        for (int kk = 0; kk < 32; kk++) {
            float a[4], bb[4];
#pragma unroll
            for (int i = 0; i < 4; i++) a[i]  = xs_s[kk][ty * 4 + i];
#pragma unroll
            for (int j = 0; j < 4; j++) bb[j] = mu_s[kk][tx * 4 + j];
#pragma unroll
            for (int i = 0; i < 4; i++)
#pragma unroll
                for (int j = 0; j < 4; j++) acc[i][j] = fmaf(a[i], bb[j], acc[i][j]);
        }
        __syncthreads();
    }

#pragma unroll
    for (int i = 0; i < 4; i++)
#pragma unroll
        for (int j = 0; j < 4; j++) L[ty * 4 + i][tx * 4 + j] = acc[i][j];
    __syncthreads();

    // softmax over k (64), one warp per 8 rows
    const int warp = tid >> 5, lane = tid & 31;
    for (int r = warp * 8; r < warp * 8 + 8; r++) {
        float v0 = L[r][lane], v1 = L[r][lane + 32];
        float m = fmaxf(v0, v1);
#pragma unroll
        for (int off = 16; off > 0; off >>= 1)
            m = fmaxf(m, __shfl_xor_sync(0xffffffffu, m, off));
        float e0 = expf(v0 - m), e1 = expf(v1 - m);
        float s = e0 + e1;
#pragma unroll
        for (int off = 16; off > 0; off >>= 1)
            s += __shfl_xor_sync(0xffffffffu, s, off);
        float inv = 1.f / s;
        float* zr = g_z + (size_t)b * HW * KK + (size_t)(n0 + r) * KK;
        zr[lane]      = e0 * inv;
        zr[lane + 32] = e1 * inv;
    }
}

// ---------------------------------------------------------------------------
// M-step (split-K): mu_part[b,s,c,k] = sum_{n in split s} xf[c,n]*z[n,k]
// grid (C/64, SPLIT, B), 256 threads, 4x4 per thread.
// ---------------------------------------------------------------------------
__global__ __launch_bounds__(256) void mstep_kernel() {
    const int b  = blockIdx.z;
    const int s  = blockIdx.y;
    const int c0 = blockIdx.x * 64;
    const int tid = threadIdx.x;
    const int ty = tid >> 4, tx = tid & 15;

    __shared__ float xT[64][65];   // [n][c]
    __shared__ float zs[64][64];   // [n][k]

    const float* xfb = g_buf1 + (size_t)b * CC * HW;
    const float* zb  = g_z    + (size_t)b * HW * KK;

    float acc[4][4];
#pragma unroll
    for (int i = 0; i < 4; i++)
#pragma unroll
        for (int j = 0; j < 4; j++) acc[i][j] = 0.f;

    const int nbeg = s * (HW / SPLIT), nend = nbeg + (HW / SPLIT);
    for (int n0 = nbeg; n0 < nend; n0 += 64) {
        int row  = tid >> 4;          // 0..15
        int col4 = (tid & 15) * 4;
#pragma unroll
        for (int p = 0; p < 4; p++) {
            int r = row + p * 16;
            float4 v = *reinterpret_cast<const float4*>(&xfb[(size_t)(c0 + r) * HW + n0 + col4]);
            xT[col4 + 0][r] = v.x; xT[col4 + 1][r] = v.y;
            xT[col4 + 2][r] = v.z; xT[col4 + 3][r] = v.w;
            *reinterpret_cast<float4*>(&zs[r][col4]) =
                *reinterpret_cast<const float4*>(&zb[(size_t)(n0 + r) * KK + col4]);
        }
        __syncthreads();
#pragma unroll
        for (int nn = 0; nn < 64; nn++) {
            float a[4], bb[4];
#pragma unroll
            for (int i = 0; i < 4; i++) a[i]  = xT[nn][ty * 4 + i];
#pragma unroll
            for (int j = 0; j < 4; j++) bb[j] = zs[nn][tx * 4 + j];
#pragma unroll
            for (int i = 0; i < 4; i++)
#pragma unroll
                for (int j = 0; j < 4; j++) acc[i][j] = fmaf(a[i], bb[j], acc[i][j]);
        }
        __syncthreads();
    }

    float* outp = g_mu_part + ((size_t)b * SPLIT + s) * CC * KK;
#pragma unroll
    for (int i = 0; i < 4; i++) {
        float4 v; v.x = acc[i][0]; v.y = acc[i][1]; v.z = acc[i][2]; v.w = acc[i][3];
        *reinterpret_cast<float4*>(&outp[(size_t)(c0 + ty * 4 + i) * KK + tx * 4]) = v;
    }
}

// ---------------------------------------------------------------------------
// Reduce split-K partials + l2-normalize column k of batch b over c.
// (colsum normalization of z_ cancels in the l2norm: scale invariance)
// grid = B*K blocks, 128 threads.
// ---------------------------------------------------------------------------
__global__ void reduce_l2norm_kernel(float* __restrict__ out_mu) {
    const int bk = blockIdx.x;
    const int b = bk >> 6, k = bk & 63;
    const int tid = threadIdx.x;

    float* mub = g_mu + (size_t)b * CC * KK;
    const float* part = g_mu_part + (size_t)b * SPLIT * CC * KK;

    float s2 = 0.f;
    for (int c = tid; c < CC; c += 128) {
        float v = 0.f;
#pragma unroll
        for (int s = 0; s < SPLIT; s++)
            v += part[(size_t)s * CC * KK + (size_t)c * KK + k];
        mub[(size_t)c * KK + k] = v;
        s2 += v * v;
    }
    __shared__ float red[128];
    red[tid] = s2; __syncthreads();
    for (int st = 64; st > 0; st >>= 1) {
        if (tid < st) red[tid] += red[tid + st];
        __syncthreads();
    }
    float scale = 1.f / (1e-6f + sqrtf(red[0]));
    for (int c = tid; c < CC; c += 128) {
        float v = mub[(size_t)c * KK + k] * scale;
        mub[(size_t)c * KK + k] = v;
        if (out_mu) out_mu[(size_t)b * CC * KK + (size_t)c * KK + k] = v;
    }
}

// ---------------------------------------------------------------------------
// Reconstruction: xr[c,n] = relu( sum_k mu[c,k]*z[n,k] )
// grid (C/64, HW/64, B), 256 threads, 4x4 per thread, full K=64 in one pass.
// ---------------------------------------------------------------------------
__global__ __launch_bounds__(256) void recon_kernel() {
    const int b  = blockIdx.z;
    const int c0 = blockIdx.x * 64;
    const int n0 = blockIdx.y * 64;
    const int tid = threadIdx.x;
    const int ty = tid >> 4, tx = tid & 15;

    __shared__ float muT[64][65];  // [k][c]
    __shared__ float zT[64][65];   // [k][n]

    const float* mub = g_mu + (size_t)b * CC * KK;
    const float* zb  = g_z  + (size_t)b * HW * KK;

    {
        int row  = tid >> 4;
        int col4 = (tid & 15) * 4;
#pragma unroll
        for (int p = 0; p < 4; p++) {
            int r = row + p * 16;
            float4 vm = *reinterpret_cast<const float4*>(&mub[(size_t)(c0 + r) * KK + col4]);
            muT[col4 + 0][r] = vm.x; muT[col4 + 1][r] = vm.y;
            muT[col4 + 2][r] = vm.z; muT[col4 + 3][r] = vm.w;
            float4 vz = *reinterpret_cast<const float4*>(&zb[(size_t)(n0 + r) * KK + col4]);
            zT[col4 + 0][r] = vz.x; zT[col4 + 1][r] = vz.y;
            zT[col4 + 2][r] = vz.z; zT[col4 + 3][r] = vz.w;
        }
    }
    __syncthreads();

    float acc[4][4];
#pragma unroll
    for (int i = 0; i < 4; i++)
#pragma unroll
        for (int j = 0; j < 4; j++) acc[i][j] = 0.f;

#pragma unroll
    for (int kk = 0; kk < 64; kk++) {
        float a[4], bb[4];
#pragma unroll
        for (int i = 0; i < 4; i++) a[i]  = muT[kk][ty * 4 + i];
#pragma unroll
        for (int j = 0; j < 4; j++) bb[j] = zT[kk][tx * 4 + j];
#pragma unroll
        for (int i = 0; i < 4; i++)
#pragma unroll
            for (int j = 0; j < 4; j++) acc[i][j] = fmaf(a[i], bb[j], acc[i][j]);
    }

    float* xrb = g_buf2 + (size_t)b * CC * HW;
#pragma unroll
    for (int i = 0; i < 4; i++) {
        float4 v;
        v.x = fmaxf(acc[i][0], 0.f); v.y = fmaxf(acc[i][1], 0.f);
        v.z = fmaxf(acc[i][2], 0.f); v.w = fmaxf(acc[i][3], 0.f);
        *reinterpret_cast<float4*>(&xrb[(size_t)(c0 + ty * 4 + i) * HW + n0 + tx * 4]) = v;
    }
}

// ---------------------------------------------------------------------------
// BatchNorm statistics: one block per channel. scale/shift folded.
// ---------------------------------------------------------------------------
__global__ void bn_stats_kernel(const float* __restrict__ gamma,
                                const float* __restrict__ beta) {
    const int o = blockIdx.x;
    const int tid = threadIdx.x;   // 256
    float s = 0.f, s2 = 0.f;
    for (int b = 0; b < BB; b++) {
        const float* p = g_buf1 + (size_t)b * CC * HW + (size_t)o * HW;
        for (int n = tid; n < HW; n += 256) {
            float v = p[n];
            s += v; s2 = fmaf(v, v, s2);
        }
    }
    __shared__ float r1[256], r2[256];
    r1[tid] = s; r2[tid] = s2; __syncthreads();
    for (int st = 128; st > 0; st >>= 1) {
        if (tid < st) { r1[tid] += r1[tid + st]; r2[tid] += r2[tid + st]; }
        __syncthreads();
    }
    if (tid == 0) {
        const float invM = 1.f / (float)(BB * HW);
        float mean = r1[0] * invM;
        float var  = r2[0] * invM - mean * mean;
        float sc = gamma[o] * rsqrtf(var + 1e-5f);
        g_scale[o] = sc;
        g_shift[o] = beta[o] - mean * sc;
    }
}

// ---------------------------------------------------------------------------
// Final: out = relu(x2*scale + shift + x)
// ---------------------------------------------------------------------------
__global__ void final_kernel(const float* __restrict__ x, float* __restrict__ out) {
    const int b = blockIdx.z, o = blockIdx.y;
    const size_t base = (size_t)b * CC * HW + (size_t)o * HW
                      + (size_t)blockIdx.x * 1024 + (size_t)threadIdx.x * 4;
    const float sc = g_scale[o], sh = g_shift[o];
    float4 v2 = *reinterpret_cast<const float4*>(&g_buf1[base]);
    float4 vx = *reinterpret_cast<const float4*>(&x[base]);
    float4 r;
    r.x = fmaxf(fmaf(v2.x, sc, sh) + vx.x, 0.f);
    r.y = fmaxf(fmaf(v2.y, sc, sh) + vx.y, 0.f);
    r.z = fmaxf(fmaf(v2.z, sc, sh) + vx.z, 0.f);
    r.w = fmaxf(fmaf(v2.w, sc, sh) + vx.w, 0.f);
    *reinterpret_cast<float4*>(&out[base]) = r;
}

// ---------------------------------------------------------------------------
// Transpose z [b][n][k] -> z_t [b][k][n]
// ---------------------------------------------------------------------------
__global__ void zt_kernel(float* __restrict__ zt) {
    const int b  = blockIdx.z;
    const int n0 = blockIdx.x * 32;
    const int k0 = blockIdx.y * 32;
    __shared__ float t[32][33];
    const int tx = threadIdx.x, ty = threadIdx.y; // 32 x 8
    const float* zb = g_z + (size_t)b * HW * KK;
#pragma unroll
    for (int c = 0; c < 32; c += 8)
        t[ty + c][tx] = zb[(size_t)(n0 + ty + c) * KK + k0 + tx];
    __syncthreads();
    float* ztb = zt + (size_t)b * KK * HW;
#pragma unroll
    for (int c = 0; c < 32; c += 8)
        ztb[(size_t)(k0 + ty + c) * HW + n0 + tx] = t[tx][ty + c];
}

// ---------------------------------------------------------------------------
// Launch
// ---------------------------------------------------------------------------
extern "C" void kernel_launch(void* const* d_in, const int* in_sizes, int n_in,
                              void* d_out, int out_size) {
    const float* x     = (const float*)d_in[0];
    const float* w1    = (const float*)d_in[1];
    const float* b1    = (const float*)d_in[2];
    const float* w2    = (const float*)d_in[3];
    const float* gamma = (const float*)d_in[4];
    const float* beta  = (const float*)d_in[5];
    const float* mu_in = (const float*)d_in[6];

    float* out    = (float*)d_out;
    float* out_mu = out + (size_t)BB * CC * HW;
    float* out_zt = out_mu + (size_t)BB * CC * KK;

    // replicate initial mu
    copymu_kernel<<<dim3(CC * KK / 256, BB), 256>>>(mu_in);

    // conv1: xf = w1 @ x + b1   -> g_buf1
    conv_gemm_kernel<<<dim3(HW / 128, CC / 128, BB), 256>>>(w1, x, b1, 0);

    // EM loop (3 stages)
    for (int s = 0; s < 3; s++) {
        estep_kernel<<<dim3(HW / 64, BB), 256>>>();
        mstep_kernel<<<dim3(CC / 64, SPLIT, BB), 256>>>();
        reduce_l2norm_kernel<<<BB * KK, 128>>>(s == 2 ? out_mu : nullptr);
    }

    // reconstruction + relu -> g_buf2
    recon_kernel<<<dim3(CC / 64, HW / 64, BB), 256>>>();

    // conv2: x2 = w2 @ xr -> g_buf1
    conv_gemm_kernel<<<dim3(HW / 128, CC / 128, BB), 256>>>(w2, nullptr, nullptr, 1);

    // BN stats + final residual relu
    bn_stats_kernel<<<CC, 256>>>(gamma, beta);
    final_kernel<<<dim3(HW / 1024, CC, BB), 256>>>(x, out);

    // z transpose output
    zt_kernel<<<dim3(HW / 32, KK / 32, BB), dim3(32, 8)>>>(out_zt);
}

// round 2
// speedup vs baseline: 1.5092x; 1.5092x over previous
#include <cuda_runtime.h>
#include <cuda_bf16.h>
#include <cstdint>
#include <math.h>

// Problem constants
#define BB 16
#define CC 512
#define HW 4096
#define KK 64
#define SPLIT 8   // M-step split-K factor

// ---------------------------------------------------------------------------
// Scratch (device globals: allocation-guard safe)
// ---------------------------------------------------------------------------
__device__ float g_buf1[BB * CC * HW];            // xf (conv1 out) / x2 (conv2 out), fp32
__device__ float g_z[BB * HW * KK];               // z  [b][n][k]
__device__ float g_mu[BB * CC * KK];              // mu [b][c][k]
__device__ float g_mu_part[BB * SPLIT * CC * KK]; // split-K partials
__device__ float g_scale[CC];
__device__ float g_shift[CC];

// bf16 split operands for tensor-core conv GEMMs
__device__ __nv_bfloat16 g_w1hi[CC * CC], g_w1lo[CC * CC];
__device__ __nv_bfloat16 g_w2hi[CC * CC], g_w2lo[CC * CC];
__device__ __nv_bfloat16 g_xhi[BB * CC * HW],  g_xlo[BB * CC * HW];   // input x split
__device__ __nv_bfloat16 g_xrhi[BB * CC * HW], g_xrlo[BB * CC * HW];  // recon split

// ---------------------------------------------------------------------------
// PTX helpers
// ---------------------------------------------------------------------------
__device__ __forceinline__ uint32_t smem_u32(const void* p) {
    return (uint32_t)__cvta_generic_to_shared(p);
}
__device__ __forceinline__ void cp_async16(uint32_t saddr, const void* gaddr) {
    asm volatile("cp.async.cg.shared.global [%0], [%1], 16;" :: "r"(saddr), "l"(gaddr));
}
__device__ __forceinline__ void ldsm_x4(uint32_t& r0, uint32_t& r1, uint32_t& r2, uint32_t& r3, uint32_t a) {
    asm volatile("ldmatrix.sync.aligned.m8n8.x4.shared.b16 {%0,%1,%2,%3}, [%4];"
                 : "=r"(r0), "=r"(r1), "=r"(r2), "=r"(r3) : "r"(a));
}
__device__ __forceinline__ void ldsm_x4_t(uint32_t& r0, uint32_t& r1, uint32_t& r2, uint32_t& r3, uint32_t a) {
    asm volatile("ldmatrix.sync.aligned.m8n8.x4.trans.shared.b16 {%0,%1,%2,%3}, [%4];"
                 : "=r"(r0), "=r"(r1), "=r"(r2), "=r"(r3) : "r"(a));
}
__device__ __forceinline__ void mma_bf16(float* c, uint32_t a0, uint32_t a1, uint32_t a2, uint32_t a3,
                                         uint32_t b0, uint32_t b1) {
    asm volatile("mma.sync.aligned.m16n8k16.row.col.f32.bf16.bf16.f32 "
                 "{%0,%1,%2,%3}, {%4,%5,%6,%7}, {%8,%9}, {%0,%1,%2,%3};"
                 : "+f"(c[0]), "+f"(c[1]), "+f"(c[2]), "+f"(c[3])
                 : "r"(a0), "r"(a1), "r"(a2), "r"(a3), "r"(b0), "r"(b1));
}
__device__ __forceinline__ void split_val(float v, __nv_bfloat16& h, __nv_bfloat16& l) {
    h = __float2bfloat16(v);
    l = __float2bfloat16(v - __bfloat162float(h));
}

// ---------------------------------------------------------------------------
// Split conversions
// ---------------------------------------------------------------------------
__global__ void split_w_kernel(const float* __restrict__ w1, const float* __restrict__ w2) {
    int i = blockIdx.x * 256 + threadIdx.x;   // over CC*CC
    split_val(w1[i], g_w1hi[i], g_w1lo[i]);
    split_val(w2[i], g_w2hi[i], g_w2lo[i]);
}
__global__ void split_x_kernel(const float* __restrict__ x) {
    size_t i = ((size_t)blockIdx.x * 256 + threadIdx.x) * 4;
    float4 v = *reinterpret_cast<const float4*>(&x[i]);
    __nv_bfloat16 h0, h1, h2, h3, l0, l1, l2, l3;
    split_val(v.x, h0, l0); split_val(v.y, h1, l1);
    split_val(v.z, h2, l2); split_val(v.w, h3, l3);
    *reinterpret_cast<__nv_bfloat162*>(&g_xhi[i])     = __nv_bfloat162{h0, h1};
    *reinterpret_cast<__nv_bfloat162*>(&g_xhi[i + 2]) = __nv_bfloat162{h2, h3};
    *reinterpret_cast<__nv_bfloat162*>(&g_xlo[i])     = __nv_bfloat162{l0, l1};
    *reinterpret_cast<__nv_bfloat162*>(&g_xlo[i + 2]) = __nv_bfloat162{l2, l3};
}

// ---------------------------------------------------------------------------
// Replicate initial mu (1,C,K) -> (B,C,K)
// ---------------------------------------------------------------------------
__global__ void copymu_kernel(const float* __restrict__ mu_in) {
    int b = blockIdx.y;
    int i = blockIdx.x * 256 + threadIdx.x;
    g_mu[(size_t)b * CC * KK + i] = mu_in[i];
}

// ---------------------------------------------------------------------------
// Tensor-core conv GEMM (bf16 split, 3 passes: Ah*Bh + Al*Bh + Ah*Bl)
// Y[b,m,n] = sum_c W[m,c]*X[b,c,n] (+bias), Y fp32 -> g_buf1
// Block 128x128, BK=32, 256 thr, 8 warps (2x4), mma m16n8k16.
// ---------------------------------------------------------------------------
#define APITCH 40
#define BPITCH 136
__global__ __launch_bounds__(256) void conv_mma_kernel(const float* __restrict__ bias, int sel /*0:conv1 1:conv2*/) {
    const int b  = blockIdx.z;
    const int m0 = blockIdx.y * 128;
    const int n0 = blockIdx.x * 128;
    const int tid  = threadIdx.x;
    const int lane = tid & 31;
    const int wid  = tid >> 5;
    const int wm   = (wid & 1) * 64;   // warp m offset
    const int wn   = (wid >> 1) * 32;  // warp n offset

    __shared__ __nv_bfloat16 As[2][128 * APITCH];
    __shared__ __nv_bfloat16 Bs[2][32 * BPITCH];

    const __nv_bfloat16* Whi = sel ? g_w2hi : g_w1hi;
    const __nv_bfloat16* Wlo = sel ? g_w2lo : g_w1lo;
    const __nv_bfloat16* Xhi = (sel ? g_xrhi : g_xhi) + (size_t)b * CC * HW;
    const __nv_bfloat16* Xlo = (sel ? g_xrlo : g_xlo) + (size_t)b * CC * HW;

    float acc[4][4][4];
#pragma unroll
    for (int i = 0; i < 4; i++)
#pragma unroll
        for (int j = 0; j < 4; j++)
#pragma unroll
            for (int q = 0; q < 4; q++) acc[i][j][q] = 0.f;

    const uint32_t sA0 = smem_u32(As[0]);
    const uint32_t sB0 = smem_u32(Bs[0]);
    const uint32_t sAsz = 128 * APITCH * 2;
    const uint32_t sBsz = 32 * BPITCH * 2;

    // per-thread load slots
    const int aq0 = tid, aq1 = tid + 256;          // A: 512 chunks of 16B
    const int ar0 = aq0 >> 2, ac0 = (aq0 & 3) * 8;
    const int ar1 = aq1 >> 2, ac1 = (aq1 & 3) * 8;
    const int br0 = aq0 >> 4, bc0 = (aq0 & 15) * 8; // B: 512 chunks
    const int br1 = aq1 >> 4, bc1 = (aq1 & 15) * 8;

    const int NT = 48;  // 3 passes * 16 k-tiles

#define LOAD_TILE(IT, BUF) do {                                                   \
        int pass = (IT) >> 4, kt = (IT) & 15, k0 = kt * 32;                       \
        const __nv_bfloat16* Ap = (pass == 1) ? Wlo : Whi;                        \
        const __nv_bfloat16* Bp = (pass == 2) ? Xlo : Xhi;                        \
        uint32_t sa = sA0 + (BUF) * sAsz, sb = sB0 + (BUF) * sBsz;                \
        cp_async16(sa + (ar0 * APITCH + ac0) * 2, Ap + (size_t)(m0 + ar0) * CC + k0 + ac0); \
        cp_async16(sa + (ar1 * APITCH + ac1) * 2, Ap + (size_t)(m0 + ar1) * CC + k0 + ac1); \
        cp_async16(sb + (br0 * BPITCH + bc0) * 2, Bp + (size_t)(k0 + br0) * HW + n0 + bc0); \
        cp_async16(sb + (br1 * BPITCH + bc1) * 2, Bp + (size_t)(k0 + br1) * HW + n0 + bc1); \
        asm volatile("cp.async.commit_group;");                                   \
    } while (0)

    LOAD_TILE(0, 0);

    for (int it = 0; it < NT; ++it) {
        if (it + 1 < NT) {
            LOAD_TILE(it + 1, (it + 1) & 1);
            asm volatile("cp.async.wait_group 1;");
        } else {
            asm volatile("cp.async.wait_group 0;");
        }
        __syncthreads();

        const uint32_t sa = sA0 + (it & 1) * sAsz;
        const uint32_t sb = sB0 + (it & 1) * sBsz;
#pragma unroll
        for (int kk = 0; kk < 32; kk += 16) {
            uint32_t a[4][4], bfr[2][4];
#pragma unroll
            for (int im = 0; im < 4; im++) {
                uint32_t addr = sa + (((wm + im * 16 + (lane & 15)) * APITCH) + kk + ((lane >> 4) << 3)) * 2;
                ldsm_x4(a[im][0], a[im][1], a[im][2], a[im][3], addr);
            }
#pragma unroll
            for (int jn = 0; jn < 2; jn++) {
                uint32_t addr = sb + (((kk + (lane & 7) + ((lane >> 3) & 1) * 8) * BPITCH)
                                      + wn + jn * 16 + ((lane >> 4) << 3)) * 2;
                ldsm_x4_t(bfr[jn][0], bfr[jn][1], bfr[jn][2], bfr[jn][3], addr);
            }
#pragma unroll
            for (int im = 0; im < 4; im++) {
#pragma unroll
                for (int jn = 0; jn < 2; jn++) {
                    mma_bf16(acc[im][jn * 2 + 0], a[im][0], a[im][1], a[im][2], a[im][3], bfr[jn][0], bfr[jn][1]);
                    mma_bf16(acc[im][jn * 2 + 1], a[im][0], a[im][1], a[im][2], a[im][3], bfr[jn][2], bfr[jn][3]);
                }
            }
        }
        __syncthreads();
    }
#undef LOAD_TILE

    // epilogue: fp32 + bias
    float* Yb = g_buf1 + (size_t)b * CC * HW;
#pragma unroll
    for (int im = 0; im < 4; im++) {
        int row = m0 + wm + im * 16 + (lane >> 2);
        float bv0 = bias ? bias[row] : 0.f;
        float bv1 = bias ? bias[row + 8] : 0.f;
#pragma unroll
        for (int j8 = 0; j8 < 4; j8++) {
            int col = n0 + wn + j8 * 8 + (lane & 3) * 2;
            float2 v0 = {acc[im][j8][0] + bv0, acc[im][j8][1] + bv0};
            float2 v1 = {acc[im][j8][2] + bv1, acc[im][j8][3] + bv1};
            *reinterpret_cast<float2*>(&Yb[(size_t)row * HW + col]) = v0;
            *reinterpret_cast<float2*>(&Yb[(size_t)(row + 8) * HW + col]) = v1;
        }
    }
}

// ---------------------------------------------------------------------------
// E-step: logits[n,k] = sum_c xf[c,n]*mu[c,k]; z = softmax_k(logits)
// ---------------------------------------------------------------------------
__global__ __launch_bounds__(256) void estep_kernel() {
    const int b  = blockIdx.y;
    const int n0 = blockIdx.x * 64;
    const int tid = threadIdx.x;
    const int ty = tid >> 4, tx = tid & 15;

    __shared__ float xs_s[32][64];
    __shared__ float mu_s[32][64];
    __shared__ float L[64][65];

    const float* xfb = g_buf1 + (size_t)b * CC * HW;
    const float* mub = g_mu  + (size_t)b * CC * KK;

    float acc[4][4];
#pragma unroll
    for (int i = 0; i < 4; i++)
#pragma unroll
        for (int j = 0; j < 4; j++) acc[i][j] = 0.f;

    for (int c0 = 0; c0 < CC; c0 += 32) {
        int row  = tid >> 4;
        int col4 = (tid & 15) * 4;
#pragma unroll
        for (int p = 0; p < 2; p++) {
            int r = row + p * 16;
            *reinterpret_cast<float4*>(&xs_s[r][col4]) =
                *reinterpret_cast<const float4*>(&xfb[(size_t)(c0 + r) * HW + n0 + col4]);
            *reinterpret_cast<float4*>(&mu_s[r][col4]) =
                *reinterpret_cast<const float4*>(&mub[(size_t)(c0 + r) * KK + col4]);
        }
        __syncthreads();
#pragma unroll
        for (int kk = 0; kk < 32; kk++) {
            float a[4], bb[4];
#pragma unroll
            for (int i = 0; i < 4; i++) a[i]  = xs_s[kk][ty * 4 + i];
#pragma unroll
            for (int j = 0; j < 4; j++) bb[j] = mu_s[kk][tx * 4 + j];
#pragma unroll
            for (int i = 0; i < 4; i++)
#pragma unroll
                for (int j = 0; j < 4; j++) acc[i][j] = fmaf(a[i], bb[j], acc[i][j]);
        }
        __syncthreads();
    }

#pragma unroll
    for (int i = 0; i < 4; i++)
#pragma unroll
        for (int j = 0; j < 4; j++) L[ty * 4 + i][tx * 4 + j] = acc[i][j];
    __syncthreads();

    const int warp = tid >> 5, lane = tid & 31;
    for (int r = warp * 8; r < warp * 8 + 8; r++) {
        float v0 = L[r][lane], v1 = L[r][lane + 32];
        float m = fmaxf(v0, v1);
#pragma unroll
        for (int off = 16; off > 0; off >>= 1)
            m = fmaxf(m, __shfl_xor_sync(0xffffffffu, m, off));
        float e0 = expf(v0 - m), e1 = expf(v1 - m);
        float s = e0 + e1;
#pragma unroll
        for (int off = 16; off > 0; off >>= 1)
            s += __shfl_xor_sync(0xffffffffu, s, off);
        float inv = 1.f / s;
        float* zr = g_z + (size_t)b * HW * KK + (size_t)(n0 + r) * KK;
        zr[lane]      = e0 * inv;
        zr[lane + 32] = e1 * inv;
    }
}

// ---------------------------------------------------------------------------
// M-step (split-K)
// ---------------------------------------------------------------------------
__global__ __launch_bounds__(256) void mstep_kernel() {
    const int b  = blockIdx.z;
    const int s  = blockIdx.y;
    const int c0 = blockIdx.x * 64;
    const int tid = threadIdx.x;
    const int ty = tid >> 4, tx = tid & 15;

    __shared__ float xT[64][65];
    __shared__ float zs[64][64];

    const float* xfb = g_buf1 + (size_t)b * CC * HW;
    const float* zb  = g_z    + (size_t)b * HW * KK;

    float acc[4][4];
#pragma unroll
    for (int i = 0; i < 4; i++)
#pragma unroll
        for (int j = 0; j < 4; j++) acc[i][j] = 0.f;

    const int nbeg = s * (HW / SPLIT), nend = nbeg + (HW / SPLIT);
    for (int n0 = nbeg; n0 < nend; n0 += 64) {
        int row  = tid >> 4;
        int col4 = (tid & 15) * 4;
#pragma unroll
        for (int p = 0; p < 4; p++) {
            int r = row + p * 16;
            float4 v = *reinterpret_cast<const float4*>(&xfb[(size_t)(c0 + r) * HW + n0 + col4]);
            xT[col4 + 0][r] = v.x; xT[col4 + 1][r] = v.y;
            xT[col4 + 2][r] = v.z; xT[col4 + 3][r] = v.w;
            *reinterpret_cast<float4*>(&zs[r][col4]) =
                *reinterpret_cast<const float4*>(&zb[(size_t)(n0 + r) * KK + col4]);
        }
        __syncthreads();
#pragma unroll
        for (int nn = 0; nn < 64; nn++) {
            float a[4], bb[4];
#pragma unroll
            for (int i = 0; i < 4; i++) a[i]  = xT[nn][ty * 4 + i];
#pragma unroll
            for (int j = 0; j < 4; j++) bb[j] = zs[nn][tx * 4 + j];
#pragma unroll
            for (int i = 0; i < 4; i++)
#pragma unroll
                for (int j = 0; j < 4; j++) acc[i][j] = fmaf(a[i], bb[j], acc[i][j]);
        }
        __syncthreads();
    }

    float* outp = g_mu_part + ((size_t)b * SPLIT + s) * CC * KK;
#pragma unroll
    for (int i = 0; i < 4; i++) {
        float4 v; v.x = acc[i][0]; v.y = acc[i][1]; v.z = acc[i][2]; v.w = acc[i][3];
        *reinterpret_cast<float4*>(&outp[(size_t)(c0 + ty * 4 + i) * KK + tx * 4]) = v;
    }
}

// ---------------------------------------------------------------------------
// Reduce split-K partials + l2-normalize (colsum norm of z_ cancels in l2norm)
// ---------------------------------------------------------------------------
__global__ void reduce_l2norm_kernel(float* __restrict__ out_mu) {
    const int bk = blockIdx.x;
    const int b = bk >> 6, k = bk & 63;
    const int tid = threadIdx.x;

    float* mub = g_mu + (size_t)b * CC * KK;
    const float* part = g_mu_part + (size_t)b * SPLIT * CC * KK;

    float s2 = 0.f;
    for (int c = tid; c < CC; c += 128) {
        float v = 0.f;
#pragma unroll
        for (int s = 0; s < SPLIT; s++)
            v += part[(size_t)s * CC * KK + (size_t)c * KK + k];
        mub[(size_t)c * KK + k] = v;
        s2 += v * v;
    }
    __shared__ float red[128];
    red[tid] = s2; __syncthreads();
    for (int st = 64; st > 0; st >>= 1) {
        if (tid < st) red[tid] += red[tid + st];
        __syncthreads();
    }
    float scale = 1.f / (1e-6f + sqrtf(red[0]));
    for (int c = tid; c < CC; c += 128) {
        float v = mub[(size_t)c * KK + k] * scale;
        mub[(size_t)c * KK + k] = v;
        if (out_mu) out_mu[(size_t)b * CC * KK + (size_t)c * KK + k] = v;
    }
}

// ---------------------------------------------------------------------------
// Reconstruction: xr = relu(mu @ z^T), emitted as split-bf16 for conv2
// ---------------------------------------------------------------------------
__global__ __launch_bounds__(256) void recon_kernel() {
    const int b  = blockIdx.z;
    const int c0 = blockIdx.x * 64;
    const int n0 = blockIdx.y * 64;
    const int tid = threadIdx.x;
    const int ty = tid >> 4, tx = tid & 15;

    __shared__ float muT[64][65];
    __shared__ float zT[64][65];

    const float* mub = g_mu + (size_t)b * CC * KK;
    const float* zb  = g_z  + (size_t)b * HW * KK;

    {
        int row  = tid >> 4;
        int col4 = (tid & 15) * 4;
#pragma unroll
        for (int p = 0; p < 4; p++) {
            int r = row + p * 16;
            float4 vm = *reinterpret_cast<const float4*>(&mub[(size_t)(c0 + r) * KK + col4]);
            muT[col4 + 0][r] = vm.x; muT[col4 + 1][r] = vm.y;
            muT[col4 + 2][r] = vm.z; muT[col4 + 3][r] = vm.w;
            float4 vz = *reinterpret_cast<const float4*>(&zb[(size_t)(n0 + r) * KK + col4]);
            zT[col4 + 0][r] = vz.x; zT[col4 + 1][r] = vz.y;
            zT[col4 + 2][r] = vz.z; zT[col4 + 3][r] = vz.w;
        }
    }
    __syncthreads();

    float acc[4][4];
#pragma unroll
    for (int i = 0; i < 4; i++)
#pragma unroll
        for (int j = 0; j < 4; j++) acc[i][j] = 0.f;

#pragma unroll
    for (int kk = 0; kk < 64; kk++) {
        float a[4], bb[4];
#pragma unroll
        for (int i = 0; i < 4; i++) a[i]  = muT[kk][ty * 4 + i];
#pragma unroll
        for (int j = 0; j < 4; j++) bb[j] = zT[kk][tx * 4 + j];
#pragma unroll
        for (int i = 0; i < 4; i++)
#pragma unroll
            for (int j = 0; j < 4; j++) acc[i][j] = fmaf(a[i], bb[j], acc[i][j]);
    }

#pragma unroll
    for (int i = 0; i < 4; i++) {
        size_t idx = (size_t)b * CC * HW + (size_t)(c0 + ty * 4 + i) * HW + n0 + tx * 4;
        __nv_bfloat16 h[4], l[4];
#pragma unroll
        for (int j = 0; j < 4; j++)
            split_val(fmaxf(acc[i][j], 0.f), h[j], l[j]);
        *reinterpret_cast<__nv_bfloat162*>(&g_xrhi[idx])     = __nv_bfloat162{h[0], h[1]};
        *reinterpret_cast<__nv_bfloat162*>(&g_xrhi[idx + 2]) = __nv_bfloat162{h[2], h[3]};
        *reinterpret_cast<__nv_bfloat162*>(&g_xrlo[idx])     = __nv_bfloat162{l[0], l[1]};
        *reinterpret_cast<__nv_bfloat162*>(&g_xrlo[idx + 2]) = __nv_bfloat162{l[2], l[3]};
    }
}

// ---------------------------------------------------------------------------
// BatchNorm statistics
// ---------------------------------------------------------------------------
__global__ void bn_stats_kernel(const float* __restrict__ gamma,
                                const float* __restrict__ beta) {
    const int o = blockIdx.x;
    const int tid = threadIdx.x;
    float s = 0.f, s2 = 0.f;
    for (int b = 0; b < BB; b++) {
        const float* p = g_buf1 + (size_t)b * CC * HW + (size_t)o * HW;
        for (int n = tid; n < HW; n += 256) {
            float v = p[n];
            s += v; s2 = fmaf(v, v, s2);
        }
    }
    __shared__ float r1[256], r2[256];
    r1[tid] = s; r2[tid] = s2; __syncthreads();
    for (int st = 128; st > 0; st >>= 1) {
        if (tid < st) { r1[tid] += r1[tid + st]; r2[tid] += r2[tid + st]; }
        __syncthreads();
    }
    if (tid == 0) {
        const float invM = 1.f / (float)(BB * HW);
        float mean = r1[0] * invM;
        float var  = r2[0] * invM - mean * mean;
        float sc = gamma[o] * rsqrtf(var + 1e-5f);
        g_scale[o] = sc;
        g_shift[o] = beta[o] - mean * sc;
    }
}

// ---------------------------------------------------------------------------
// Final: out = relu(x2*scale + shift + x)
// ---------------------------------------------------------------------------
__global__ void final_kernel(const float* __restrict__ x, float* __restrict__ out) {
    const int b = blockIdx.z, o = blockIdx.y;
    const size_t base = (size_t)b * CC * HW + (size_t)o * HW
                      + (size_t)blockIdx.x * 1024 + (size_t)threadIdx.x * 4;
    const float sc = g_scale[o], sh = g_shift[o];
    float4 v2 = *reinterpret_cast<const float4*>(&g_buf1[base]);
    float4 vx = *reinterpret_cast<const float4*>(&x[base]);
    float4 r;
    r.x = fmaxf(fmaf(v2.x, sc, sh) + vx.x, 0.f);
    r.y = fmaxf(fmaf(v2.y, sc, sh) + vx.y, 0.f);
    r.z = fmaxf(fmaf(v2.z, sc, sh) + vx.z, 0.f);
    r.w = fmaxf(fmaf(v2.w, sc, sh) + vx.w, 0.f);
    *reinterpret_cast<float4*>(&out[base]) = r;
}

// ---------------------------------------------------------------------------
// Transpose z [b][n][k] -> z_t [b][k][n]
// ---------------------------------------------------------------------------
__global__ void zt_kernel(float* __restrict__ zt) {
    const int b  = blockIdx.z;
    const int n0 = blockIdx.x * 32;
    const int k0 = blockIdx.y * 32;
    __shared__ float t[32][33];
    const int tx = threadIdx.x, ty = threadIdx.y;
    const float* zb = g_z + (size_t)b * HW * KK;
#pragma unroll
    for (int c = 0; c < 32; c += 8)
        t[ty + c][tx] = zb[(size_t)(n0 + ty + c) * KK + k0 + tx];
    __syncthreads();
    float* ztb = zt + (size_t)b * KK * HW;
#pragma unroll
    for (int c = 0; c < 32; c += 8)
        ztb[(size_t)(k0 + ty + c) * HW + n0 + tx] = t[tx][ty + c];
}

// ---------------------------------------------------------------------------
// Launch
// ---------------------------------------------------------------------------
extern "C" void kernel_launch(void* const* d_in, const int* in_sizes, int n_in,
                              void* d_out, int out_size) {
    const float* x     = (const float*)d_in[0];
    const float* w1    = (const float*)d_in[1];
    const float* b1    = (const float*)d_in[2];
    const float* w2    = (const float*)d_in[3];
    const float* gamma = (const float*)d_in[4];
    const float* beta  = (const float*)d_in[5];
    const float* mu_in = (const float*)d_in[6];

    float* out    = (float*)d_out;
    float* out_mu = out + (size_t)BB * CC * HW;
    float* out_zt = out_mu + (size_t)BB * CC * KK;

    split_w_kernel<<<CC * CC / 256, 256>>>(w1, w2);
    split_x_kernel<<<(BB * CC * HW) / (256 * 4), 256>>>(x);
    copymu_kernel<<<dim3(CC * KK / 256, BB), 256>>>(mu_in);

    // conv1: xf = w1 @ x + b1 -> g_buf1 (fp32)
    conv_mma_kernel<<<dim3(HW / 128, CC / 128, BB), 256>>>(b1, 0);

    // EM loop (3 stages)
    for (int s = 0; s < 3; s++) {
        estep_kernel<<<dim3(HW / 64, BB), 256>>>();
        mstep_kernel<<<dim3(CC / 64, SPLIT, BB), 256>>>();
        reduce_l2norm_kernel<<<BB * KK, 128>>>(s == 2 ? out_mu : nullptr);
    }

    // reconstruction + relu -> split bf16 (g_xrhi/g_xrlo)
    recon_kernel<<<dim3(CC / 64, HW / 64, BB), 256>>>();

    // conv2: x2 = w2 @ xr -> g_buf1 (fp32)
    conv_mma_kernel<<<dim3(HW / 128, CC / 128, BB), 256>>>(nullptr, 1);

    // BN stats + final residual relu
    bn_stats_kernel<<<CC, 256>>>(gamma, beta);
    final_kernel<<<dim3(HW / 1024, CC, BB), 256>>>(x, out);

    // z transpose output
    zt_kernel<<<dim3(HW / 32, KK / 32, BB), dim3(32, 8)>>>(out_zt);
}

// round 3
// speedup vs baseline: 2.0550x; 1.3616x over previous
#include <cuda_runtime.h>
#include <cuda_bf16.h>
#include <cstdint>
#include <math.h>

#define BB 16
#define CC 512
#define HW 4096
#define KK 64
#define SPLIT 8

// ---------------------------------------------------------------------------
// Scratch
// ---------------------------------------------------------------------------
__device__ float g_buf1[BB * CC * HW];            // x2 (conv2 out) fp32
__device__ float g_z[BB * HW * KK];               // z fp32 [b][n][k]
__device__ float g_mu[BB * CC * KK];              // mu fp32 scratch
__device__ float g_mu_part[BB * SPLIT * CC * KK];
__device__ float g_scale[CC];
__device__ float g_shift[CC];

__device__ __nv_bfloat16 g_w1hi[CC * CC], g_w1lo[CC * CC];
__device__ __nv_bfloat16 g_w2hi[CC * CC], g_w2lo[CC * CC];
__device__ __nv_bfloat16 g_xhi[BB * CC * HW],  g_xlo[BB * CC * HW];   // input x split
__device__ __nv_bfloat16 g_xfhi[BB * CC * HW], g_xflo[BB * CC * HW];  // conv1 out split
__device__ __nv_bfloat16 g_xrhi[BB * CC * HW], g_xrlo[BB * CC * HW];  // recon split
__device__ __nv_bfloat16 g_zhi[BB * HW * KK],  g_zlo[BB * HW * KK];   // z split
__device__ __nv_bfloat16 g_muhi[BB * CC * KK], g_mulo[BB * CC * KK];  // mu split

// ---------------------------------------------------------------------------
// PTX helpers
// ---------------------------------------------------------------------------
__device__ __forceinline__ uint32_t smem_u32(const void* p) {
    return (uint32_t)__cvta_generic_to_shared(p);
}
__device__ __forceinline__ void cp_async16(uint32_t saddr, const void* gaddr) {
    asm volatile("cp.async.cg.shared.global [%0], [%1], 16;" :: "r"(saddr), "l"(gaddr));
}
__device__ __forceinline__ void ldsm_x4(uint32_t& r0, uint32_t& r1, uint32_t& r2, uint32_t& r3, uint32_t a) {
    asm volatile("ldmatrix.sync.aligned.m8n8.x4.shared.b16 {%0,%1,%2,%3}, [%4];"
                 : "=r"(r0), "=r"(r1), "=r"(r2), "=r"(r3) : "r"(a));
}
__device__ __forceinline__ void ldsm_x4_t(uint32_t& r0, uint32_t& r1, uint32_t& r2, uint32_t& r3, uint32_t a) {
    asm volatile("ldmatrix.sync.aligned.m8n8.x4.trans.shared.b16 {%0,%1,%2,%3}, [%4];"
                 : "=r"(r0), "=r"(r1), "=r"(r2), "=r"(r3) : "r"(a));
}
__device__ __forceinline__ void mma_bf16(float* c, uint32_t a0, uint32_t a1, uint32_t a2, uint32_t a3,
                                         uint32_t b0, uint32_t b1) {
    asm volatile("mma.sync.aligned.m16n8k16.row.col.f32.bf16.bf16.f32 "
                 "{%0,%1,%2,%3}, {%4,%5,%6,%7}, {%8,%9}, {%0,%1,%2,%3};"
                 : "+f"(c[0]), "+f"(c[1]), "+f"(c[2]), "+f"(c[3])
                 : "r"(a0), "r"(a1), "r"(a2), "r"(a3), "r"(b0), "r"(b1));
}
__device__ __forceinline__ void split_val(float v, __nv_bfloat16& h, __nv_bfloat16& l) {
    h = __float2bfloat16(v);
    l = __float2bfloat16(v - __bfloat162float(h));
}

// ---------------------------------------------------------------------------
// Conversions
// ---------------------------------------------------------------------------
__global__ void split_w_kernel(const float* __restrict__ w1, const float* __restrict__ w2) {
    int i = blockIdx.x * 256 + threadIdx.x;
    split_val(w1[i], g_w1hi[i], g_w1lo[i]);
    split_val(w2[i], g_w2hi[i], g_w2lo[i]);
}
__global__ void split_x_kernel(const float* __restrict__ x) {
    size_t i = ((size_t)blockIdx.x * 256 + threadIdx.x) * 4;
    float4 v = *reinterpret_cast<const float4*>(&x[i]);
    __nv_bfloat16 h0, h1, h2, h3, l0, l1, l2, l3;
    split_val(v.x, h0, l0); split_val(v.y, h1, l1);
    split_val(v.z, h2, l2); split_val(v.w, h3, l3);
    *reinterpret_cast<__nv_bfloat162*>(&g_xhi[i])     = __nv_bfloat162{h0, h1};
    *reinterpret_cast<__nv_bfloat162*>(&g_xhi[i + 2]) = __nv_bfloat162{h2, h3};
    *reinterpret_cast<__nv_bfloat162*>(&g_xlo[i])     = __nv_bfloat162{l0, l1};
    *reinterpret_cast<__nv_bfloat162*>(&g_xlo[i + 2]) = __nv_bfloat162{l2, l3};
}
__global__ void copymu_kernel(const float* __restrict__ mu_in) {
    int b = blockIdx.y;
    int i = blockIdx.x * 256 + threadIdx.x;
    __nv_bfloat16 h, l; split_val(mu_in[i], h, l);
    size_t idx = (size_t)b * CC * KK + i;
    g_muhi[idx] = h; g_mulo[idx] = l;
}

// ---------------------------------------------------------------------------
// conv GEMM (tensor, split-bf16 3 passes). sel 0: conv1 (out -> xf splits, +bias)
//                                          sel 1: conv2 (out -> g_buf1 fp32)
// ---------------------------------------------------------------------------
#define APITCH 40
#define BPITCH 136
__global__ __launch_bounds__(256) void conv_mma_kernel(const float* __restrict__ bias, int sel) {
    const int b  = blockIdx.z;
    const int m0 = blockIdx.y * 128;
    const int n0 = blockIdx.x * 128;
    const int tid  = threadIdx.x;
    const int lane = tid & 31;
    const int wid  = tid >> 5;
    const int wm   = (wid & 1) * 64;
    const int wn   = (wid >> 1) * 32;

    __shared__ __nv_bfloat16 As[2][128 * APITCH];
    __shared__ __nv_bfloat16 Bs[2][32 * BPITCH];

    const __nv_bfloat16* Whi = sel ? g_w2hi : g_w1hi;
    const __nv_bfloat16* Wlo = sel ? g_w2lo : g_w1lo;
    const __nv_bfloat16* Xhi = (sel ? g_xrhi : g_xhi) + (size_t)b * CC * HW;
    const __nv_bfloat16* Xlo = (sel ? g_xrlo : g_xlo) + (size_t)b * CC * HW;

    float acc[4][4][4];
#pragma unroll
    for (int i = 0; i < 4; i++)
#pragma unroll
        for (int j = 0; j < 4; j++)
#pragma unroll
            for (int q = 0; q < 4; q++) acc[i][j][q] = 0.f;

    const uint32_t sA0 = smem_u32(As[0]);
    const uint32_t sB0 = smem_u32(Bs[0]);
    const uint32_t sAsz = 128 * APITCH * 2;
    const uint32_t sBsz = 32 * BPITCH * 2;

    const int aq0 = tid, aq1 = tid + 256;
    const int ar0 = aq0 >> 2, ac0 = (aq0 & 3) * 8;
    const int ar1 = aq1 >> 2, ac1 = (aq1 & 3) * 8;
    const int br0 = aq0 >> 4, bc0 = (aq0 & 15) * 8;
    const int br1 = aq1 >> 4, bc1 = (aq1 & 15) * 8;

    const int NT = 48;

#define LOAD_TILE(IT, BUF) do {                                                   \
        int pass = (IT) >> 4, kt = (IT) & 15, k0 = kt * 32;                       \
        const __nv_bfloat16* Ap = (pass == 1) ? Wlo : Whi;                        \
        const __nv_bfloat16* Bp = (pass == 2) ? Xlo : Xhi;                        \
        uint32_t sa = sA0 + (BUF) * sAsz, sb = sB0 + (BUF) * sBsz;                \
        cp_async16(sa + (ar0 * APITCH + ac0) * 2, Ap + (size_t)(m0 + ar0) * CC + k0 + ac0); \
        cp_async16(sa + (ar1 * APITCH + ac1) * 2, Ap + (size_t)(m0 + ar1) * CC + k0 + ac1); \
        cp_async16(sb + (br0 * BPITCH + bc0) * 2, Bp + (size_t)(k0 + br0) * HW + n0 + bc0); \
        cp_async16(sb + (br1 * BPITCH + bc1) * 2, Bp + (size_t)(k0 + br1) * HW + n0 + bc1); \
        asm volatile("cp.async.commit_group;");                                   \
    } while (0)

    LOAD_TILE(0, 0);
    for (int it = 0; it < NT; ++it) {
        if (it + 1 < NT) { LOAD_TILE(it + 1, (it + 1) & 1); asm volatile("cp.async.wait_group 1;"); }
        else             { asm volatile("cp.async.wait_group 0;"); }
        __syncthreads();
        const uint32_t sa = sA0 + (it & 1) * sAsz;
        const uint32_t sb = sB0 + (it & 1) * sBsz;
#pragma unroll
        for (int kk = 0; kk < 32; kk += 16) {
            uint32_t a[4][4], bfr[2][4];
#pragma unroll
            for (int im = 0; im < 4; im++) {
                uint32_t addr = sa + (((wm + im * 16 + (lane & 15)) * APITCH) + kk + ((lane >> 4) << 3)) * 2;
                ldsm_x4(a[im][0], a[im][1], a[im][2], a[im][3], addr);
            }
#pragma unroll
            for (int jn = 0; jn < 2; jn++) {
                uint32_t addr = sb + (((kk + (lane & 7) + ((lane >> 3) & 1) * 8) * BPITCH)
                                      + wn + jn * 16 + ((lane >> 4) << 3)) * 2;
                ldsm_x4_t(bfr[jn][0], bfr[jn][1], bfr[jn][2], bfr[jn][3], addr);
            }
#pragma unroll
            for (int im = 0; im < 4; im++)
#pragma unroll
                for (int jn = 0; jn < 2; jn++) {
                    mma_bf16(acc[im][jn * 2 + 0], a[im][0], a[im][1], a[im][2], a[im][3], bfr[jn][0], bfr[jn][1]);
                    mma_bf16(acc[im][jn * 2 + 1], a[im][0], a[im][1], a[im][2], a[im][3], bfr[jn][2], bfr[jn][3]);
                }
        }
        __syncthreads();
    }
#undef LOAD_TILE

    if (sel == 0) {
        // conv1: bias + split-bf16 out
        __nv_bfloat16* Oh = g_xfhi + (size_t)b * CC * HW;
        __nv_bfloat16* Ol = g_xflo + (size_t)b * CC * HW;
#pragma unroll
        for (int im = 0; im < 4; im++) {
            int row = m0 + wm + im * 16 + (lane >> 2);
            float bv0 = bias[row], bv1 = bias[row + 8];
#pragma unroll
            for (int j8 = 0; j8 < 4; j8++) {
                int col = n0 + wn + j8 * 8 + (lane & 3) * 2;
                __nv_bfloat16 h0, h1, h2, h3, l0, l1, l2, l3;
                split_val(acc[im][j8][0] + bv0, h0, l0);
                split_val(acc[im][j8][1] + bv0, h1, l1);
                split_val(acc[im][j8][2] + bv1, h2, l2);
                split_val(acc[im][j8][3] + bv1, h3, l3);
                *reinterpret_cast<__nv_bfloat162*>(&Oh[(size_t)row * HW + col]) = __nv_bfloat162{h0, h1};
                *reinterpret_cast<__nv_bfloat162*>(&Ol[(size_t)row * HW + col]) = __nv_bfloat162{l0, l1};
                *reinterpret_cast<__nv_bfloat162*>(&Oh[(size_t)(row + 8) * HW + col]) = __nv_bfloat162{h2, h3};
                *reinterpret_cast<__nv_bfloat162*>(&Ol[(size_t)(row + 8) * HW + col]) = __nv_bfloat162{l2, l3};
            }
        }
    } else {
        float* Yb = g_buf1 + (size_t)b * CC * HW;
#pragma unroll
        for (int im = 0; im < 4; im++) {
            int row = m0 + wm + im * 16 + (lane >> 2);
#pragma unroll
            for (int j8 = 0; j8 < 4; j8++) {
                int col = n0 + wn + j8 * 8 + (lane & 3) * 2;
                float2 v0 = {acc[im][j8][0], acc[im][j8][1]};
                float2 v1 = {acc[im][j8][2], acc[im][j8][3]};
                *reinterpret_cast<float2*>(&Yb[(size_t)row * HW + col]) = v0;
                *reinterpret_cast<float2*>(&Yb[(size_t)(row + 8) * HW + col]) = v1;
            }
        }
    }
}

// ---------------------------------------------------------------------------
// E-step (tensor): logits[n,k] = sum_c xf[c,n]*mu[c,k], softmax -> z (+splits)
// M-tile 128 (pixels), N=64, K=512, 3 passes. 8 warps: 4 along M, 2 along N.
// A: trans-ldmatrix from [c][n] tiles; B: trans-ldmatrix from [c][k] tiles.
// ---------------------------------------------------------------------------
#define EAP 136   // A tile pitch: [32][128]
#define EBP 72    // B tile pitch: [32][64]
__global__ __launch_bounds__(256) void estep_mma_kernel() {
    const int b  = blockIdx.y;
    const int n0 = blockIdx.x * 128;
    const int tid  = threadIdx.x;
    const int lane = tid & 31;
    const int wid  = tid >> 5;
    const int wm   = (wid & 3) * 32;
    const int wn   = (wid >> 2) * 32;

    __shared__ __align__(16) char sm[35328];
    __nv_bfloat16* As = (__nv_bfloat16*)sm;             // 2 x 32*136*2 = 17408
    __nv_bfloat16* Bs = (__nv_bfloat16*)(sm + 17408);   // 2 x 32*72*2  =  9216
    float* L = (float*)sm;                               // reuse: 128 x 68 x 4 = 34816

    const __nv_bfloat16* Xh = g_xfhi + (size_t)b * CC * HW;
    const __nv_bfloat16* Xl = g_xflo + (size_t)b * CC * HW;
    const __nv_bfloat16* Mh = g_muhi + (size_t)b * CC * KK;
    const __nv_bfloat16* Ml = g_mulo + (size_t)b * CC * KK;

    float acc[2][4][4];
#pragma unroll
    for (int i = 0; i < 2; i++)
#pragma unroll
        for (int j = 0; j < 4; j++)
#pragma unroll
            for (int q = 0; q < 4; q++) acc[i][j][q] = 0.f;

    const uint32_t sA0 = smem_u32(As);
    const uint32_t sB0 = smem_u32(Bs);
    const uint32_t sAsz = 32 * EAP * 2;
    const uint32_t sBsz = 32 * EBP * 2;

    // A: 512 chunks (32 rows x 16 chunks); B: 256 chunks (32 rows x 8)
    const int aq0 = tid, aq1 = tid + 256;
    const int ar0 = aq0 >> 4, ac0 = (aq0 & 15) * 8;
    const int ar1 = aq1 >> 4, ac1 = (aq1 & 15) * 8;
    const int br = tid >> 3, bc = (tid & 7) * 8;

    const int NT = 48;
#define LOAD_TILE(IT, BUF) do {                                                   \
        int pass = (IT) >> 4, k0 = ((IT) & 15) * 32;                              \
        const __nv_bfloat16* Ap = (pass == 1) ? Xl : Xh;                          \
        const __nv_bfloat16* Bp = (pass == 2) ? Ml : Mh;                          \
        uint32_t sa = sA0 + (BUF) * sAsz, sb = sB0 + (BUF) * sBsz;                \
        cp_async16(sa + (ar0 * EAP + ac0) * 2, Ap + (size_t)(k0 + ar0) * HW + n0 + ac0); \
        cp_async16(sa + (ar1 * EAP + ac1) * 2, Ap + (size_t)(k0 + ar1) * HW + n0 + ac1); \
        cp_async16(sb + (br * EBP + bc) * 2,  Bp + (size_t)(k0 + br) * KK + bc);  \
        asm volatile("cp.async.commit_group;");                                   \
    } while (0)

    LOAD_TILE(0, 0);
    for (int it = 0; it < NT; ++it) {
        if (it + 1 < NT) { LOAD_TILE(it + 1, (it + 1) & 1); asm volatile("cp.async.wait_group 1;"); }
        else             { asm volatile("cp.async.wait_group 0;"); }
        __syncthreads();
        const uint32_t sa = sA0 + (it & 1) * sAsz;
        const uint32_t sb = sB0 + (it & 1) * sBsz;
#pragma unroll
        for (int kk = 0; kk < 32; kk += 16) {
            uint32_t a[2][4], bfr[2][4];
#pragma unroll
            for (int f = 0; f < 2; f++) {
                uint32_t addr = sa + (((kk + (lane & 7) + ((lane >> 4) << 3)) * EAP)
                                      + wm + f * 16 + ((lane >> 3) & 1) * 8) * 2;
                ldsm_x4_t(a[f][0], a[f][1], a[f][2], a[f][3], addr);
            }
#pragma unroll
            for (int jn = 0; jn < 2; jn++) {
                uint32_t addr = sb + (((kk + (lane & 7) + ((lane >> 3) & 1) * 8) * EBP)
                                      + wn + jn * 16 + ((lane >> 4) << 3)) * 2;
                ldsm_x4_t(bfr[jn][0], bfr[jn][1], bfr[jn][2], bfr[jn][3], addr);
            }
#pragma unroll
            for (int f = 0; f < 2; f++)
#pragma unroll
                for (int jn = 0; jn < 2; jn++) {
                    mma_bf16(acc[f][jn * 2 + 0], a[f][0], a[f][1], a[f][2], a[f][3], bfr[jn][0], bfr[jn][1]);
                    mma_bf16(acc[f][jn * 2 + 1], a[f][0], a[f][1], a[f][2], a[f][3], bfr[jn][2], bfr[jn][3]);
                }
        }
        __syncthreads();
    }
#undef LOAD_TILE

    // logits -> smem
#pragma unroll
    for (int f = 0; f < 2; f++) {
        int row = wm + f * 16 + (lane >> 2);
#pragma unroll
        for (int j8 = 0; j8 < 4; j8++) {
            int col = wn + j8 * 8 + (lane & 3) * 2;
            *reinterpret_cast<float2*>(&L[row * 68 + col])       = {acc[f][j8][0], acc[f][j8][1]};
            *reinterpret_cast<float2*>(&L[(row + 8) * 68 + col]) = {acc[f][j8][2], acc[f][j8][3]};
        }
    }
    __syncthreads();

    // softmax over k: each warp 16 rows
    for (int i = 0; i < 16; i++) {
        int r = wid * 16 + i;
        float v0 = L[r * 68 + lane], v1 = L[r * 68 + lane + 32];
        float m = fmaxf(v0, v1);
#pragma unroll
        for (int off = 16; off > 0; off >>= 1)
            m = fmaxf(m, __shfl_xor_sync(0xffffffffu, m, off));
        float e0 = expf(v0 - m), e1 = expf(v1 - m);
        float s = e0 + e1;
#pragma unroll
        for (int off = 16; off > 0; off >>= 1)
            s += __shfl_xor_sync(0xffffffffu, s, off);
        float inv = 1.f / s;
        float z0 = e0 * inv, z1 = e1 * inv;
        size_t base = (size_t)b * HW * KK + (size_t)(n0 + r) * KK;
        g_z[base + lane]      = z0;
        g_z[base + lane + 32] = z1;
        __nv_bfloat16 h, l;
        split_val(z0, h, l); g_zhi[base + lane] = h;      g_zlo[base + lane] = l;
        split_val(z1, h, l); g_zhi[base + lane + 32] = h; g_zlo[base + lane + 32] = l;
    }
}

// ---------------------------------------------------------------------------
// M-step (tensor, split-K over n): mu_part[c,k] = sum_n xf[c,n]*z[n,k]
// M-tile 128 (c), N=64, K=512 per split, 3 passes.
// A: non-trans from xf [c][n]; B: trans from z [n][k].
// ---------------------------------------------------------------------------
#define MAP 40   // A tile [128][32]
#define MBP 72   // B tile [32][64]
__global__ __launch_bounds__(256) void mstep_mma_kernel() {
    const int b  = blockIdx.z;
    const int s  = blockIdx.y;
    const int c0 = blockIdx.x * 128;
    const int tid  = threadIdx.x;
    const int lane = tid & 31;
    const int wid  = tid >> 5;
    const int wm   = (wid & 3) * 32;
    const int wn   = (wid >> 2) * 32;

    __shared__ __nv_bfloat16 As[2][128 * MAP];
    __shared__ __nv_bfloat16 Bs[2][32 * MBP];

    const __nv_bfloat16* Xh = g_xfhi + (size_t)b * CC * HW;
    const __nv_bfloat16* Xl = g_xflo + (size_t)b * CC * HW;
    const __nv_bfloat16* Zh = g_zhi  + (size_t)b * HW * KK;
    const __nv_bfloat16* Zl = g_zlo  + (size_t)b * HW * KK;

    float acc[2][4][4];
#pragma unroll
    for (int i = 0; i < 2; i++)
#pragma unroll
        for (int j = 0; j < 4; j++)
#pragma unroll
            for (int q = 0; q < 4; q++) acc[i][j][q] = 0.f;

    const uint32_t sA0 = smem_u32(As[0]);
    const uint32_t sB0 = smem_u32(Bs[0]);
    const uint32_t sAsz = 128 * MAP * 2;
    const uint32_t sBsz = 32 * MBP * 2;

    const int aq0 = tid, aq1 = tid + 256;     // A: 512 chunks (128 rows x 4)
    const int ar0 = aq0 >> 2, ac0 = (aq0 & 3) * 8;
    const int ar1 = aq1 >> 2, ac1 = (aq1 & 3) * 8;
    const int br = tid >> 3, bc = (tid & 7) * 8;  // B: 256 chunks

    const int nbeg = s * (HW / SPLIT);
    const int NT = 48;
#define LOAD_TILE(IT, BUF) do {                                                   \
        int pass = (IT) >> 4, n0 = nbeg + ((IT) & 15) * 32;                       \
        const __nv_bfloat16* Ap = (pass == 1) ? Xl : Xh;                          \
        const __nv_bfloat16* Bp = (pass == 2) ? Zl : Zh;                          \
        uint32_t sa = sA0 + (BUF) * sAsz, sb = sB0 + (BUF) * sBsz;                \
        cp_async16(sa + (ar0 * MAP + ac0) * 2, Ap + (size_t)(c0 + ar0) * HW + n0 + ac0); \
        cp_async16(sa + (ar1 * MAP + ac1) * 2, Ap + (size_t)(c0 + ar1) * HW + n0 + ac1); \
        cp_async16(sb + (br * MBP + bc) * 2,  Bp + (size_t)(n0 + br) * KK + bc);  \
        asm volatile("cp.async.commit_group;");                                   \
    } while (0)

    LOAD_TILE(0, 0);
    for (int it = 0; it < NT; ++it) {
        if (it + 1 < NT) { LOAD_TILE(it + 1, (it + 1) & 1); asm volatile("cp.async.wait_group 1;"); }
        else             { asm volatile("cp.async.wait_group 0;"); }
        __syncthreads();
        const uint32_t sa = sA0 + (it & 1) * sAsz;
        const uint32_t sb = sB0 + (it & 1) * sBsz;
#pragma unroll
        for (int kk = 0; kk < 32; kk += 16) {
            uint32_t a[2][4], bfr[2][4];
#pragma unroll
            for (int f = 0; f < 2; f++) {
                uint32_t addr = sa + (((wm + f * 16 + (lane & 15)) * MAP) + kk + ((lane >> 4) << 3)) * 2;
                ldsm_x4(a[f][0], a[f][1], a[f][2], a[f][3], addr);
            }
#pragma unroll
            for (int jn = 0; jn < 2; jn++) {
                uint32_t addr = sb + (((kk + (lane & 7) + ((lane >> 3) & 1) * 8) * MBP)
                                      + wn + jn * 16 + ((lane >> 4) << 3)) * 2;
                ldsm_x4_t(bfr[jn][0], bfr[jn][1], bfr[jn][2], bfr[jn][3], addr);
            }
#pragma unroll
            for (int f = 0; f < 2; f++)
#pragma unroll
                for (int jn = 0; jn < 2; jn++) {
                    mma_bf16(acc[f][jn * 2 + 0], a[f][0], a[f][1], a[f][2], a[f][3], bfr[jn][0], bfr[jn][1]);
                    mma_bf16(acc[f][jn * 2 + 1], a[f][0], a[f][1], a[f][2], a[f][3], bfr[jn][2], bfr[jn][3]);
                }
        }
        __syncthreads();
    }
#undef LOAD_TILE

    float* outp = g_mu_part + ((size_t)b * SPLIT + s) * CC * KK;
#pragma unroll
    for (int f = 0; f < 2; f++) {
        int row = c0 + wm + f * 16 + (lane >> 2);
#pragma unroll
        for (int j8 = 0; j8 < 4; j8++) {
            int col = wn + j8 * 8 + (lane & 3) * 2;
            *reinterpret_cast<float2*>(&outp[(size_t)row * KK + col])       = {acc[f][j8][0], acc[f][j8][1]};
            *reinterpret_cast<float2*>(&outp[(size_t)(row + 8) * KK + col]) = {acc[f][j8][2], acc[f][j8][3]};
        }
    }
}

// ---------------------------------------------------------------------------
// Reduce split-K partials + l2-normalize; emit fp32 (out_mu) + splits
// ---------------------------------------------------------------------------
__global__ void reduce_l2norm_kernel(float* __restrict__ out_mu) {
    const int bk = blockIdx.x;
    const int b = bk >> 6, k = bk & 63;
    const int tid = threadIdx.x;

    float* mub = g_mu + (size_t)b * CC * KK;
    const float* part = g_mu_part + (size_t)b * SPLIT * CC * KK;

    float s2 = 0.f;
    for (int c = tid; c < CC; c += 128) {
        float v = 0.f;
#pragma unroll
        for (int s = 0; s < SPLIT; s++)
            v += part[(size_t)s * CC * KK + (size_t)c * KK + k];
        mub[(size_t)c * KK + k] = v;
        s2 += v * v;
    }
    __shared__ float red[128];
    red[tid] = s2; __syncthreads();
    for (int st = 64; st > 0; st >>= 1) {
        if (tid < st) red[tid] += red[tid + st];
        __syncthreads();
    }
    float scale = 1.f / (1e-6f + sqrtf(red[0]));
    for (int c = tid; c < CC; c += 128) {
        size_t idx = (size_t)b * CC * KK + (size_t)c * KK + k;
        float v = mub[(size_t)c * KK + k] * scale;
        __nv_bfloat16 h, l; split_val(v, h, l);
        g_muhi[idx] = h; g_mulo[idx] = l;
        if (out_mu) out_mu[idx] = v;
    }
}

// ---------------------------------------------------------------------------
// Reconstruction (tensor): xr[c,n] = relu(sum_k mu[c,k]*z[n,k]) -> splits
// M-tile 128 (c), N-tile 128 (n), K=64, 3 passes (6 k-tiles).
// A: non-trans from mu [c][k]; B: non-trans from z [n][k].
// ---------------------------------------------------------------------------
#define RP 40
__global__ __launch_bounds__(256) void recon_mma_kernel() {
    const int b  = blockIdx.z;
    const int c0 = blockIdx.y * 128;
    const int n0 = blockIdx.x * 128;
    const int tid  = threadIdx.x;
    const int lane = tid & 31;
    const int wid  = tid >> 5;
    const int wm   = (wid & 1) * 64;
    const int wn   = (wid >> 1) * 32;

    __shared__ __nv_bfloat16 As[2][128 * RP];
    __shared__ __nv_bfloat16 Bs[2][128 * RP];

    const __nv_bfloat16* Mh = g_muhi + (size_t)b * CC * KK;
    const __nv_bfloat16* Ml = g_mulo + (size_t)b * CC * KK;
    const __nv_bfloat16* Zh = g_zhi  + (size_t)b * HW * KK;
    const __nv_bfloat16* Zl = g_zlo  + (size_t)b * HW * KK;

    float acc[4][4][4];
#pragma unroll
    for (int i = 0; i < 4; i++)
#pragma unroll
        for (int j = 0; j < 4; j++)
#pragma unroll
            for (int q = 0; q < 4; q++) acc[i][j][q] = 0.f;

    const uint32_t sA0 = smem_u32(As[0]);
    const uint32_t sB0 = smem_u32(Bs[0]);
    const uint32_t ssz = 128 * RP * 2;

    const int aq0 = tid, aq1 = tid + 256;   // each tile: 512 chunks (128 rows x 4)
    const int ar0 = aq0 >> 2, ac0 = (aq0 & 3) * 8;
    const int ar1 = aq1 >> 2, ac1 = (aq1 & 3) * 8;

    const int NT = 6;
#define LOAD_TILE(IT, BUF) do {                                                   \
        int pass = (IT) >> 1, k0 = ((IT) & 1) * 32;                               \
        const __nv_bfloat16* Ap = (pass == 1) ? Ml : Mh;                          \
        const __nv_bfloat16* Bp = (pass == 2) ? Zl : Zh;                          \
        uint32_t sa = sA0 + (BUF) * ssz, sb = sB0 + (BUF) * ssz;                  \
        cp_async16(sa + (ar0 * RP + ac0) * 2, Ap + (size_t)(c0 + ar0) * KK + k0 + ac0); \
        cp_async16(sa + (ar1 * RP + ac1) * 2, Ap + (size_t)(c0 + ar1) * KK + k0 + ac1); \
        cp_async16(sb + (ar0 * RP + ac0) * 2, Bp + (size_t)(n0 + ar0) * KK + k0 + ac0); \
        cp_async16(sb + (ar1 * RP + ac1) * 2, Bp + (size_t)(n0 + ar1) * KK + k0 + ac1); \
        asm volatile("cp.async.commit_group;");                                   \
    } while (0)

    LOAD_TILE(0, 0);
    for (int it = 0; it < NT; ++it) {
        if (it + 1 < NT) { LOAD_TILE(it + 1, (it + 1) & 1); asm volatile("cp.async.wait_group 1;"); }
        else             { asm volatile("cp.async.wait_group 0;"); }
        __syncthreads();
        const uint32_t sa = sA0 + (it & 1) * ssz;
        const uint32_t sb = sB0 + (it & 1) * ssz;
#pragma unroll
        for (int kk = 0; kk < 32; kk += 16) {
            uint32_t a[4][4], bfr[2][4];
#pragma unroll
            for (int im = 0; im < 4; im++) {
                uint32_t addr = sa + (((wm + im * 16 + (lane & 15)) * RP) + kk + ((lane >> 4) << 3)) * 2;
                ldsm_x4(a[im][0], a[im][1], a[im][2], a[im][3], addr);
            }
#pragma unroll
            for (int jn = 0; jn < 2; jn++) {
                uint32_t addr = sb + (((wn + jn * 16 + (lane & 7) + ((lane >> 4) << 3)) * RP)
                                      + kk + ((lane >> 3) & 1) * 8) * 2;
                ldsm_x4(bfr[jn][0], bfr[jn][1], bfr[jn][2], bfr[jn][3], addr);
            }
#pragma unroll
            for (int im = 0; im < 4; im++)
#pragma unroll
                for (int jn = 0; jn < 2; jn++) {
                    mma_bf16(acc[im][jn * 2 + 0], a[im][0], a[im][1], a[im][2], a[im][3], bfr[jn][0], bfr[jn][1]);
                    mma_bf16(acc[im][jn * 2 + 1], a[im][0], a[im][1], a[im][2], a[im][3], bfr[jn][2], bfr[jn][3]);
                }
        }
        __syncthreads();
    }
#undef LOAD_TILE

    __nv_bfloat16* Oh = g_xrhi + (size_t)b * CC * HW;
    __nv_bfloat16* Ol = g_xrlo + (size_t)b * CC * HW;
#pragma unroll
    for (int im = 0; im < 4; im++) {
        int row = c0 + wm + im * 16 + (lane >> 2);
#pragma unroll
        for (int j8 = 0; j8 < 4; j8++) {
            int col = n0 + wn + j8 * 8 + (lane & 3) * 2;
            __nv_bfloat16 h0, h1, h2, h3, l0, l1, l2, l3;
            split_val(fmaxf(acc[im][j8][0], 0.f), h0, l0);
            split_val(fmaxf(acc[im][j8][1], 0.f), h1, l1);
            split_val(fmaxf(acc[im][j8][2], 0.f), h2, l2);
            split_val(fmaxf(acc[im][j8][3], 0.f), h3, l3);
            *reinterpret_cast<__nv_bfloat162*>(&Oh[(size_t)row * HW + col]) = __nv_bfloat162{h0, h1};
            *reinterpret_cast<__nv_bfloat162*>(&Ol[(size_t)row * HW + col]) = __nv_bfloat162{l0, l1};
            *reinterpret_cast<__nv_bfloat162*>(&Oh[(size_t)(row + 8) * HW + col]) = __nv_bfloat162{h2, h3};
            *reinterpret_cast<__nv_bfloat162*>(&Ol[(size_t)(row + 8) * HW + col]) = __nv_bfloat162{l2, l3};
        }
    }
}

// ---------------------------------------------------------------------------
// BatchNorm stats / final / z-transpose
// ---------------------------------------------------------------------------
__global__ void bn_stats_kernel(const float* __restrict__ gamma,
                                const float* __restrict__ beta) {
    const int o = blockIdx.x;
    const int tid = threadIdx.x;
    float s = 0.f, s2 = 0.f;
    for (int b = 0; b < BB; b++) {
        const float* p = g_buf1 + (size_t)b * CC * HW + (size_t)o * HW;
        for (int n = tid; n < HW; n += 256) {
            float v = p[n];
            s += v; s2 = fmaf(v, v, s2);
        }
    }
    __shared__ float r1[256], r2[256];
    r1[tid] = s; r2[tid] = s2; __syncthreads();
    for (int st = 128; st > 0; st >>= 1) {
        if (tid < st) { r1[tid] += r1[tid + st]; r2[tid] += r2[tid + st]; }
        __syncthreads();
    }
    if (tid == 0) {
        const float invM = 1.f / (float)(BB * HW);
        float mean = r1[0] * invM;
        float var  = r2[0] * invM - mean * mean;
        float sc = gamma[o] * rsqrtf(var + 1e-5f);
        g_scale[o] = sc;
        g_shift[o] = beta[o] - mean * sc;
    }
}

__global__ void final_kernel(const float* __restrict__ x, float* __restrict__ out) {
    const int b = blockIdx.z, o = blockIdx.y;
    const size_t base = (size_t)b * CC * HW + (size_t)o * HW
                      + (size_t)blockIdx.x * 1024 + (size_t)threadIdx.x * 4;
    const float sc = g_scale[o], sh = g_shift[o];
    float4 v2 = *reinterpret_cast<const float4*>(&g_buf1[base]);
    float4 vx = *reinterpret_cast<const float4*>(&x[base]);
    float4 r;
    r.x = fmaxf(fmaf(v2.x, sc, sh) + vx.x, 0.f);
    r.y = fmaxf(fmaf(v2.y, sc, sh) + vx.y, 0.f);
    r.z = fmaxf(fmaf(v2.z, sc, sh) + vx.z, 0.f);
    r.w = fmaxf(fmaf(v2.w, sc, sh) + vx.w, 0.f);
    *reinterpret_cast<float4*>(&out[base]) = r;
}

__global__ void zt_kernel(float* __restrict__ zt) {
    const int b  = blockIdx.z;
    const int n0 = blockIdx.x * 32;
    const int k0 = blockIdx.y * 32;
    __shared__ float t[32][33];
    const int tx = threadIdx.x, ty = threadIdx.y;
    const float* zb = g_z + (size_t)b * HW * KK;
#pragma unroll
    for (int c = 0; c < 32; c += 8)
        t[ty + c][tx] = zb[(size_t)(n0 + ty + c) * KK + k0 + tx];
    __syncthreads();
    float* ztb = zt + (size_t)b * KK * HW;
#pragma unroll
    for (int c = 0; c < 32; c += 8)
        ztb[(size_t)(k0 + ty + c) * HW + n0 + tx] = t[tx][ty + c];
}

// ---------------------------------------------------------------------------
// Launch
// ---------------------------------------------------------------------------
extern "C" void kernel_launch(void* const* d_in, const int* in_sizes, int n_in,
                              void* d_out, int out_size) {
    const float* x     = (const float*)d_in[0];
    const float* w1    = (const float*)d_in[1];
    const float* b1    = (const float*)d_in[2];
    const float* w2    = (const float*)d_in[3];
    const float* gamma = (const float*)d_in[4];
    const float* beta  = (const float*)d_in[5];
    const float* mu_in = (const float*)d_in[6];

    float* out    = (float*)d_out;
    float* out_mu = out + (size_t)BB * CC * HW;
    float* out_zt = out_mu + (size_t)BB * CC * KK;

    split_w_kernel<<<CC * CC / 256, 256>>>(w1, w2);
    split_x_kernel<<<(BB * CC * HW) / (256 * 4), 256>>>(x);
    copymu_kernel<<<dim3(CC * KK / 256, BB), 256>>>(mu_in);

    // conv1 -> xf splits
    conv_mma_kernel<<<dim3(HW / 128, CC / 128, BB), 256>>>(b1, 0);

    for (int s = 0; s < 3; s++) {
        estep_mma_kernel<<<dim3(HW / 128, BB), 256>>>();
        mstep_mma_kernel<<<dim3(CC / 128, SPLIT, BB), 256>>>();
        reduce_l2norm_kernel<<<BB * KK, 128>>>(s == 2 ? out_mu : nullptr);
    }

    // recon -> xr splits
    recon_mma_kernel<<<dim3(HW / 128, CC / 128, BB), 256>>>();

    // conv2 -> g_buf1 fp32
    conv_mma_kernel<<<dim3(HW / 128, CC / 128, BB), 256>>>(nullptr, 1);

    bn_stats_kernel<<<CC, 256>>>(gamma, beta);
    final_kernel<<<dim3(HW / 1024, CC, BB), 256>>>(x, out);
    zt_kernel<<<dim3(HW / 32, KK / 32, BB), dim3(32, 8)>>>(out_zt);
}

// round 5
// speedup vs baseline: 2.0608x; 1.0028x over previous
#include <cuda_runtime.h>
#include <cuda_bf16.h>
#include <cstdint>
#include <math.h>

#define BB 16
#define CC 512
#define HW 4096
#define KK 64
#define SPLIT 8

// ---------------------------------------------------------------------------
// Scratch
// ---------------------------------------------------------------------------
__device__ float g_buf1[BB * CC * HW];            // x2 (conv2 out) fp32
__device__ float g_z[BB * HW * KK];               // z fp32 [b][n][k] (last stage only)
__device__ float g_mu[BB * CC * KK];              // mu fp32 scratch
__device__ float g_mu_part[BB * SPLIT * CC * KK];
__device__ float g_scale[CC];
__device__ float g_shift[CC];

__device__ __nv_bfloat16 g_w1hi[CC * CC], g_w1lo[CC * CC];
__device__ __nv_bfloat16 g_w2hi[CC * CC], g_w2lo[CC * CC];
__device__ __nv_bfloat16 g_xhi[BB * CC * HW],  g_xlo[BB * CC * HW];
__device__ __nv_bfloat16 g_xfhi[BB * CC * HW], g_xflo[BB * CC * HW];
__device__ __nv_bfloat16 g_xrhi[BB * CC * HW], g_xrlo[BB * CC * HW];
__device__ __nv_bfloat16 g_zhi[BB * HW * KK],  g_zlo[BB * HW * KK];
__device__ __nv_bfloat16 g_muhi[BB * CC * KK], g_mulo[BB * CC * KK];

// ---------------------------------------------------------------------------
// PTX helpers
// ---------------------------------------------------------------------------
__device__ __forceinline__ uint32_t smem_u32(const void* p) {
    return (uint32_t)__cvta_generic_to_shared(p);
}
__device__ __forceinline__ void cp_async16(uint32_t saddr, const void* gaddr) {
    asm volatile("cp.async.cg.shared.global [%0], [%1], 16;" :: "r"(saddr), "l"(gaddr));
}
__device__ __forceinline__ void ldsm_x4(uint32_t& r0, uint32_t& r1, uint32_t& r2, uint32_t& r3, uint32_t a) {
    asm volatile("ldmatrix.sync.aligned.m8n8.x4.shared.b16 {%0,%1,%2,%3}, [%4];"
                 : "=r"(r0), "=r"(r1), "=r"(r2), "=r"(r3) : "r"(a));
}
__device__ __forceinline__ void ldsm_x4_t(uint32_t& r0, uint32_t& r1, uint32_t& r2, uint32_t& r3, uint32_t a) {
    asm volatile("ldmatrix.sync.aligned.m8n8.x4.trans.shared.b16 {%0,%1,%2,%3}, [%4];"
                 : "=r"(r0), "=r"(r1), "=r"(r2), "=r"(r3) : "r"(a));
}
__device__ __forceinline__ void mma_bf16(float* c, uint32_t a0, uint32_t a1, uint32_t a2, uint32_t a3,
                                         uint32_t b0, uint32_t b1) {
    asm volatile("mma.sync.aligned.m16n8k16.row.col.f32.bf16.bf16.f32 "
                 "{%0,%1,%2,%3}, {%4,%5,%6,%7}, {%8,%9}, {%0,%1,%2,%3};"
                 : "+f"(c[0]), "+f"(c[1]), "+f"(c[2]), "+f"(c[3])
                 : "r"(a0), "r"(a1), "r"(a2), "r"(a3), "r"(b0), "r"(b1));
}
__device__ __forceinline__ void split_val(float v, __nv_bfloat16& h, __nv_bfloat16& l) {
    h = __float2bfloat16(v);
    l = __float2bfloat16(v - __bfloat162float(h));
}

// Pipeline step: wait correctly at tail, sync, prefetch next+1
#define PIPE_WAIT_SYNC(IT, NT)                                   \
    if ((IT) + 2 < (NT)) { asm volatile("cp.async.wait_group 1;"); } \
    else                 { asm volatile("cp.async.wait_group 0;"); } \
    __syncthreads();

// ---------------------------------------------------------------------------
// Conversions
// ---------------------------------------------------------------------------
__global__ void split_w_kernel(const float* __restrict__ w1, const float* __restrict__ w2) {
    int i = blockIdx.x * 256 + threadIdx.x;
    split_val(w1[i], g_w1hi[i], g_w1lo[i]);
    split_val(w2[i], g_w2hi[i], g_w2lo[i]);
}
__global__ void split_x_kernel(const float* __restrict__ x) {
    size_t i = ((size_t)blockIdx.x * 256 + threadIdx.x) * 4;
    float4 v = *reinterpret_cast<const float4*>(&x[i]);
    __nv_bfloat16 h0, h1, h2, h3, l0, l1, l2, l3;
    split_val(v.x, h0, l0); split_val(v.y, h1, l1);
    split_val(v.z, h2, l2); split_val(v.w, h3, l3);
    *reinterpret_cast<__nv_bfloat162*>(&g_xhi[i])     = __nv_bfloat162{h0, h1};
    *reinterpret_cast<__nv_bfloat162*>(&g_xhi[i + 2]) = __nv_bfloat162{h2, h3};
    *reinterpret_cast<__nv_bfloat162*>(&g_xlo[i])     = __nv_bfloat162{l0, l1};
    *reinterpret_cast<__nv_bfloat162*>(&g_xlo[i + 2]) = __nv_bfloat162{l2, l3};
}
__global__ void copymu_kernel(const float* __restrict__ mu_in) {
    int b = blockIdx.y;
    int i = blockIdx.x * 256 + threadIdx.x;
    __nv_bfloat16 h, l; split_val(mu_in[i], h, l);
    size_t idx = (size_t)b * CC * KK + i;
    g_muhi[idx] = h; g_mulo[idx] = l;
}

// ---------------------------------------------------------------------------
// conv GEMM (tensor, split-bf16 3 passes), 3-stage cp.async ring, 1 sync/iter
// ---------------------------------------------------------------------------
#define APITCH 40
#define BPITCH 136
__global__ __launch_bounds__(256) void conv_mma_kernel(const float* __restrict__ bias, int sel) {
    const int b  = blockIdx.z;
    const int m0 = blockIdx.y * 128;
    const int n0 = blockIdx.x * 128;
    const int tid  = threadIdx.x;
    const int lane = tid & 31;
    const int wid  = tid >> 5;
    const int wm   = (wid & 1) * 64;
    const int wn   = (wid >> 1) * 32;

    __shared__ __nv_bfloat16 As[3][128 * APITCH];
    __shared__ __nv_bfloat16 Bs[3][32 * BPITCH];

    const __nv_bfloat16* Whi = sel ? g_w2hi : g_w1hi;
    const __nv_bfloat16* Wlo = sel ? g_w2lo : g_w1lo;
    const __nv_bfloat16* Xhi = (sel ? g_xrhi : g_xhi) + (size_t)b * CC * HW;
    const __nv_bfloat16* Xlo = (sel ? g_xrlo : g_xlo) + (size_t)b * CC * HW;

    float acc[4][4][4];
#pragma unroll
    for (int i = 0; i < 4; i++)
#pragma unroll
        for (int j = 0; j < 4; j++)
#pragma unroll
            for (int q = 0; q < 4; q++) acc[i][j][q] = 0.f;

    const uint32_t sA0 = smem_u32(As[0]);
    const uint32_t sB0 = smem_u32(Bs[0]);
    const uint32_t sAsz = 128 * APITCH * 2;
    const uint32_t sBsz = 32 * BPITCH * 2;

    const int aq0 = tid, aq1 = tid + 256;
    const int ar0 = aq0 >> 2, ac0 = (aq0 & 3) * 8;
    const int ar1 = aq1 >> 2, ac1 = (aq1 & 3) * 8;
    const int br0 = aq0 >> 4, bc0 = (aq0 & 15) * 8;
    const int br1 = aq1 >> 4, bc1 = (aq1 & 15) * 8;

    const int NT = 48;

#define LOAD_TILE(IT, BUF) do {                                                   \
        int pass = (IT) >> 4, k0 = ((IT) & 15) * 32;                              \
        const __nv_bfloat16* Ap = (pass == 1) ? Wlo : Whi;                        \
        const __nv_bfloat16* Bp = (pass == 2) ? Xlo : Xhi;                        \
        uint32_t sa = sA0 + (BUF) * sAsz, sb = sB0 + (BUF) * sBsz;                \
        cp_async16(sa + (ar0 * APITCH + ac0) * 2, Ap + (size_t)(m0 + ar0) * CC + k0 + ac0); \
        cp_async16(sa + (ar1 * APITCH + ac1) * 2, Ap + (size_t)(m0 + ar1) * CC + k0 + ac1); \
        cp_async16(sb + (br0 * BPITCH + bc0) * 2, Bp + (size_t)(k0 + br0) * HW + n0 + bc0); \
        cp_async16(sb + (br1 * BPITCH + bc1) * 2, Bp + (size_t)(k0 + br1) * HW + n0 + bc1); \
        asm volatile("cp.async.commit_group;");                                   \
    } while (0)

    LOAD_TILE(0, 0);
    LOAD_TILE(1, 1);
    int buf = 0;
    for (int it = 0; it < NT; ++it) {
        PIPE_WAIT_SYNC(it, NT);
        if (it + 2 < NT) {
            int nb = buf + 2; if (nb >= 3) nb -= 3;
            LOAD_TILE(it + 2, nb);
        }
        const uint32_t sa = sA0 + buf * sAsz;
        const uint32_t sb = sB0 + buf * sBsz;
#pragma unroll
        for (int kk = 0; kk < 32; kk += 16) {
            uint32_t a[4][4], bfr[2][4];
#pragma unroll
            for (int im = 0; im < 4; im++) {
                uint32_t addr = sa + (((wm + im * 16 + (lane & 15)) * APITCH) + kk + ((lane >> 4) << 3)) * 2;
                ldsm_x4(a[im][0], a[im][1], a[im][2], a[im][3], addr);
            }
#pragma unroll
            for (int jn = 0; jn < 2; jn++) {
                uint32_t addr = sb + (((kk + (lane & 7) + ((lane >> 3) & 1) * 8) * BPITCH)
                                      + wn + jn * 16 + ((lane >> 4) << 3)) * 2;
                ldsm_x4_t(bfr[jn][0], bfr[jn][1], bfr[jn][2], bfr[jn][3], addr);
            }
#pragma unroll
            for (int im = 0; im < 4; im++)
#pragma unroll
                for (int jn = 0; jn < 2; jn++) {
                    mma_bf16(acc[im][jn * 2 + 0], a[im][0], a[im][1], a[im][2], a[im][3], bfr[jn][0], bfr[jn][1]);
                    mma_bf16(acc[im][jn * 2 + 1], a[im][0], a[im][1], a[im][2], a[im][3], bfr[jn][2], bfr[jn][3]);
                }
        }
        if (++buf == 3) buf = 0;
    }
#undef LOAD_TILE

    if (sel == 0) {
        __nv_bfloat16* Oh = g_xfhi + (size_t)b * CC * HW;
        __nv_bfloat16* Ol = g_xflo + (size_t)b * CC * HW;
#pragma unroll
        for (int im = 0; im < 4; im++) {
            int row = m0 + wm + im * 16 + (lane >> 2);
            float bv0 = bias[row], bv1 = bias[row + 8];
#pragma unroll
            for (int j8 = 0; j8 < 4; j8++) {
                int col = n0 + wn + j8 * 8 + (lane & 3) * 2;
                __nv_bfloat16 h0, h1, h2, h3, l0, l1, l2, l3;
                split_val(acc[im][j8][0] + bv0, h0, l0);
                split_val(acc[im][j8][1] + bv0, h1, l1);
                split_val(acc[im][j8][2] + bv1, h2, l2);
                split_val(acc[im][j8][3] + bv1, h3, l3);
                *reinterpret_cast<__nv_bfloat162*>(&Oh[(size_t)row * HW + col]) = __nv_bfloat162{h0, h1};
                *reinterpret_cast<__nv_bfloat162*>(&Ol[(size_t)row * HW + col]) = __nv_bfloat162{l0, l1};
                *reinterpret_cast<__nv_bfloat162*>(&Oh[(size_t)(row + 8) * HW + col]) = __nv_bfloat162{h2, h3};
                *reinterpret_cast<__nv_bfloat162*>(&Ol[(size_t)(row + 8) * HW + col]) = __nv_bfloat162{l2, l3};
            }
        }
    } else {
        float* Yb = g_buf1 + (size_t)b * CC * HW;
#pragma unroll
        for (int im = 0; im < 4; im++) {
            int row = m0 + wm + im * 16 + (lane >> 2);
#pragma unroll
            for (int j8 = 0; j8 < 4; j8++) {
                int col = n0 + wn + j8 * 8 + (lane & 3) * 2;
                float2 v0 = {acc[im][j8][0], acc[im][j8][1]};
                float2 v1 = {acc[im][j8][2], acc[im][j8][3]};
                *reinterpret_cast<float2*>(&Yb[(size_t)row * HW + col]) = v0;
                *reinterpret_cast<float2*>(&Yb[(size_t)(row + 8) * HW + col]) = v1;
            }
        }
    }
}

// ---------------------------------------------------------------------------
// E-step (tensor): logits -> softmax -> z splits (+ fp32 z if write_z)
// ---------------------------------------------------------------------------
#define EAP 136
#define EBP 72
__global__ __launch_bounds__(256) void estep_mma_kernel(int write_z) {
    const int b  = blockIdx.y;
    const int n0 = blockIdx.x * 128;
    const int tid  = threadIdx.x;
    const int lane = tid & 31;
    const int wid  = tid >> 5;
    const int wm   = (wid & 3) * 32;
    const int wn   = (wid >> 2) * 32;

    __shared__ __align__(16) char sm[3 * 32 * EAP * 2 + 3 * 32 * EBP * 2];
    __nv_bfloat16* As = (__nv_bfloat16*)sm;
    __nv_bfloat16* Bs = (__nv_bfloat16*)(sm + 3 * 32 * EAP * 2);
    float* L = (float*)sm;

    const __nv_bfloat16* Xh = g_xfhi + (size_t)b * CC * HW;
    const __nv_bfloat16* Xl = g_xflo + (size_t)b * CC * HW;
    const __nv_bfloat16* Mh = g_muhi + (size_t)b * CC * KK;
    const __nv_bfloat16* Ml = g_mulo + (size_t)b * CC * KK;

    float acc[2][4][4];
#pragma unroll
    for (int i = 0; i < 2; i++)
#pragma unroll
        for (int j = 0; j < 4; j++)
#pragma unroll
            for (int q = 0; q < 4; q++) acc[i][j][q] = 0.f;

    const uint32_t sA0 = smem_u32(As);
    const uint32_t sB0 = smem_u32(Bs);
    const uint32_t sAsz = 32 * EAP * 2;
    const uint32_t sBsz = 32 * EBP * 2;

    const int aq0 = tid, aq1 = tid + 256;
    const int ar0 = aq0 >> 4, ac0 = (aq0 & 15) * 8;
    const int ar1 = aq1 >> 4, ac1 = (aq1 & 15) * 8;
    const int br = tid >> 3, bc = (tid & 7) * 8;

    const int NT = 48;
#define LOAD_TILE(IT, BUF) do {                                                   \
        int pass = (IT) >> 4, k0 = ((IT) & 15) * 32;                              \
        const __nv_bfloat16* Ap = (pass == 1) ? Xl : Xh;                          \
        const __nv_bfloat16* Bp = (pass == 2) ? Ml : Mh;                          \
        uint32_t sa = sA0 + (BUF) * sAsz, sb = sB0 + (BUF) * sBsz;                \
        cp_async16(sa + (ar0 * EAP + ac0) * 2, Ap + (size_t)(k0 + ar0) * HW + n0 + ac0); \
        cp_async16(sa + (ar1 * EAP + ac1) * 2, Ap + (size_t)(k0 + ar1) * HW + n0 + ac1); \
        cp_async16(sb + (br * EBP + bc) * 2,  Bp + (size_t)(k0 + br) * KK + bc);  \
        asm volatile("cp.async.commit_group;");                                   \
    } while (0)

    LOAD_TILE(0, 0);
    LOAD_TILE(1, 1);
    int buf = 0;
    for (int it = 0; it < NT; ++it) {
        PIPE_WAIT_SYNC(it, NT);
        if (it + 2 < NT) {
            int nb = buf + 2; if (nb >= 3) nb -= 3;
            LOAD_TILE(it + 2, nb);
        }
        const uint32_t sa = sA0 + buf * sAsz;
        const uint32_t sb = sB0 + buf * sBsz;
#pragma unroll
        for (int kk = 0; kk < 32; kk += 16) {
            uint32_t a[2][4], bfr[2][4];
#pragma unroll
            for (int f = 0; f < 2; f++) {
                uint32_t addr = sa + (((kk + (lane & 7) + ((lane >> 4) << 3)) * EAP)
                                      + wm + f * 16 + ((lane >> 3) & 1) * 8) * 2;
                ldsm_x4_t(a[f][0], a[f][1], a[f][2], a[f][3], addr);
            }
#pragma unroll
            for (int jn = 0; jn < 2; jn++) {
                uint32_t addr = sb + (((kk + (lane & 7) + ((lane >> 3) & 1) * 8) * EBP)
                                      + wn + jn * 16 + ((lane >> 4) << 3)) * 2;
                ldsm_x4_t(bfr[jn][0], bfr[jn][1], bfr[jn][2], bfr[jn][3], addr);
            }
#pragma unroll
            for (int f = 0; f < 2; f++)
#pragma unroll
                for (int jn = 0; jn < 2; jn++) {
                    mma_bf16(acc[f][jn * 2 + 0], a[f][0], a[f][1], a[f][2], a[f][3], bfr[jn][0], bfr[jn][1]);
                    mma_bf16(acc[f][jn * 2 + 1], a[f][0], a[f][1], a[f][2], a[f][3], bfr[jn][2], bfr[jn][3]);
                }
        }
        if (++buf == 3) buf = 0;
    }
#undef LOAD_TILE

    __syncthreads();  // all compute done before L overwrites As/Bs

#pragma unroll
    for (int f = 0; f < 2; f++) {
        int row = wm + f * 16 + (lane >> 2);
#pragma unroll
        for (int j8 = 0; j8 < 4; j8++) {
            int col = wn + j8 * 8 + (lane & 3) * 2;
            *reinterpret_cast<float2*>(&L[row * 68 + col])       = {acc[f][j8][0], acc[f][j8][1]};
            *reinterpret_cast<float2*>(&L[(row + 8) * 68 + col]) = {acc[f][j8][2], acc[f][j8][3]};
        }
    }
    __syncthreads();

    for (int i = 0; i < 16; i++) {
        int r = wid * 16 + i;
        float v0 = L[r * 68 + lane], v1 = L[r * 68 + lane + 32];
        float m = fmaxf(v0, v1);
#pragma unroll
        for (int off = 16; off > 0; off >>= 1)
            m = fmaxf(m, __shfl_xor_sync(0xffffffffu, m, off));
        float e0 = expf(v0 - m), e1 = expf(v1 - m);
        float s = e0 + e1;
#pragma unroll
        for (int off = 16; off > 0; off >>= 1)
            s += __shfl_xor_sync(0xffffffffu, s, off);
        float inv = 1.f / s;
        float z0 = e0 * inv, z1 = e1 * inv;
        size_t base = (size_t)b * HW * KK + (size_t)(n0 + r) * KK;
        if (write_z) {
            g_z[base + lane]      = z0;
            g_z[base + lane + 32] = z1;
        }
        __nv_bfloat16 h, l;
        split_val(z0, h, l); g_zhi[base + lane] = h;      g_zlo[base + lane] = l;
        split_val(z1, h, l); g_zhi[base + lane + 32] = h; g_zlo[base + lane + 32] = l;
    }
}

// ---------------------------------------------------------------------------
// M-step (tensor, split-K over n)
// ---------------------------------------------------------------------------
#define MAP 40
#define MBP 72
__global__ __launch_bounds__(256) void mstep_mma_kernel() {
    const int b  = blockIdx.z;
    const int s  = blockIdx.y;
    const int c0 = blockIdx.x * 128;
    const int tid  = threadIdx.x;
    const int lane = tid & 31;
    const int wid  = tid >> 5;
    const int wm   = (wid & 3) * 32;
    const int wn   = (wid >> 2) * 32;

    __shared__ __nv_bfloat16 As[3][128 * MAP];
    __shared__ __nv_bfloat16 Bs[3][32 * MBP];

    const __nv_bfloat16* Xh = g_xfhi + (size_t)b * CC * HW;
    const __nv_bfloat16* Xl = g_xflo + (size_t)b * CC * HW;
    const __nv_bfloat16* Zh = g_zhi  + (size_t)b * HW * KK;
    const __nv_bfloat16* Zl = g_zlo  + (size_t)b * HW * KK;

    float acc[2][4][4];
#pragma unroll
    for (int i = 0; i < 2; i++)
#pragma unroll
        for (int j = 0; j < 4; j++)
#pragma unroll
            for (int q = 0; q < 4; q++) acc[i][j][q] = 0.f;

    const uint32_t sA0 = smem_u32(As[0]);
    const uint32_t sB0 = smem_u32(Bs[0]);
    const uint32_t sAsz = 128 * MAP * 2;
    const uint32_t sBsz = 32 * MBP * 2;

    const int aq0 = tid, aq1 = tid + 256;
    const int ar0 = aq0 >> 2, ac0 = (aq0 & 3) * 8;
    const int ar1 = aq1 >> 2, ac1 = (aq1 & 3) * 8;
    const int br = tid >> 3, bc = (tid & 7) * 8;

    const int nbeg = s * (HW / SPLIT);
    const int NT = 48;
#define LOAD_TILE(IT, BUF) do {                                                   \
        int pass = (IT) >> 4, n0 = nbeg + ((IT) & 15) * 32;                       \
        const __nv_bfloat16* Ap = (pass == 1) ? Xl : Xh;                          \
        const __nv_bfloat16* Bp = (pass == 2) ? Zl : Zh;                          \
        uint32_t sa = sA0 + (BUF) * sAsz, sb = sB0 + (BUF) * sBsz;                \
        cp_async16(sa + (ar0 * MAP + ac0) * 2, Ap + (size_t)(c0 + ar0) * HW + n0 + ac0); \
        cp_async16(sa + (ar1 * MAP + ac1) * 2, Ap + (size_t)(c0 + ar1) * HW + n0 + ac1); \
        cp_async16(sb + (br * MBP + bc) * 2,  Bp + (size_t)(n0 + br) * KK + bc);  \
        asm volatile("cp.async.commit_group;");                                   \
    } while (0)

    LOAD_TILE(0, 0);
    LOAD_TILE(1, 1);
    int buf = 0;
    for (int it = 0; it < NT; ++it) {
        PIPE_WAIT_SYNC(it, NT);
        if (it + 2 < NT) {
            int nb = buf + 2; if (nb >= 3) nb -= 3;
            LOAD_TILE(it + 2, nb);
        }
        const uint32_t sa = sA0 + buf * sAsz;
        const uint32_t sb = sB0 + buf * sBsz;
#pragma unroll
        for (int kk = 0; kk < 32; kk += 16) {
            uint32_t a[2][4], bfr[2][4];
#pragma unroll
            for (int f = 0; f < 2; f++) {
                uint32_t addr = sa + (((wm + f * 16 + (lane & 15)) * MAP) + kk + ((lane >> 4) << 3)) * 2;
                ldsm_x4(a[f][0], a[f][1], a[f][2], a[f][3], addr);
            }
#pragma unroll
            for (int jn = 0; jn < 2; jn++) {
                uint32_t addr = sb + (((kk + (lane & 7) + ((lane >> 3) & 1) * 8) * MBP)
                                      + wn + jn * 16 + ((lane >> 4) << 3)) * 2;
                ldsm_x4_t(bfr[jn][0], bfr[jn][1], bfr[jn][2], bfr[jn][3], addr);
            }
#pragma unroll
            for (int f = 0; f < 2; f++)
#pragma unroll
                for (int jn = 0; jn < 2; jn++) {
                    mma_bf16(acc[f][jn * 2 + 0], a[f][0], a[f][1], a[f][2], a[f][3], bfr[jn][0], bfr[jn][1]);
                    mma_bf16(acc[f][jn * 2 + 1], a[f][0], a[f][1], a[f][2], a[f][3], bfr[jn][2], bfr[jn][3]);
                }
        }
        if (++buf == 3) buf = 0;
    }
#undef LOAD_TILE

    float* outp = g_mu_part + ((size_t)b * SPLIT + s) * CC * KK;
#pragma unroll
    for (int f = 0; f < 2; f++) {
        int row = c0 + wm + f * 16 + (lane >> 2);
#pragma unroll
        for (int j8 = 0; j8 < 4; j8++) {
            int col = wn + j8 * 8 + (lane & 3) * 2;
            *reinterpret_cast<float2*>(&outp[(size_t)row * KK + col])       = {acc[f][j8][0], acc[f][j8][1]};
            *reinterpret_cast<float2*>(&outp[(size_t)(row + 8) * KK + col]) = {acc[f][j8][2], acc[f][j8][3]};
        }
    }
}

// ---------------------------------------------------------------------------
// Reduce split-K partials + l2-normalize
// ---------------------------------------------------------------------------
__global__ void reduce_l2norm_kernel(float* __restrict__ out_mu) {
    const int bk = blockIdx.x;
    const int b = bk >> 6, k = bk & 63;
    const int tid = threadIdx.x;

    float* mub = g_mu + (size_t)b * CC * KK;
    const float* part = g_mu_part + (size_t)b * SPLIT * CC * KK;

    float s2 = 0.f;
    for (int c = tid; c < CC; c += 128) {
        float v = 0.f;
#pragma unroll
        for (int s = 0; s < SPLIT; s++)
            v += part[(size_t)s * CC * KK + (size_t)c * KK + k];
        mub[(size_t)c * KK + k] = v;
        s2 += v * v;
    }
    __shared__ float red[128];
    red[tid] = s2; __syncthreads();
    for (int st = 64; st > 0; st >>= 1) {
        if (tid < st) red[tid] += red[tid + st];
        __syncthreads();
    }
    float scale = 1.f / (1e-6f + sqrtf(red[0]));
    for (int c = tid; c < CC; c += 128) {
        size_t idx = (size_t)b * CC * KK + (size_t)c * KK + k;
        float v = mub[(size_t)c * KK + k] * scale;
        __nv_bfloat16 h, l; split_val(v, h, l);
        g_muhi[idx] = h; g_mulo[idx] = l;
        if (out_mu) out_mu[idx] = v;
    }
}

// ---------------------------------------------------------------------------
// Reconstruction (tensor): xr = relu(mu @ z^T) -> splits
// ---------------------------------------------------------------------------
#define RP 40
__global__ __launch_bounds__(256) void recon_mma_kernel() {
    const int b  = blockIdx.z;
    const int c0 = blockIdx.y * 128;
    const int n0 = blockIdx.x * 128;
    const int tid  = threadIdx.x;
    const int lane = tid & 31;
    const int wid  = tid >> 5;
    const int wm   = (wid & 1) * 64;
    const int wn   = (wid >> 1) * 32;

    __shared__ __nv_bfloat16 As[3][128 * RP];
    __shared__ __nv_bfloat16 Bs[3][128 * RP];

    const __nv_bfloat16* Mh = g_muhi + (size_t)b * CC * KK;
    const __nv_bfloat16* Ml = g_mulo + (size_t)b * CC * KK;
    const __nv_bfloat16* Zh = g_zhi  + (size_t)b * HW * KK;
    const __nv_bfloat16* Zl = g_zlo  + (size_t)b * HW * KK;

    float acc[4][4][4];
#pragma unroll
    for (int i = 0; i < 4; i++)
#pragma unroll
        for (int j = 0; j < 4; j++)
#pragma unroll
            for (int q = 0; q < 4; q++) acc[i][j][q] = 0.f;

    const uint32_t sA0 = smem_u32(As[0]);
    const uint32_t sB0 = smem_u32(Bs[0]);
    const uint32_t ssz = 128 * RP * 2;

    const int aq0 = tid, aq1 = tid + 256;
    const int ar0 = aq0 >> 2, ac0 = (aq0 & 3) * 8;
    const int ar1 = aq1 >> 2, ac1 = (aq1 & 3) * 8;

    const int NT = 6;
#define LOAD_TILE(IT, BUF) do {                                                   \
        int pass = (IT) >> 1, k0 = ((IT) & 1) * 32;                               \
        const __nv_bfloat16* Ap = (pass == 1) ? Ml : Mh;                          \
        const __nv_bfloat16* Bp = (pass == 2) ? Zl : Zh;                          \
        uint32_t sa = sA0 + (BUF) * ssz, sb = sB0 + (BUF) * ssz;                  \
        cp_async16(sa + (ar0 * RP + ac0) * 2, Ap + (size_t)(c0 + ar0) * KK + k0 + ac0); \
        cp_async16(sa + (ar1 * RP + ac1) * 2, Ap + (size_t)(c0 + ar1) * KK + k0 + ac1); \
        cp_async16(sb + (ar0 * RP + ac0) * 2, Bp + (size_t)(n0 + ar0) * KK + k0 + ac0); \
        cp_async16(sb + (ar1 * RP + ac1) * 2, Bp + (size_t)(n0 + ar1) * KK + k0 + ac1); \
        asm volatile("cp.async.commit_group;");                                   \
    } while (0)

    LOAD_TILE(0, 0);
    LOAD_TILE(1, 1);
    int buf = 0;
    for (int it = 0; it < NT; ++it) {
        PIPE_WAIT_SYNC(it, NT);
        if (it + 2 < NT) {
            int nb = buf + 2; if (nb >= 3) nb -= 3;
            LOAD_TILE(it + 2, nb);
        }
        const uint32_t sa = sA0 + buf * ssz;
        const uint32_t sb = sB0 + buf * ssz;
#pragma unroll
        for (int kk = 0; kk < 32; kk += 16) {
            uint32_t a[4][4], bfr[2][4];
#pragma unroll
            for (int im = 0; im < 4; im++) {
                uint32_t addr = sa + (((wm + im * 16 + (lane & 15)) * RP) + kk + ((lane >> 4) << 3)) * 2;
                ldsm_x4(a[im][0], a[im][1], a[im][2], a[im][3], addr);
            }
#pragma unroll
            for (int jn = 0; jn < 2; jn++) {
                uint32_t addr = sb + (((wn + jn * 16 + (lane & 7) + ((lane >> 4) << 3)) * RP)
                                      + kk + ((lane >> 3) & 1) * 8) * 2;
                ldsm_x4(bfr[jn][0], bfr[jn][1], bfr[jn][2], bfr[jn][3], addr);
            }
#pragma unroll
            for (int im = 0; im < 4; im++)
#pragma unroll
                for (int jn = 0; jn < 2; jn++) {
                    mma_bf16(acc[im][jn * 2 + 0], a[im][0], a[im][1], a[im][2], a[im][3], bfr[jn][0], bfr[jn][1]);
                    mma_bf16(acc[im][jn * 2 + 1], a[im][0], a[im][1], a[im][2], a[im][3], bfr[jn][2], bfr[jn][3]);
                }
        }
        if (++buf == 3) buf = 0;
    }
#undef LOAD_TILE

    __nv_bfloat16* Oh = g_xrhi + (size_t)b * CC * HW;
    __nv_bfloat16* Ol = g_xrlo + (size_t)b * CC * HW;
#pragma unroll
    for (int im = 0; im < 4; im++) {
        int row = c0 + wm + im * 16 + (lane >> 2);
#pragma unroll
        for (int j8 = 0; j8 < 4; j8++) {
            int col = n0 + wn + j8 * 8 + (lane & 3) * 2;
            __nv_bfloat16 h0, h1, h2, h3, l0, l1, l2, l3;
            split_val(fmaxf(acc[im][j8][0], 0.f), h0, l0);
            split_val(fmaxf(acc[im][j8][1], 0.f), h1, l1);
            split_val(fmaxf(acc[im][j8][2], 0.f), h2, l2);
            split_val(fmaxf(acc[im][j8][3], 0.f), h3, l3);
            *reinterpret_cast<__nv_bfloat162*>(&Oh[(size_t)row * HW + col]) = __nv_bfloat162{h0, h1};
            *reinterpret_cast<__nv_bfloat162*>(&Ol[(size_t)row * HW + col]) = __nv_bfloat162{l0, l1};
            *reinterpret_cast<__nv_bfloat162*>(&Oh[(size_t)(row + 8) * HW + col]) = __nv_bfloat162{h2, h3};
            *reinterpret_cast<__nv_bfloat162*>(&Ol[(size_t)(row + 8) * HW + col]) = __nv_bfloat162{l2, l3};
        }
    }
}

// ---------------------------------------------------------------------------
// BatchNorm stats / final / z-transpose
// ---------------------------------------------------------------------------
__global__ void bn_stats_kernel(const float* __restrict__ gamma,
                                const float* __restrict__ beta) {
    const int o = blockIdx.x;
    const int tid = threadIdx.x;
    float s = 0.f, s2 = 0.f;
    for (int b = 0; b < BB; b++) {
        const float* p = g_buf1 + (size_t)b * CC * HW + (size_t)o * HW;
        for (int n = tid; n < HW; n += 256) {
            float v = p[n];
            s += v; s2 = fmaf(v, v, s2);
        }
    }
    __shared__ float r1[256], r2[256];
    r1[tid] = s; r2[tid] = s2; __syncthreads();
    for (int st = 128; st > 0; st >>= 1) {
        if (tid < st) { r1[tid] += r1[tid + st]; r2[tid] += r2[tid + st]; }
        __syncthreads();
    }
    if (tid == 0) {
        const float invM = 1.f / (float)(BB * HW);
        float mean = r1[0] * invM;
        float var  = r2[0] * invM - mean * mean;
        float sc = gamma[o] * rsqrtf(var + 1e-5f);
        g_scale[o] = sc;
        g_shift[o] = beta[o] - mean * sc;
    }
}

__global__ void final_kernel(const float* __restrict__ x, float* __restrict__ out) {
    const int b = blockIdx.z, o = blockIdx.y;
    const size_t base = (size_t)b * CC * HW + (size_t)o * HW
                      + (size_t)blockIdx.x * 1024 + (size_t)threadIdx.x * 4;
    const float sc = g_scale[o], sh = g_shift[o];
    float4 v2 = *reinterpret_cast<const float4*>(&g_buf1[base]);
    float4 vx = *reinterpret_cast<const float4*>(&x[base]);
    float4 r;
    r.x = fmaxf(fmaf(v2.x, sc, sh) + vx.x, 0.f);
    r.y = fmaxf(fmaf(v2.y, sc, sh) + vx.y, 0.f);
    r.z = fmaxf(fmaf(v2.z, sc, sh) + vx.z, 0.f);
    r.w = fmaxf(fmaf(v2.w, sc, sh) + vx.w, 0.f);
    *reinterpret_cast<float4*>(&out[base]) = r;
}

__global__ void zt_kernel(float* __restrict__ zt) {
    const int b  = blockIdx.z;
    const int n0 = blockIdx.x * 32;
    const int k0 = blockIdx.y * 32;
    __shared__ float t[32][33];
    const int tx = threadIdx.x, ty = threadIdx.y;
    const float* zb = g_z + (size_t)b * HW * KK;
#pragma unroll
    for (int c = 0; c < 32; c += 8)
        t[ty + c][tx] = zb[(size_t)(n0 + ty + c) * KK + k0 + tx];
    __syncthreads();
    float* ztb = zt + (size_t)b * KK * HW;
#pragma unroll
    for (int c = 0; c < 32; c += 8)
        ztb[(size_t)(k0 + ty + c) * HW + n0 + tx] = t[tx][ty + c];
}

// ---------------------------------------------------------------------------
// Launch
// ---------------------------------------------------------------------------
extern "C" void kernel_launch(void* const* d_in, const int* in_sizes, int n_in,
                              void* d_out, int out_size) {
    const float* x     = (const float*)d_in[0];
    const float* w1    = (const float*)d_in[1];
    const float* b1    = (const float*)d_in[2];
    const float* w2    = (const float*)d_in[3];
    const float* gamma = (const float*)d_in[4];
    const float* beta  = (const float*)d_in[5];
    const float* mu_in = (const float*)d_in[6];

    float* out    = (float*)d_out;
    float* out_mu = out + (size_t)BB * CC * HW;
    float* out_zt = out_mu + (size_t)BB * CC * KK;

    split_w_kernel<<<CC * CC / 256, 256>>>(w1, w2);
    split_x_kernel<<<(BB * CC * HW) / (256 * 4), 256>>>(x);
    copymu_kernel<<<dim3(CC * KK / 256, BB), 256>>>(mu_in);

    conv_mma_kernel<<<dim3(HW / 128, CC / 128, BB), 256>>>(b1, 0);

    for (int s = 0; s < 3; s++) {
        estep_mma_kernel<<<dim3(HW / 128, BB), 256>>>(s == 2 ? 1 : 0);
        mstep_mma_kernel<<<dim3(CC / 128, SPLIT, BB), 256>>>();
        reduce_l2norm_kernel<<<BB * KK, 128>>>(s == 2 ? out_mu : nullptr);
    }

    recon_mma_kernel<<<dim3(HW / 128, CC / 128, BB), 256>>>();
    conv_mma_kernel<<<dim3(HW / 128, CC / 128, BB), 256>>>(nullptr, 1);

    bn_stats_kernel<<<CC, 256>>>(gamma, beta);
    final_kernel<<<dim3(HW / 1024, CC, BB), 256>>>(x, out);
    zt_kernel<<<dim3(HW / 32, KK / 32, BB), dim3(32, 8)>>>(out_zt);
}

// round 7
// speedup vs baseline: 2.2822x; 1.1074x over previous
#include <cuda_runtime.h>
#include <cuda_bf16.h>
#include <cstdint>
#include <math.h>

#define BB 16
#define CC 512
#define HW 4096
#define KK 64
#define SPLIT 8

// ---------------------------------------------------------------------------
// Scratch
// ---------------------------------------------------------------------------
__device__ float g_buf1[BB * CC * HW];            // x2 (conv2 out) fp32
__device__ float g_z[BB * HW * KK];               // z fp32 (last stage only)
__device__ float g_mu[BB * CC * KK];
__device__ float g_mu_part[BB * SPLIT * CC * KK];
__device__ float g_scale[CC];
__device__ float g_shift[CC];

__device__ __nv_bfloat16 g_w1hi[CC * CC], g_w1lo[CC * CC];
__device__ __nv_bfloat16 g_w2hi[CC * CC], g_w2lo[CC * CC];
__device__ __nv_bfloat16 g_xhi[BB * CC * HW],  g_xlo[BB * CC * HW];
__device__ __nv_bfloat16 g_xfhi[BB * CC * HW], g_xflo[BB * CC * HW];
__device__ __nv_bfloat16 g_xrhi[BB * CC * HW], g_xrlo[BB * CC * HW];
__device__ __nv_bfloat16 g_zhi[BB * HW * KK],  g_zlo[BB * HW * KK];
__device__ __nv_bfloat16 g_muhi[BB * CC * KK], g_mulo[BB * CC * KK];

// ---------------------------------------------------------------------------
// PTX helpers
// ---------------------------------------------------------------------------
__device__ __forceinline__ uint32_t smem_u32(const void* p) {
    return (uint32_t)__cvta_generic_to_shared(p);
}
__device__ __forceinline__ void cp_async16(uint32_t saddr, const void* gaddr) {
    asm volatile("cp.async.cg.shared.global [%0], [%1], 16;" :: "r"(saddr), "l"(gaddr));
}
__device__ __forceinline__ void ldsm_x4(uint32_t& r0, uint32_t& r1, uint32_t& r2, uint32_t& r3, uint32_t a) {
    asm volatile("ldmatrix.sync.aligned.m8n8.x4.shared.b16 {%0,%1,%2,%3}, [%4];"
                 : "=r"(r0), "=r"(r1), "=r"(r2), "=r"(r3) : "r"(a));
}
__device__ __forceinline__ void ldsm_x4_t(uint32_t& r0, uint32_t& r1, uint32_t& r2, uint32_t& r3, uint32_t a) {
    asm volatile("ldmatrix.sync.aligned.m8n8.x4.trans.shared.b16 {%0,%1,%2,%3}, [%4];"
                 : "=r"(r0), "=r"(r1), "=r"(r2), "=r"(r3) : "r"(a));
}
__device__ __forceinline__ void mma_bf16(float* c, const uint32_t* a, uint32_t b0, uint32_t b1) {
    asm volatile("mma.sync.aligned.m16n8k16.row.col.f32.bf16.bf16.f32 "
                 "{%0,%1,%2,%3}, {%4,%5,%6,%7}, {%8,%9}, {%0,%1,%2,%3};"
                 : "+f"(c[0]), "+f"(c[1]), "+f"(c[2]), "+f"(c[3])
                 : "r"(a[0]), "r"(a[1]), "r"(a[2]), "r"(a[3]), "r"(b0), "r"(b1));
}
__device__ __forceinline__ void split_val(float v, __nv_bfloat16& h, __nv_bfloat16& l) {
    h = __float2bfloat16(v);
    l = __float2bfloat16(v - __bfloat162float(h));
}

// ---------------------------------------------------------------------------
// Conversions
// ---------------------------------------------------------------------------
__global__ void split_w_kernel(const float* __restrict__ w1, const float* __restrict__ w2) {
    int i = blockIdx.x * 256 + threadIdx.x;
    split_val(w1[i], g_w1hi[i], g_w1lo[i]);
    split_val(w2[i], g_w2hi[i], g_w2lo[i]);
}
__global__ void split_x_kernel(const float* __restrict__ x) {
    size_t i = ((size_t)blockIdx.x * 256 + threadIdx.x) * 4;
    float4 v = *reinterpret_cast<const float4*>(&x[i]);
    __nv_bfloat16 h0, h1, h2, h3, l0, l1, l2, l3;
    split_val(v.x, h0, l0); split_val(v.y, h1, l1);
    split_val(v.z, h2, l2); split_val(v.w, h3, l3);
    *reinterpret_cast<__nv_bfloat162*>(&g_xhi[i])     = __nv_bfloat162{h0, h1};
    *reinterpret_cast<__nv_bfloat162*>(&g_xhi[i + 2]) = __nv_bfloat162{h2, h3};
    *reinterpret_cast<__nv_bfloat162*>(&g_xlo[i])     = __nv_bfloat162{l0, l1};
    *reinterpret_cast<__nv_bfloat162*>(&g_xlo[i + 2]) = __nv_bfloat162{l2, l3};
}
__global__ void copymu_kernel(const float* __restrict__ mu_in) {
    int b = blockIdx.y;
    int i = blockIdx.x * 256 + threadIdx.x;
    __nv_bfloat16 h, l; split_val(mu_in[i], h, l);
    size_t idx = (size_t)b * CC * KK + i;
    g_muhi[idx] = h; g_mulo[idx] = l;
}

// ---------------------------------------------------------------------------
// conv GEMM, FUSED split-bf16: per k-tile load Ah,Al,Bh,Bl once and issue
// AhBh + AlBh + AhBl into the same accumulators. Double-buffered cp.async.
// Block 128x128, BK=32, 8 warps (2 x M, 4 x N), warp tile 64x32.
// ---------------------------------------------------------------------------
#define APITCH 40
#define BPITCH 136
#define CSTG_A (128 * APITCH * 2)
#define CSTG_B (32 * BPITCH * 2)
#define CONV_SMEM (4 * CSTG_A + 4 * CSTG_B)   // 75776 B

__global__ __launch_bounds__(256) void conv_mma_kernel(const float* __restrict__ bias, int sel) {
    extern __shared__ __align__(16) char csm[];
    const int b  = blockIdx.z;
    const int m0 = blockIdx.y * 128;
    const int n0 = blockIdx.x * 128;
    const int tid  = threadIdx.x;
    const int lane = tid & 31;
    const int wid  = tid >> 5;
    const int wm   = (wid & 1) * 64;
    const int wn   = (wid >> 1) * 32;

    const uint32_t base = smem_u32(csm);
    const uint32_t oAH = 0, oAL = 2 * CSTG_A;
    const uint32_t oBH = 4 * CSTG_A, oBL = 4 * CSTG_A + 2 * CSTG_B;

    const __nv_bfloat16* Whi = sel ? g_w2hi : g_w1hi;
    const __nv_bfloat16* Wlo = sel ? g_w2lo : g_w1lo;
    const __nv_bfloat16* Xhi = (sel ? g_xrhi : g_xhi) + (size_t)b * CC * HW;
    const __nv_bfloat16* Xlo = (sel ? g_xrlo : g_xlo) + (size_t)b * CC * HW;

    float acc[4][4][4];
#pragma unroll
    for (int i = 0; i < 4; i++)
#pragma unroll
        for (int j = 0; j < 4; j++)
#pragma unroll
            for (int q = 0; q < 4; q++) acc[i][j][q] = 0.f;

    const int ar0 = tid >> 2,          ac0 = (tid & 3) * 8;
    const int ar1 = (tid + 256) >> 2,  ac1 = (tid & 3) * 8;       // (tid+256)&3 == tid&3
    const int br0 = tid >> 4,          bc0 = (tid & 15) * 8;
    const int br1 = (tid + 256) >> 4,  bc1 = (tid & 15) * 8;

    const int NT = 16;

#define LOAD_TILE(IT, BUF) do {                                                   \
        int k0 = (IT) * 32;                                                       \
        uint32_t aH = base + oAH + (BUF) * CSTG_A, aL = base + oAL + (BUF) * CSTG_A; \
        uint32_t bH = base + oBH + (BUF) * CSTG_B, bL = base + oBL + (BUF) * CSTG_B; \
        cp_async16(aH + (ar0 * APITCH + ac0) * 2, Whi + (size_t)(m0 + ar0) * CC + k0 + ac0); \
        cp_async16(aH + (ar1 * APITCH + ac1) * 2, Whi + (size_t)(m0 + ar1) * CC + k0 + ac1); \
        cp_async16(aL + (ar0 * APITCH + ac0) * 2, Wlo + (size_t)(m0 + ar0) * CC + k0 + ac0); \
        cp_async16(aL + (ar1 * APITCH + ac1) * 2, Wlo + (size_t)(m0 + ar1) * CC + k0 + ac1); \
        cp_async16(bH + (br0 * BPITCH + bc0) * 2, Xhi + (size_t)(k0 + br0) * HW + n0 + bc0); \
        cp_async16(bH + (br1 * BPITCH + bc1) * 2, Xhi + (size_t)(k0 + br1) * HW + n0 + bc1); \
        cp_async16(bL + (br0 * BPITCH + bc0) * 2, Xlo + (size_t)(k0 + br0) * HW + n0 + bc0); \
        cp_async16(bL + (br1 * BPITCH + bc1) * 2, Xlo + (size_t)(k0 + br1) * HW + n0 + bc1); \
        asm volatile("cp.async.commit_group;");                                   \
    } while (0)

    LOAD_TILE(0, 0);
    for (int it = 0; it < NT; ++it) {
        if (it + 1 < NT) { LOAD_TILE(it + 1, (it + 1) & 1); asm volatile("cp.async.wait_group 1;"); }
        else             { asm volatile("cp.async.wait_group 0;"); }
        __syncthreads();

        const int buf = it & 1;
        const uint32_t aH = base + oAH + buf * CSTG_A, aL = base + oAL + buf * CSTG_A;
        const uint32_t bH = base + oBH + buf * CSTG_B, bL = base + oBL + buf * CSTG_B;
#pragma unroll
        for (int kk = 0; kk < 32; kk += 16) {
            uint32_t ah[4][4], al[4][4], bh[2][4], bl[2][4];
#pragma unroll
            for (int im = 0; im < 4; im++) {
                uint32_t off = (((wm + im * 16 + (lane & 15)) * APITCH) + kk + ((lane >> 4) << 3)) * 2;
                ldsm_x4(ah[im][0], ah[im][1], ah[im][2], ah[im][3], aH + off);
                ldsm_x4(al[im][0], al[im][1], al[im][2], al[im][3], aL + off);
            }
#pragma unroll
            for (int jn = 0; jn < 2; jn++) {
                uint32_t off = (((kk + (lane & 7) + ((lane >> 3) & 1) * 8) * BPITCH)
                                + wn + jn * 16 + ((lane >> 4) << 3)) * 2;
                ldsm_x4_t(bh[jn][0], bh[jn][1], bh[jn][2], bh[jn][3], bH + off);
                ldsm_x4_t(bl[jn][0], bl[jn][1], bl[jn][2], bl[jn][3], bL + off);
            }
#pragma unroll
            for (int im = 0; im < 4; im++)
#pragma unroll
                for (int jn = 0; jn < 2; jn++) {
                    mma_bf16(acc[im][jn * 2 + 0], ah[im], bh[jn][0], bh[jn][1]);
                    mma_bf16(acc[im][jn * 2 + 1], ah[im], bh[jn][2], bh[jn][3]);
                    mma_bf16(acc[im][jn * 2 + 0], al[im], bh[jn][0], bh[jn][1]);
                    mma_bf16(acc[im][jn * 2 + 1], al[im], bh[jn][2], bh[jn][3]);
                    mma_bf16(acc[im][jn * 2 + 0], ah[im], bl[jn][0], bl[jn][1]);
                    mma_bf16(acc[im][jn * 2 + 1], ah[im], bl[jn][2], bl[jn][3]);
                }
        }
        __syncthreads();
    }
#undef LOAD_TILE

    if (sel == 0) {
        __nv_bfloat16* Oh = g_xfhi + (size_t)b * CC * HW;
        __nv_bfloat16* Ol = g_xflo + (size_t)b * CC * HW;
#pragma unroll
        for (int im = 0; im < 4; im++) {
            int row = m0 + wm + im * 16 + (lane >> 2);
            float bv0 = bias[row], bv1 = bias[row + 8];
#pragma unroll
            for (int j8 = 0; j8 < 4; j8++) {
                int col = n0 + wn + j8 * 8 + (lane & 3) * 2;
                __nv_bfloat16 h0, h1, h2, h3, l0, l1, l2, l3;
                split_val(acc[im][j8][0] + bv0, h0, l0);
                split_val(acc[im][j8][1] + bv0, h1, l1);
                split_val(acc[im][j8][2] + bv1, h2, l2);
                split_val(acc[im][j8][3] + bv1, h3, l3);
                *reinterpret_cast<__nv_bfloat162*>(&Oh[(size_t)row * HW + col]) = __nv_bfloat162{h0, h1};
                *reinterpret_cast<__nv_bfloat162*>(&Ol[(size_t)row * HW + col]) = __nv_bfloat162{l0, l1};
                *reinterpret_cast<__nv_bfloat162*>(&Oh[(size_t)(row + 8) * HW + col]) = __nv_bfloat162{h2, h3};
                *reinterpret_cast<__nv_bfloat162*>(&Ol[(size_t)(row + 8) * HW + col]) = __nv_bfloat162{l2, l3};
            }
        }
    } else {
        float* Yb = g_buf1 + (size_t)b * CC * HW;
#pragma unroll
        for (int im = 0; im < 4; im++) {
            int row = m0 + wm + im * 16 + (lane >> 2);
#pragma unroll
            for (int j8 = 0; j8 < 4; j8++) {
                int col = n0 + wn + j8 * 8 + (lane & 3) * 2;
                float2 v0 = {acc[im][j8][0], acc[im][j8][1]};
                float2 v1 = {acc[im][j8][2], acc[im][j8][3]};
                *reinterpret_cast<float2*>(&Yb[(size_t)row * HW + col]) = v0;
                *reinterpret_cast<float2*>(&Yb[(size_t)(row + 8) * HW + col]) = v1;
            }
        }
    }
}

// ---------------------------------------------------------------------------
// E-step FUSED: logits[n,k] = sum_c xf[c,n]*mu[c,k] (3 split terms per k-tile),
// softmax -> z splits (+ fp32 z if write_z)
// ---------------------------------------------------------------------------
#define EAP 136
#define EBP 72
#define ESTG_A (32 * EAP * 2)
#define ESTG_B (32 * EBP * 2)
__global__ __launch_bounds__(256) void estep_mma_kernel(int write_z) {
    const int b  = blockIdx.y;
    const int n0 = blockIdx.x * 128;
    const int tid  = threadIdx.x;
    const int lane = tid & 31;
    const int wid  = tid >> 5;
    const int wm   = (wid & 3) * 32;
    const int wn   = (wid >> 2) * 32;

    __shared__ __align__(16) char sm[2 * (2 * ESTG_A + 2 * ESTG_B)];
    const uint32_t base = smem_u32(sm);
    const uint32_t oAH = 0, oAL = 2 * ESTG_A;
    const uint32_t oBH = 4 * ESTG_A, oBL = 4 * ESTG_A + 2 * ESTG_B;
    float* L = (float*)sm;

    const __nv_bfloat16* Xh = g_xfhi + (size_t)b * CC * HW;
    const __nv_bfloat16* Xl = g_xflo + (size_t)b * CC * HW;
    const __nv_bfloat16* Mh = g_muhi + (size_t)b * CC * KK;
    const __nv_bfloat16* Ml = g_mulo + (size_t)b * CC * KK;

    float acc[2][4][4];
#pragma unroll
    for (int i = 0; i < 2; i++)
#pragma unroll
        for (int j = 0; j < 4; j++)
#pragma unroll
            for (int q = 0; q < 4; q++) acc[i][j][q] = 0.f;

    const int ar0 = tid >> 4,         ac0 = (tid & 15) * 8;
    const int ar1 = (tid + 256) >> 4, ac1 = (tid & 15) * 8;
    const int br = tid >> 3, bc = (tid & 7) * 8;

    const int NT = 16;
#define LOAD_TILE(IT, BUF) do {                                                   \
        int k0 = (IT) * 32;                                                       \
        uint32_t aH = base + oAH + (BUF) * ESTG_A, aL = base + oAL + (BUF) * ESTG_A; \
        uint32_t bH = base + oBH + (BUF) * ESTG_B, bL = base + oBL + (BUF) * ESTG_B; \
        cp_async16(aH + (ar0 * EAP + ac0) * 2, Xh + (size_t)(k0 + ar0) * HW + n0 + ac0); \
        cp_async16(aH + (ar1 * EAP + ac1) * 2, Xh + (size_t)(k0 + ar1) * HW + n0 + ac1); \
        cp_async16(aL + (ar0 * EAP + ac0) * 2, Xl + (size_t)(k0 + ar0) * HW + n0 + ac0); \
        cp_async16(aL + (ar1 * EAP + ac1) * 2, Xl + (size_t)(k0 + ar1) * HW + n0 + ac1); \
        cp_async16(bH + (br * EBP + bc) * 2,  Mh + (size_t)(k0 + br) * KK + bc);  \
        cp_async16(bL + (br * EBP + bc) * 2,  Ml + (size_t)(k0 + br) * KK + bc);  \
        asm volatile("cp.async.commit_group;");                                   \
    } while (0)

    LOAD_TILE(0, 0);
    for (int it = 0; it < NT; ++it) {
        if (it + 1 < NT) { LOAD_TILE(it + 1, (it + 1) & 1); asm volatile("cp.async.wait_group 1;"); }
        else             { asm volatile("cp.async.wait_group 0;"); }
        __syncthreads();

        const int buf = it & 1;
        const uint32_t aH = base + oAH + buf * ESTG_A, aL = base + oAL + buf * ESTG_A;
        const uint32_t bH = base + oBH + buf * ESTG_B, bL = base + oBL + buf * ESTG_B;
#pragma unroll
        for (int kk = 0; kk < 32; kk += 16) {
            uint32_t ah[2][4], al[2][4], bh[2][4], bl[2][4];
#pragma unroll
            for (int f = 0; f < 2; f++) {
                uint32_t off = (((kk + (lane & 7) + ((lane >> 4) << 3)) * EAP)
                                + wm + f * 16 + ((lane >> 3) & 1) * 8) * 2;
                ldsm_x4_t(ah[f][0], ah[f][1], ah[f][2], ah[f][3], aH + off);
                ldsm_x4_t(al[f][0], al[f][1], al[f][2], al[f][3], aL + off);
            }
#pragma unroll
            for (int jn = 0; jn < 2; jn++) {
                uint32_t off = (((kk + (lane & 7) + ((lane >> 3) & 1) * 8) * EBP)
                                + wn + jn * 16 + ((lane >> 4) << 3)) * 2;
                ldsm_x4_t(bh[jn][0], bh[jn][1], bh[jn][2], bh[jn][3], bH + off);
                ldsm_x4_t(bl[jn][0], bl[jn][1], bl[jn][2], bl[jn][3], bL + off);
            }
#pragma unroll
            for (int f = 0; f < 2; f++)
#pragma unroll
                for (int jn = 0; jn < 2; jn++) {
                    mma_bf16(acc[f][jn * 2 + 0], ah[f], bh[jn][0], bh[jn][1]);
                    mma_bf16(acc[f][jn * 2 + 1], ah[f], bh[jn][2], bh[jn][3]);
                    mma_bf16(acc[f][jn * 2 + 0], al[f], bh[jn][0], bh[jn][1]);
                    mma_bf16(acc[f][jn * 2 + 1], al[f], bh[jn][2], bh[jn][3]);
                    mma_bf16(acc[f][jn * 2 + 0], ah[f], bl[jn][0], bl[jn][1]);
                    mma_bf16(acc[f][jn * 2 + 1], ah[f], bl[jn][2], bl[jn][3]);
                }
        }
        __syncthreads();
    }
#undef LOAD_TILE

#pragma unroll
    for (int f = 0; f < 2; f++) {
        int row = wm + f * 16 + (lane >> 2);
#pragma unroll
        for (int j8 = 0; j8 < 4; j8++) {
            int col = wn + j8 * 8 + (lane & 3) * 2;
            *reinterpret_cast<float2*>(&L[row * 68 + col])       = {acc[f][j8][0], acc[f][j8][1]};
            *reinterpret_cast<float2*>(&L[(row + 8) * 68 + col]) = {acc[f][j8][2], acc[f][j8][3]};
        }
    }
    __syncthreads();

    for (int i = 0; i < 16; i++) {
        int r = wid * 16 + i;
        float v0 = L[r * 68 + lane], v1 = L[r * 68 + lane + 32];
        float m = fmaxf(v0, v1);
#pragma unroll
        for (int off = 16; off > 0; off >>= 1)
            m = fmaxf(m, __shfl_xor_sync(0xffffffffu, m, off));
        float e0 = expf(v0 - m), e1 = expf(v1 - m);
        float s = e0 + e1;
#pragma unroll
        for (int off = 16; off > 0; off >>= 1)
            s += __shfl_xor_sync(0xffffffffu, s, off);
        float inv = 1.f / s;
        float z0 = e0 * inv, z1 = e1 * inv;
        size_t zbase = (size_t)b * HW * KK + (size_t)(n0 + r) * KK;
        if (write_z) {
            g_z[zbase + lane]      = z0;
            g_z[zbase + lane + 32] = z1;
        }
        __nv_bfloat16 h, l;
        split_val(z0, h, l); g_zhi[zbase + lane] = h;      g_zlo[zbase + lane] = l;
        split_val(z1, h, l); g_zhi[zbase + lane + 32] = h; g_zlo[zbase + lane + 32] = l;
    }
}

// ---------------------------------------------------------------------------
// M-step FUSED (split-K over n): mu_part[c,k] = sum_n xf[c,n]*z[n,k]
// ---------------------------------------------------------------------------
#define MAP 40
#define MBP 72
#define MSTG_A (128 * MAP * 2)
#define MSTG_B (32 * MBP * 2)
__global__ __launch_bounds__(256) void mstep_mma_kernel() {
    const int b  = blockIdx.z;
    const int s  = blockIdx.y;
    const int c0 = blockIdx.x * 128;
    const int tid  = threadIdx.x;
    const int lane = tid & 31;
    const int wid  = tid >> 5;
    const int wm   = (wid & 3) * 32;
    const int wn   = (wid >> 2) * 32;

    __shared__ __align__(16) char sm[2 * (2 * MSTG_A + 2 * MSTG_B)];
    const uint32_t base = smem_u32(sm);
    const uint32_t oAH = 0, oAL = 2 * MSTG_A;
    const uint32_t oBH = 4 * MSTG_A, oBL = 4 * MSTG_A + 2 * MSTG_B;

    const __nv_bfloat16* Xh = g_xfhi + (size_t)b * CC * HW;
    const __nv_bfloat16* Xl = g_xflo + (size_t)b * CC * HW;
    const __nv_bfloat16* Zh = g_zhi  + (size_t)b * HW * KK;
    const __nv_bfloat16* Zl = g_zlo  + (size_t)b * HW * KK;

    float acc[2][4][4];
#pragma unroll
    for (int i = 0; i < 2; i++)
#pragma unroll
        for (int j = 0; j < 4; j++)
#pragma unroll
            for (int q = 0; q < 4; q++) acc[i][j][q] = 0.f;

    const int ar0 = tid >> 2,         ac0 = (tid & 3) * 8;
    const int ar1 = (tid + 256) >> 2, ac1 = (tid & 3) * 8;
    const int br = tid >> 3, bc = (tid & 7) * 8;

    const int nbeg = s * (HW / SPLIT);
    const int NT = 16;
#define LOAD_TILE(IT, BUF) do {                                                   \
        int n0 = nbeg + (IT) * 32;                                                \
        uint32_t aH = base + oAH + (BUF) * MSTG_A, aL = base + oAL + (BUF) * MSTG_A; \
        uint32_t bH = base + oBH + (BUF) * MSTG_B, bL = base + oBL + (BUF) * MSTG_B; \
        cp_async16(aH + (ar0 * MAP + ac0) * 2, Xh + (size_t)(c0 + ar0) * HW + n0 + ac0); \
        cp_async16(aH + (ar1 * MAP + ac1) * 2, Xh + (size_t)(c0 + ar1) * HW + n0 + ac1); \
        cp_async16(aL + (ar0 * MAP + ac0) * 2, Xl + (size_t)(c0 + ar0) * HW + n0 + ac0); \
        cp_async16(aL + (ar1 * MAP + ac1) * 2, Xl + (size_t)(c0 + ar1) * HW + n0 + ac1); \
        cp_async16(bH + (br * MBP + bc) * 2,  Zh + (size_t)(n0 + br) * KK + bc);  \
        cp_async16(bL + (br * MBP + bc) * 2,  Zl + (size_t)(n0 + br) * KK + bc);  \
        asm volatile("cp.async.commit_group;");                                   \
    } while (0)

    LOAD_TILE(0, 0);
    for (int it = 0; it < NT; ++it) {
        if (it + 1 < NT) { LOAD_TILE(it + 1, (it + 1) & 1); asm volatile("cp.async.wait_group 1;"); }
        else             { asm volatile("cp.async.wait_group 0;"); }
        __syncthreads();

        const int buf = it & 1;
        const uint32_t aH = base + oAH + buf * MSTG_A, aL = base + oAL + buf * MSTG_A;
        const uint32_t bH = base + oBH + buf * MSTG_B, bL = base + oBL + buf * MSTG_B;
#pragma unroll
        for (int kk = 0; kk < 32; kk += 16) {
            uint32_t ah[2][4], al[2][4], bh[2][4], bl[2][4];
#pragma unroll
            for (int f = 0; f < 2; f++) {
                uint32_t off = (((wm + f * 16 + (lane & 15)) * MAP) + kk + ((lane >> 4) << 3)) * 2;
                ldsm_x4(ah[f][0], ah[f][1], ah[f][2], ah[f][3], aH + off);
                ldsm_x4(al[f][0], al[f][1], al[f][2], al[f][3], aL + off);
            }
#pragma unroll
            for (int jn = 0; jn < 2; jn++) {
                uint32_t off = (((kk + (lane & 7) + ((lane >> 3) & 1) * 8) * MBP)
                                + wn + jn * 16 + ((lane >> 4) << 3)) * 2;
                ldsm_x4_t(bh[jn][0], bh[jn][1], bh[jn][2], bh[jn][3], bH + off);
                ldsm_x4_t(bl[jn][0], bl[jn][1], bl[jn][2], bl[jn][3], bL + off);
            }
#pragma unroll
            for (int f = 0; f < 2; f++)
#pragma unroll
                for (int jn = 0; jn < 2; jn++) {
                    mma_bf16(acc[f][jn * 2 + 0], ah[f], bh[jn][0], bh[jn][1]);
                    mma_bf16(acc[f][jn * 2 + 1], ah[f], bh[jn][2], bh[jn][3]);
                    mma_bf16(acc[f][jn * 2 + 0], al[f], bh[jn][0], bh[jn][1]);
                    mma_bf16(acc[f][jn * 2 + 1], al[f], bh[jn][2], bh[jn][3]);
                    mma_bf16(acc[f][jn * 2 + 0], ah[f], bl[jn][0], bl[jn][1]);
                    mma_bf16(acc[f][jn * 2 + 1], ah[f], bl[jn][2], bl[jn][3]);
                }
        }
        __syncthreads();
    }
#undef LOAD_TILE

    float* outp = g_mu_part + ((size_t)b * SPLIT + s) * CC * KK;
#pragma unroll
    for (int f = 0; f < 2; f++) {
        int row = c0 + wm + f * 16 + (lane >> 2);
#pragma unroll
        for (int j8 = 0; j8 < 4; j8++) {
            int col = wn + j8 * 8 + (lane & 3) * 2;
            *reinterpret_cast<float2*>(&outp[(size_t)row * KK + col])       = {acc[f][j8][0], acc[f][j8][1]};
            *reinterpret_cast<float2*>(&outp[(size_t)(row + 8) * KK + col]) = {acc[f][j8][2], acc[f][j8][3]};
        }
    }
}

// ---------------------------------------------------------------------------
// Reduce split-K partials + l2-normalize
// ---------------------------------------------------------------------------
__global__ void reduce_l2norm_kernel(float* __restrict__ out_mu) {
    const int bk = blockIdx.x;
    const int b = bk >> 6, k = bk & 63;
    const int tid = threadIdx.x;

    float* mub = g_mu + (size_t)b * CC * KK;
    const float* part = g_mu_part + (size_t)b * SPLIT * CC * KK;

    float s2 = 0.f;
    for (int c = tid; c < CC; c += 128) {
        float v = 0.f;
#pragma unroll
        for (int s = 0; s < SPLIT; s++)
            v += part[(size_t)s * CC * KK + (size_t)c * KK + k];
        mub[(size_t)c * KK + k] = v;
        s2 += v * v;
    }
    __shared__ float red[128];
    red[tid] = s2; __syncthreads();
    for (int st = 64; st > 0; st >>= 1) {
        if (tid < st) red[tid] += red[tid + st];
        __syncthreads();
    }
    float scale = 1.f / (1e-6f + sqrtf(red[0]));
    for (int c = tid; c < CC; c += 128) {
        size_t idx = (size_t)b * CC * KK + (size_t)c * KK + k;
        float v = mub[(size_t)c * KK + k] * scale;
        __nv_bfloat16 h, l; split_val(v, h, l);
        g_muhi[idx] = h; g_mulo[idx] = l;
        if (out_mu) out_mu[idx] = v;
    }
}

// ---------------------------------------------------------------------------
// Reconstruction (mma.sync): xr = relu(mu @ z^T) -> splits  (3-stage ring)
// ---------------------------------------------------------------------------
#define RP 40
#define PIPE_WAIT_SYNC(IT, NT)                                   \
    if ((IT) + 2 < (NT)) { asm volatile("cp.async.wait_group 1;"); } \
    else                 { asm volatile("cp.async.wait_group 0;"); } \
    __syncthreads();

__global__ __launch_bounds__(256) void recon_mma_kernel() {
    const int b  = blockIdx.z;
    const int c0 = blockIdx.y * 128;
    const int n0 = blockIdx.x * 128;
    const int tid  = threadIdx.x;
    const int lane = tid & 31;
    const int wid  = tid >> 5;
    const int wm   = (wid & 1) * 64;
    const int wn   = (wid >> 1) * 32;

    __shared__ __nv_bfloat16 As[3][128 * RP];
    __shared__ __nv_bfloat16 Bs[3][128 * RP];

    const __nv_bfloat16* Mh = g_muhi + (size_t)b * CC * KK;
    const __nv_bfloat16* Ml = g_mulo + (size_t)b * CC * KK;
    const __nv_bfloat16* Zh = g_zhi  + (size_t)b * HW * KK;
    const __nv_bfloat16* Zl = g_zlo  + (size_t)b * HW * KK;

    float acc[4][4][4];
#pragma unroll
    for (int i = 0; i < 4; i++)
#pragma unroll
        for (int j = 0; j < 4; j++)
#pragma unroll
            for (int q = 0; q < 4; q++) acc[i][j][q] = 0.f;

    const uint32_t sA0 = smem_u32(As[0]);
    const uint32_t sB0 = smem_u32(Bs[0]);
    const uint32_t ssz = 128 * RP * 2;

    const int aq0 = tid, aq1 = tid + 256;
    const int ar0 = aq0 >> 2, ac0 = (aq0 & 3) * 8;
    const int ar1 = aq1 >> 2, ac1 = (aq1 & 3) * 8;

    const int NT = 6;
#define LOAD_TILE(IT, BUF) do {                                                   \
        int pass = (IT) >> 1, k0 = ((IT) & 1) * 32;                               \
        const __nv_bfloat16* Ap = (pass == 1) ? Ml : Mh;                          \
        const __nv_bfloat16* Bp = (pass == 2) ? Zl : Zh;                          \
        uint32_t sa = sA0 + (BUF) * ssz, sb = sB0 + (BUF) * ssz;                  \
        cp_async16(sa + (ar0 * RP + ac0) * 2, Ap + (size_t)(c0 + ar0) * KK + k0 + ac0); \
        cp_async16(sa + (ar1 * RP + ac1) * 2, Ap + (size_t)(c0 + ar1) * KK + k0 + ac1); \
        cp_async16(sb + (ar0 * RP + ac0) * 2, Bp + (size_t)(n0 + ar0) * KK + k0 + ac0); \
        cp_async16(sb + (ar1 * RP + ac1) * 2, Bp + (size_t)(n0 + ar1) * KK + k0 + ac1); \
        asm volatile("cp.async.commit_group;");                                   \
    } while (0)

    LOAD_TILE(0, 0);
    LOAD_TILE(1, 1);
    int buf = 0;
    for (int it = 0; it < NT; ++it) {
        PIPE_WAIT_SYNC(it, NT);
        if (it + 2 < NT) {
            int nb = buf + 2; if (nb >= 3) nb -= 3;
            LOAD_TILE(it + 2, nb);
        }
        const uint32_t sa = sA0 + buf * ssz;
        const uint32_t sb = sB0 + buf * ssz;
#pragma unroll
        for (int kk = 0; kk < 32; kk += 16) {
            uint32_t a[4][4], bfr[2][4];
#pragma unroll
            for (int im = 0; im < 4; im++) {
                uint32_t addr = sa + (((wm + im * 16 + (lane & 15)) * RP) + kk + ((lane >> 4) << 3)) * 2;
                ldsm_x4(a[im][0], a[im][1], a[im][2], a[im][3], addr);
            }
#pragma unroll
            for (int jn = 0; jn < 2; jn++) {
                uint32_t addr = sb + (((wn + jn * 16 + (lane & 7) + ((lane >> 4) << 3)) * RP)
                                      + kk + ((lane >> 3) & 1) * 8) * 2;
                ldsm_x4(bfr[jn][0], bfr[jn][1], bfr[jn][2], bfr[jn][3], addr);
            }
#pragma unroll
            for (int im = 0; im < 4; im++)
#pragma unroll
                for (int jn = 0; jn < 2; jn++) {
                    mma_bf16(acc[im][jn * 2 + 0], a[im], bfr[jn][0], bfr[jn][1]);
                    mma_bf16(acc[im][jn * 2 + 1], a[im], bfr[jn][2], bfr[jn][3]);
                }
        }
        if (++buf == 3) buf = 0;
    }
#undef LOAD_TILE

    __nv_bfloat16* Oh = g_xrhi + (size_t)b * CC * HW;
    __nv_bfloat16* Ol = g_xrlo + (size_t)b * CC * HW;
#pragma unroll
    for (int im = 0; im < 4; im++) {
        int row = c0 + wm + im * 16 + (lane >> 2);
#pragma unroll
        for (int j8 = 0; j8 < 4; j8++) {
            int col = n0 + wn + j8 * 8 + (lane & 3) * 2;
            __nv_bfloat16 h0, h1, h2, h3, l0, l1, l2, l3;
            split_val(fmaxf(acc[im][j8][0], 0.f), h0, l0);
            split_val(fmaxf(acc[im][j8][1], 0.f), h1, l1);
            split_val(fmaxf(acc[im][j8][2], 0.f), h2, l2);
            split_val(fmaxf(acc[im][j8][3], 0.f), h3, l3);
            *reinterpret_cast<__nv_bfloat162*>(&Oh[(size_t)row * HW + col]) = __nv_bfloat162{h0, h1};
            *reinterpret_cast<__nv_bfloat162*>(&Ol[(size_t)row * HW + col]) = __nv_bfloat162{l0, l1};
            *reinterpret_cast<__nv_bfloat162*>(&Oh[(size_t)(row + 8) * HW + col]) = __nv_bfloat162{h2, h3};
            *reinterpret_cast<__nv_bfloat162*>(&Ol[(size_t)(row + 8) * HW + col]) = __nv_bfloat162{l2, l3};
        }
    }
}

// ---------------------------------------------------------------------------
// BatchNorm stats / final / z-transpose
// ---------------------------------------------------------------------------
__global__ void bn_stats_kernel(const float* __restrict__ gamma,
                                const float* __restrict__ beta) {
    const int o = blockIdx.x;
    const int tid = threadIdx.x;
    float s = 0.f, s2 = 0.f;
    for (int b = 0; b < BB; b++) {
        const float* p = g_buf1 + (size_t)b * CC * HW + (size_t)o * HW;
        for (int n = tid; n < HW; n += 256) {
            float v = p[n];
            s += v; s2 = fmaf(v, v, s2);
        }
    }
    __shared__ float r1[256], r2[256];
    r1[tid] = s; r2[tid] = s2; __syncthreads();
    for (int st = 128; st > 0; st >>= 1) {
        if (tid < st) { r1[tid] += r1[tid + st]; r2[tid] += r2[tid + st]; }
        __syncthreads();
    }
    if (tid == 0) {
        const float invM = 1.f / (float)(BB * HW);
        float mean = r1[0] * invM;
        float var  = r2[0] * invM - mean * mean;
        float sc = gamma[o] * rsqrtf(var + 1e-5f);
        g_scale[o] = sc;
        g_shift[o] = beta[o] - mean * sc;
    }
}

__global__ void final_kernel(const float* __restrict__ x, float* __restrict__ out) {
    const int b = blockIdx.z, o = blockIdx.y;
    const size_t base = (size_t)b * CC * HW + (size_t)o * HW
                      + (size_t)blockIdx.x * 1024 + (size_t)threadIdx.x * 4;
    const float sc = g_scale[o], sh = g_shift[o];
    float4 v2 = *reinterpret_cast<const float4*>(&g_buf1[base]);
    float4 vx = *reinterpret_cast<const float4*>(&x[base]);
    float4 r;
    r.x = fmaxf(fmaf(v2.x, sc, sh) + vx.x, 0.f);
    r.y = fmaxf(fmaf(v2.y, sc, sh) + vx.y, 0.f);
    r.z = fmaxf(fmaf(v2.z, sc, sh) + vx.z, 0.f);
    r.w = fmaxf(fmaf(v2.w, sc, sh) + vx.w, 0.f);
    *reinterpret_cast<float4*>(&out[base]) = r;
}

__global__ void zt_kernel(float* __restrict__ zt) {
    const int b  = blockIdx.z;
    const int n0 = blockIdx.x * 32;
    const int k0 = blockIdx.y * 32;
    __shared__ float t[32][33];
    const int tx = threadIdx.x, ty = threadIdx.y;
    const float* zb = g_z + (size_t)b * HW * KK;
#pragma unroll
    for (int c = 0; c < 32; c += 8)
        t[ty + c][tx] = zb[(size_t)(n0 + ty + c) * KK + k0 + tx];
    __syncthreads();
    float* ztb = zt + (size_t)b * KK * HW;
#pragma unroll
    for (int c = 0; c < 32; c += 8)
        ztb[(size_t)(k0 + ty + c) * HW + n0 + tx] = t[tx][ty + c];
}

// ---------------------------------------------------------------------------
// Launch
// ---------------------------------------------------------------------------
extern "C" void kernel_launch(void* const* d_in, const int* in_sizes, int n_in,
                              void* d_out, int out_size) {
    const float* x     = (const float*)d_in[0];
    const float* w1    = (const float*)d_in[1];
    const float* b1    = (const float*)d_in[2];
    const float* w2    = (const float*)d_in[3];
    const float* gamma = (const float*)d_in[4];
    const float* beta  = (const float*)d_in[5];
    const float* mu_in = (const float*)d_in[6];

    float* out    = (float*)d_out;
    float* out_mu = out + (size_t)BB * CC * HW;
    float* out_zt = out_mu + (size_t)BB * CC * KK;

    static int smem_set = 0;
    if (!smem_set) {
        cudaFuncSetAttribute(conv_mma_kernel, cudaFuncAttributeMaxDynamicSharedMemorySize, CONV_SMEM);
        smem_set = 1;
    }

    split_w_kernel<<<CC * CC / 256, 256>>>(w1, w2);
    split_x_kernel<<<(BB * CC * HW) / (256 * 4), 256>>>(x);
    copymu_kernel<<<dim3(CC * KK / 256, BB), 256>>>(mu_in);

    // conv1 -> xf splits
    conv_mma_kernel<<<dim3(HW / 128, CC / 128, BB), 256, CONV_SMEM>>>(b1, 0);

    for (int s = 0; s < 3; s++) {
        estep_mma_kernel<<<dim3(HW / 128, BB), 256>>>(s == 2 ? 1 : 0);
        mstep_mma_kernel<<<dim3(CC / 128, SPLIT, BB), 256>>>();
        reduce_l2norm_kernel<<<BB * KK, 128>>>(s == 2 ? out_mu : nullptr);
    }

    recon_mma_kernel<<<dim3(HW / 128, CC / 128, BB), 256>>>();

    // conv2 -> g_buf1 fp32
    conv_mma_kernel<<<dim3(HW / 128, CC / 128, BB), 256, CONV_SMEM>>>(nullptr, 1);

    bn_stats_kernel<<<CC, 256>>>(gamma, beta);
    final_kernel<<<dim3(HW / 1024, CC, BB), 256>>>(x, out);
    zt_kernel<<<dim3(HW / 32, KK / 32, BB), dim3(32, 8)>>>(out_zt);
}

// round 8
// speedup vs baseline: 2.2958x; 1.0060x over previous
#include <cuda_runtime.h>
#include <cuda_bf16.h>
#include <cstdint>
#include <math.h>

#define BB 16
#define CC 512
#define HW 4096
#define KK 64
#define SPLIT 8

// ---------------------------------------------------------------------------
// Scratch
// ---------------------------------------------------------------------------
__device__ float g_buf1[BB * CC * HW];            // x2 (conv2 out) fp32
__device__ float g_z[BB * HW * KK];               // z fp32 (last stage only)
__device__ float g_mu[BB * CC * KK];
__device__ float g_mu_part[BB * SPLIT * CC * KK];
__device__ float g_scale[CC];
__device__ float g_shift[CC];

__device__ __nv_bfloat16 g_w1hi[CC * CC], g_w1lo[CC * CC];
__device__ __nv_bfloat16 g_w2hi[CC * CC], g_w2lo[CC * CC];
__device__ __nv_bfloat16 g_xhi[BB * CC * HW],  g_xlo[BB * CC * HW];
__device__ __nv_bfloat16 g_xfhi[BB * CC * HW], g_xflo[BB * CC * HW];
__device__ __nv_bfloat16 g_xrhi[BB * CC * HW], g_xrlo[BB * CC * HW];
__device__ __nv_bfloat16 g_zhi[BB * HW * KK],  g_zlo[BB * HW * KK];
__device__ __nv_bfloat16 g_muhi[BB * CC * KK], g_mulo[BB * CC * KK];

// ---------------------------------------------------------------------------
// PTX helpers
// ---------------------------------------------------------------------------
__device__ __forceinline__ uint32_t smem_u32(const void* p) {
    return (uint32_t)__cvta_generic_to_shared(p);
}
__device__ __forceinline__ void cp_async16(uint32_t saddr, const void* gaddr) {
    asm volatile("cp.async.cg.shared.global [%0], [%1], 16;" :: "r"(saddr), "l"(gaddr));
}
__device__ __forceinline__ void ldsm_x4(uint32_t& r0, uint32_t& r1, uint32_t& r2, uint32_t& r3, uint32_t a) {
    asm volatile("ldmatrix.sync.aligned.m8n8.x4.shared.b16 {%0,%1,%2,%3}, [%4];"
                 : "=r"(r0), "=r"(r1), "=r"(r2), "=r"(r3) : "r"(a));
}
__device__ __forceinline__ void ldsm_x4_t(uint32_t& r0, uint32_t& r1, uint32_t& r2, uint32_t& r3, uint32_t a) {
    asm volatile("ldmatrix.sync.aligned.m8n8.x4.trans.shared.b16 {%0,%1,%2,%3}, [%4];"
                 : "=r"(r0), "=r"(r1), "=r"(r2), "=r"(r3) : "r"(a));
}
__device__ __forceinline__ void mma_bf16(float* c, const uint32_t* a, uint32_t b0, uint32_t b1) {
    asm volatile("mma.sync.aligned.m16n8k16.row.col.f32.bf16.bf16.f32 "
                 "{%0,%1,%2,%3}, {%4,%5,%6,%7}, {%8,%9}, {%0,%1,%2,%3};"
                 : "+f"(c[0]), "+f"(c[1]), "+f"(c[2]), "+f"(c[3])
                 : "r"(a[0]), "r"(a[1]), "r"(a[2]), "r"(a[3]), "r"(b0), "r"(b1));
}
__device__ __forceinline__ void split_val(float v, __nv_bfloat16& h, __nv_bfloat16& l) {
    h = __float2bfloat16(v);
    l = __float2bfloat16(v - __bfloat162float(h));
}

// ---------------------------------------------------------------------------
// Conversions
// ---------------------------------------------------------------------------
__global__ void split_w_kernel(const float* __restrict__ w1, const float* __restrict__ w2) {
    int i = blockIdx.x * 256 + threadIdx.x;
    split_val(w1[i], g_w1hi[i], g_w1lo[i]);
    split_val(w2[i], g_w2hi[i], g_w2lo[i]);
}
__global__ void split_x_kernel(const float* __restrict__ x) {
    size_t i = ((size_t)blockIdx.x * 256 + threadIdx.x) * 4;
    float4 v = *reinterpret_cast<const float4*>(&x[i]);
    __nv_bfloat16 h0, h1, h2, h3, l0, l1, l2, l3;
    split_val(v.x, h0, l0); split_val(v.y, h1, l1);
    split_val(v.z, h2, l2); split_val(v.w, h3, l3);
    *reinterpret_cast<__nv_bfloat162*>(&g_xhi[i])     = __nv_bfloat162{h0, h1};
    *reinterpret_cast<__nv_bfloat162*>(&g_xhi[i + 2]) = __nv_bfloat162{h2, h3};
    *reinterpret_cast<__nv_bfloat162*>(&g_xlo[i])     = __nv_bfloat162{l0, l1};
    *reinterpret_cast<__nv_bfloat162*>(&g_xlo[i + 2]) = __nv_bfloat162{l2, l3};
}
__global__ void copymu_kernel(const float* __restrict__ mu_in) {
    int b = blockIdx.y;
    int i = blockIdx.x * 256 + threadIdx.x;
    __nv_bfloat16 h, l; split_val(mu_in[i], h, l);
    size_t idx = (size_t)b * CC * KK + i;
    g_muhi[idx] = h; g_mulo[idx] = l;
}

// ---------------------------------------------------------------------------
// conv GEMM, FUSED split-bf16, TERM-OUTERMOST MMA order (breaks acc RAW chains)
// Block 128x128, BK=32, 8 warps (2 x M, 4 x N), warp tile 64x32.
// ---------------------------------------------------------------------------
#define APITCH 40
#define BPITCH 136
#define CSTG_A (128 * APITCH * 2)
#define CSTG_B (32 * BPITCH * 2)
#define CONV_SMEM (4 * CSTG_A + 4 * CSTG_B)   // 75776 B

__global__ __launch_bounds__(256) void conv_mma_kernel(const float* __restrict__ bias, int sel) {
    extern __shared__ __align__(16) char csm[];
    const int b  = blockIdx.z;
    const int m0 = blockIdx.y * 128;
    const int n0 = blockIdx.x * 128;
    const int tid  = threadIdx.x;
    const int lane = tid & 31;
    const int wid  = tid >> 5;
    const int wm   = (wid & 1) * 64;
    const int wn   = (wid >> 1) * 32;

    const uint32_t base = smem_u32(csm);
    const uint32_t oAH = 0, oAL = 2 * CSTG_A;
    const uint32_t oBH = 4 * CSTG_A, oBL = 4 * CSTG_A + 2 * CSTG_B;

    const __nv_bfloat16* Whi = sel ? g_w2hi : g_w1hi;
    const __nv_bfloat16* Wlo = sel ? g_w2lo : g_w1lo;
    const __nv_bfloat16* Xhi = (sel ? g_xrhi : g_xhi) + (size_t)b * CC * HW;
    const __nv_bfloat16* Xlo = (sel ? g_xrlo : g_xlo) + (size_t)b * CC * HW;

    float acc[4][4][4];
#pragma unroll
    for (int i = 0; i < 4; i++)
#pragma unroll
        for (int j = 0; j < 4; j++)
#pragma unroll
            for (int q = 0; q < 4; q++) acc[i][j][q] = 0.f;

    const int ar0 = tid >> 2,          ac0 = (tid & 3) * 8;
    const int ar1 = (tid + 256) >> 2,  ac1 = (tid & 3) * 8;
    const int br0 = tid >> 4,          bc0 = (tid & 15) * 8;
    const int br1 = (tid + 256) >> 4,  bc1 = (tid & 15) * 8;

    const int NT = 16;

#define LOAD_TILE(IT, BUF) do {                                                   \
        int k0 = (IT) * 32;                                                       \
        uint32_t aH = base + oAH + (BUF) * CSTG_A, aL = base + oAL + (BUF) * CSTG_A; \
        uint32_t bH = base + oBH + (BUF) * CSTG_B, bL = base + oBL + (BUF) * CSTG_B; \
        cp_async16(aH + (ar0 * APITCH + ac0) * 2, Whi + (size_t)(m0 + ar0) * CC + k0 + ac0); \
        cp_async16(aH + (ar1 * APITCH + ac1) * 2, Whi + (size_t)(m0 + ar1) * CC + k0 + ac1); \
        cp_async16(aL + (ar0 * APITCH + ac0) * 2, Wlo + (size_t)(m0 + ar0) * CC + k0 + ac0); \
        cp_async16(aL + (ar1 * APITCH + ac1) * 2, Wlo + (size_t)(m0 + ar1) * CC + k0 + ac1); \
        cp_async16(bH + (br0 * BPITCH + bc0) * 2, Xhi + (size_t)(k0 + br0) * HW + n0 + bc0); \
        cp_async16(bH + (br1 * BPITCH + bc1) * 2, Xhi + (size_t)(k0 + br1) * HW + n0 + bc1); \
        cp_async16(bL + (br0 * BPITCH + bc0) * 2, Xlo + (size_t)(k0 + br0) * HW + n0 + bc0); \
        cp_async16(bL + (br1 * BPITCH + bc1) * 2, Xlo + (size_t)(k0 + br1) * HW + n0 + bc1); \
        asm volatile("cp.async.commit_group;");                                   \
    } while (0)

    LOAD_TILE(0, 0);
    for (int it = 0; it < NT; ++it) {
        if (it + 1 < NT) { LOAD_TILE(it + 1, (it + 1) & 1); asm volatile("cp.async.wait_group 1;"); }
        else             { asm volatile("cp.async.wait_group 0;"); }
        __syncthreads();

        const int buf = it & 1;
        const uint32_t aH = base + oAH + buf * CSTG_A, aL = base + oAL + buf * CSTG_A;
        const uint32_t bH = base + oBH + buf * CSTG_B, bL = base + oBL + buf * CSTG_B;
#pragma unroll
        for (int kk = 0; kk < 32; kk += 16) {
            uint32_t ah[4][4], al[4][4], bh[2][4], bl[2][4];
#pragma unroll
            for (int im = 0; im < 4; im++) {
                uint32_t off = (((wm + im * 16 + (lane & 15)) * APITCH) + kk + ((lane >> 4) << 3)) * 2;
                ldsm_x4(ah[im][0], ah[im][1], ah[im][2], ah[im][3], aH + off);
                ldsm_x4(al[im][0], al[im][1], al[im][2], al[im][3], aL + off);
            }
#pragma unroll
            for (int jn = 0; jn < 2; jn++) {
                uint32_t off = (((kk + (lane & 7) + ((lane >> 3) & 1) * 8) * BPITCH)
                                + wn + jn * 16 + ((lane >> 4) << 3)) * 2;
                ldsm_x4_t(bh[jn][0], bh[jn][1], bh[jn][2], bh[jn][3], bH + off);
                ldsm_x4_t(bl[jn][0], bl[jn][1], bl[jn][2], bl[jn][3], bL + off);
            }
            // term hh: 16 MMAs
#pragma unroll
            for (int im = 0; im < 4; im++)
#pragma unroll
                for (int jn = 0; jn < 2; jn++) {
                    mma_bf16(acc[im][jn * 2 + 0], ah[im], bh[jn][0], bh[jn][1]);
                    mma_bf16(acc[im][jn * 2 + 1], ah[im], bh[jn][2], bh[jn][3]);
                }
            // term lh
#pragma unroll
            for (int im = 0; im < 4; im++)
#pragma unroll
                for (int jn = 0; jn < 2; jn++) {
                    mma_bf16(acc[im][jn * 2 + 0], al[im], bh[jn][0], bh[jn][1]);
                    mma_bf16(acc[im][jn * 2 + 1], al[im], bh[jn][2], bh[jn][3]);
                }
            // term hl
#pragma unroll
            for (int im = 0; im < 4; im++)
#pragma unroll
                for (int jn = 0; jn < 2; jn++) {
                    mma_bf16(acc[im][jn * 2 + 0], ah[im], bl[jn][0], bl[jn][1]);
                    mma_bf16(acc[im][jn * 2 + 1], ah[im], bl[jn][2], bl[jn][3]);
                }
        }
        __syncthreads();
    }
#undef LOAD_TILE

    if (sel == 0) {
        __nv_bfloat16* Oh = g_xfhi + (size_t)b * CC * HW;
        __nv_bfloat16* Ol = g_xflo + (size_t)b * CC * HW;
#pragma unroll
        for (int im = 0; im < 4; im++) {
            int row = m0 + wm + im * 16 + (lane >> 2);
            float bv0 = bias[row], bv1 = bias[row + 8];
#pragma unroll
            for (int j8 = 0; j8 < 4; j8++) {
                int col = n0 + wn + j8 * 8 + (lane & 3) * 2;
                __nv_bfloat16 h0, h1, h2, h3, l0, l1, l2, l3;
                split_val(acc[im][j8][0] + bv0, h0, l0);
                split_val(acc[im][j8][1] + bv0, h1, l1);
                split_val(acc[im][j8][2] + bv1, h2, l2);
                split_val(acc[im][j8][3] + bv1, h3, l3);
                *reinterpret_cast<__nv_bfloat162*>(&Oh[(size_t)row * HW + col]) = __nv_bfloat162{h0, h1};
                *reinterpret_cast<__nv_bfloat162*>(&Ol[(size_t)row * HW + col]) = __nv_bfloat162{l0, l1};
                *reinterpret_cast<__nv_bfloat162*>(&Oh[(size_t)(row + 8) * HW + col]) = __nv_bfloat162{h2, h3};
                *reinterpret_cast<__nv_bfloat162*>(&Ol[(size_t)(row + 8) * HW + col]) = __nv_bfloat162{l2, l3};
            }
        }
    } else {
        float* Yb = g_buf1 + (size_t)b * CC * HW;
#pragma unroll
        for (int im = 0; im < 4; im++) {
            int row = m0 + wm + im * 16 + (lane >> 2);
#pragma unroll
            for (int j8 = 0; j8 < 4; j8++) {
                int col = n0 + wn + j8 * 8 + (lane & 3) * 2;
                float2 v0 = {acc[im][j8][0], acc[im][j8][1]};
                float2 v1 = {acc[im][j8][2], acc[im][j8][3]};
                *reinterpret_cast<float2*>(&Yb[(size_t)row * HW + col]) = v0;
                *reinterpret_cast<float2*>(&Yb[(size_t)(row + 8) * HW + col]) = v1;
            }
        }
    }
}

// ---------------------------------------------------------------------------
// E-step FUSED, term-outermost: logits -> softmax -> z splits (+ fp32 z)
// ---------------------------------------------------------------------------
#define EAP 136
#define EBP 72
#define ESTG_A (32 * EAP * 2)
#define ESTG_B (32 * EBP * 2)
__global__ __launch_bounds__(256) void estep_mma_kernel(int write_z) {
    const int b  = blockIdx.y;
    const int n0 = blockIdx.x * 128;
    const int tid  = threadIdx.x;
    const int lane = tid & 31;
    const int wid  = tid >> 5;
    const int wm   = (wid & 3) * 32;
    const int wn   = (wid >> 2) * 32;

    __shared__ __align__(16) char sm[2 * (2 * ESTG_A + 2 * ESTG_B)];
    const uint32_t base = smem_u32(sm);
    const uint32_t oAH = 0, oAL = 2 * ESTG_A;
    const uint32_t oBH = 4 * ESTG_A, oBL = 4 * ESTG_A + 2 * ESTG_B;
    float* L = (float*)sm;

    const __nv_bfloat16* Xh = g_xfhi + (size_t)b * CC * HW;
    const __nv_bfloat16* Xl = g_xflo + (size_t)b * CC * HW;
    const __nv_bfloat16* Mh = g_muhi + (size_t)b * CC * KK;
    const __nv_bfloat16* Ml = g_mulo + (size_t)b * CC * KK;

    float acc[2][4][4];
#pragma unroll
    for (int i = 0; i < 2; i++)
#pragma unroll
        for (int j = 0; j < 4; j++)
#pragma unroll
            for (int q = 0; q < 4; q++) acc[i][j][q] = 0.f;

    const int ar0 = tid >> 4,         ac0 = (tid & 15) * 8;
    const int ar1 = (tid + 256) >> 4, ac1 = (tid & 15) * 8;
    const int br = tid >> 3, bc = (tid & 7) * 8;

    const int NT = 16;
#define LOAD_TILE(IT, BUF) do {                                                   \
        int k0 = (IT) * 32;                                                       \
        uint32_t aH = base + oAH + (BUF) * ESTG_A, aL = base + oAL + (BUF) * ESTG_A; \
        uint32_t bH = base + oBH + (BUF) * ESTG_B, bL = base + oBL + (BUF) * ESTG_B; \
        cp_async16(aH + (ar0 * EAP + ac0) * 2, Xh + (size_t)(k0 + ar0) * HW + n0 + ac0); \
        cp_async16(aH + (ar1 * EAP + ac1) * 2, Xh + (size_t)(k0 + ar1) * HW + n0 + ac1); \
        cp_async16(aL + (ar0 * EAP + ac0) * 2, Xl + (size_t)(k0 + ar0) * HW + n0 + ac0); \
        cp_async16(aL + (ar1 * EAP + ac1) * 2, Xl + (size_t)(k0 + ar1) * HW + n0 + ac1); \
        cp_async16(bH + (br * EBP + bc) * 2,  Mh + (size_t)(k0 + br) * KK + bc);  \
        cp_async16(bL + (br * EBP + bc) * 2,  Ml + (size_t)(k0 + br) * KK + bc);  \
        asm volatile("cp.async.commit_group;");                                   \
    } while (0)

    LOAD_TILE(0, 0);
    for (int it = 0; it < NT; ++it) {
        if (it + 1 < NT) { LOAD_TILE(it + 1, (it + 1) & 1); asm volatile("cp.async.wait_group 1;"); }
        else             { asm volatile("cp.async.wait_group 0;"); }
        __syncthreads();

        const int buf = it & 1;
        const uint32_t aH = base + oAH + buf * ESTG_A, aL = base + oAL + buf * ESTG_A;
        const uint32_t bH = base + oBH + buf * ESTG_B, bL = base + oBL + buf * ESTG_B;
#pragma unroll
        for (int kk = 0; kk < 32; kk += 16) {
            uint32_t ah[2][4], al[2][4], bh[2][4], bl[2][4];
#pragma unroll
            for (int f = 0; f < 2; f++) {
                uint32_t off = (((kk + (lane & 7) + ((lane >> 4) << 3)) * EAP)
                                + wm + f * 16 + ((lane >> 3) & 1) * 8) * 2;
                ldsm_x4_t(ah[f][0], ah[f][1], ah[f][2], ah[f][3], aH + off);
                ldsm_x4_t(al[f][0], al[f][1], al[f][2], al[f][3], aL + off);
            }
#pragma unroll
            for (int jn = 0; jn < 2; jn++) {
                uint32_t off = (((kk + (lane & 7) + ((lane >> 3) & 1) * 8) * EBP)
                                + wn + jn * 16 + ((lane >> 4) << 3)) * 2;
                ldsm_x4_t(bh[jn][0], bh[jn][1], bh[jn][2], bh[jn][3], bH + off);
                ldsm_x4_t(bl[jn][0], bl[jn][1], bl[jn][2], bl[jn][3], bL + off);
            }
#pragma unroll
            for (int f = 0; f < 2; f++)
#pragma unroll
                for (int jn = 0; jn < 2; jn++) {
                    mma_bf16(acc[f][jn * 2 + 0], ah[f], bh[jn][0], bh[jn][1]);
                    mma_bf16(acc[f][jn * 2 + 1], ah[f], bh[jn][2], bh[jn][3]);
                }
#pragma unroll
            for (int f = 0; f < 2; f++)
#pragma unroll
                for (int jn = 0; jn < 2; jn++) {
                    mma_bf16(acc[f][jn * 2 + 0], al[f], bh[jn][0], bh[jn][1]);
                    mma_bf16(acc[f][jn * 2 + 1], al[f], bh[jn][2], bh[jn][3]);
                }
#pragma unroll
            for (int f = 0; f < 2; f++)
#pragma unroll
                for (int jn = 0; jn < 2; jn++) {
                    mma_bf16(acc[f][jn * 2 + 0], ah[f], bl[jn][0], bl[jn][1]);
                    mma_bf16(acc[f][jn * 2 + 1], ah[f], bl[jn][2], bl[jn][3]);
                }
        }
        __syncthreads();
    }
#undef LOAD_TILE

#pragma unroll
    for (int f = 0; f < 2; f++) {
        int row = wm + f * 16 + (lane >> 2);
#pragma unroll
        for (int j8 = 0; j8 < 4; j8++) {
            int col = wn + j8 * 8 + (lane & 3) * 2;
            *reinterpret_cast<float2*>(&L[row * 68 + col])       = {acc[f][j8][0], acc[f][j8][1]};
            *reinterpret_cast<float2*>(&L[(row + 8) * 68 + col]) = {acc[f][j8][2], acc[f][j8][3]};
        }
    }
    __syncthreads();

    for (int i = 0; i < 16; i++) {
        int r = wid * 16 + i;
        float v0 = L[r * 68 + lane], v1 = L[r * 68 + lane + 32];
        float m = fmaxf(v0, v1);
#pragma unroll
        for (int off = 16; off > 0; off >>= 1)
            m = fmaxf(m, __shfl_xor_sync(0xffffffffu, m, off));
        float e0 = expf(v0 - m), e1 = expf(v1 - m);
        float s = e0 + e1;
#pragma unroll
        for (int off = 16; off > 0; off >>= 1)
            s += __shfl_xor_sync(0xffffffffu, s, off);
        float inv = 1.f / s;
        float z0 = e0 * inv, z1 = e1 * inv;
        size_t zbase = (size_t)b * HW * KK + (size_t)(n0 + r) * KK;
        if (write_z) {
            g_z[zbase + lane]      = z0;
            g_z[zbase + lane + 32] = z1;
        }
        __nv_bfloat16 h, l;
        split_val(z0, h, l); g_zhi[zbase + lane] = h;      g_zlo[zbase + lane] = l;
        split_val(z1, h, l); g_zhi[zbase + lane + 32] = h; g_zlo[zbase + lane + 32] = l;
    }
}

// ---------------------------------------------------------------------------
// M-step FUSED, term-outermost (split-K over n)
// ---------------------------------------------------------------------------
#define MAP 40
#define MBP 72
#define MSTG_A (128 * MAP * 2)
#define MSTG_B (32 * MBP * 2)
__global__ __launch_bounds__(256) void mstep_mma_kernel() {
    const int b  = blockIdx.z;
    const int s  = blockIdx.y;
    const int c0 = blockIdx.x * 128;
    const int tid  = threadIdx.x;
    const int lane = tid & 31;
    const int wid  = tid >> 5;
    const int wm   = (wid & 3) * 32;
    const int wn   = (wid >> 2) * 32;

    __shared__ __align__(16) char sm[2 * (2 * MSTG_A + 2 * MSTG_B)];
    const uint32_t base = smem_u32(sm);
    const uint32_t oAH = 0, oAL = 2 * MSTG_A;
    const uint32_t oBH = 4 * MSTG_A, oBL = 4 * MSTG_A + 2 * MSTG_B;

    const __nv_bfloat16* Xh = g_xfhi + (size_t)b * CC * HW;
    const __nv_bfloat16* Xl = g_xflo + (size_t)b * CC * HW;
    const __nv_bfloat16* Zh = g_zhi  + (size_t)b * HW * KK;
    const __nv_bfloat16* Zl = g_zlo  + (size_t)b * HW * KK;

    float acc[2][4][4];
#pragma unroll
    for (int i = 0; i < 2; i++)
#pragma unroll
        for (int j = 0; j < 4; j++)
#pragma unroll
            for (int q = 0; q < 4; q++) acc[i][j][q] = 0.f;

    const int ar0 = tid >> 2,         ac0 = (tid & 3) * 8;
    const int ar1 = (tid + 256) >> 2, ac1 = (tid & 3) * 8;
    const int br = tid >> 3, bc = (tid & 7) * 8;

    const int nbeg = s * (HW / SPLIT);
    const int NT = 16;
#define LOAD_TILE(IT, BUF) do {                                                   \
        int n0 = nbeg + (IT) * 32;                                                \
        uint32_t aH = base + oAH + (BUF) * MSTG_A, aL = base + oAL + (BUF) * MSTG_A; \
        uint32_t bH = base + oBH + (BUF) * MSTG_B, bL = base + oBL + (BUF) * MSTG_B; \
        cp_async16(aH + (ar0 * MAP + ac0) * 2, Xh + (size_t)(c0 + ar0) * HW + n0 + ac0); \
        cp_async16(aH + (ar1 * MAP + ac1) * 2, Xh + (size_t)(c0 + ar1) * HW + n0 + ac1); \
        cp_async16(aL + (ar0 * MAP + ac0) * 2, Xl + (size_t)(c0 + ar0) * HW + n0 + ac0); \
        cp_async16(aL + (ar1 * MAP + ac1) * 2, Xl + (size_t)(c0 + ar1) * HW + n0 + ac1); \
        cp_async16(bH + (br * MBP + bc) * 2,  Zh + (size_t)(n0 + br) * KK + bc);  \
        cp_async16(bL + (br * MBP + bc) * 2,  Zl + (size_t)(n0 + br) * KK + bc);  \
        asm volatile("cp.async.commit_group;");                                   \
    } while (0)

    LOAD_TILE(0, 0);
    for (int it = 0; it < NT; ++it) {
        if (it + 1 < NT) { LOAD_TILE(it + 1, (it + 1) & 1); asm volatile("cp.async.wait_group 1;"); }
        else             { asm volatile("cp.async.wait_group 0;"); }
        __syncthreads();

        const int buf = it & 1;
        const uint32_t aH = base + oAH + buf * MSTG_A, aL = base + oAL + buf * MSTG_A;
        const uint32_t bH = base + oBH + buf * MSTG_B, bL = base + oBL + buf * MSTG_B;
#pragma unroll
        for (int kk = 0; kk < 32; kk += 16) {
            uint32_t ah[2][4], al[2][4], bh[2][4], bl[2][4];
#pragma unroll
            for (int f = 0; f < 2; f++) {
                uint32_t off = (((wm + f * 16 + (lane & 15)) * MAP) + kk + ((lane >> 4) << 3)) * 2;
                ldsm_x4(ah[f][0], ah[f][1], ah[f][2], ah[f][3], aH + off);
                ldsm_x4(al[f][0], al[f][1], al[f][2], al[f][3], aL + off);
            }
#pragma unroll
            for (int jn = 0; jn < 2; jn++) {
                uint32_t off = (((kk + (lane & 7) + ((lane >> 3) & 1) * 8) * MBP)
                                + wn + jn * 16 + ((lane >> 4) << 3)) * 2;
                ldsm_x4_t(bh[jn][0], bh[jn][1], bh[jn][2], bh[jn][3], bH + off);
                ldsm_x4_t(bl[jn][0], bl[jn][1], bl[jn][2], bl[jn][3], bL + off);
            }
#pragma unroll
            for (int f = 0; f < 2; f++)
#pragma unroll
                for (int jn = 0; jn < 2; jn++) {
                    mma_bf16(acc[f][jn * 2 + 0], ah[f], bh[jn][0], bh[jn][1]);
                    mma_bf16(acc[f][jn * 2 + 1], ah[f], bh[jn][2], bh[jn][3]);
                }
#pragma unroll
            for (int f = 0; f < 2; f++)
#pragma unroll
                for (int jn = 0; jn < 2; jn++) {
                    mma_bf16(acc[f][jn * 2 + 0], al[f], bh[jn][0], bh[jn][1]);
                    mma_bf16(acc[f][jn * 2 + 1], al[f], bh[jn][2], bh[jn][3]);
                }
#pragma unroll
            for (int f = 0; f < 2; f++)
#pragma unroll
                for (int jn = 0; jn < 2; jn++) {
                    mma_bf16(acc[f][jn * 2 + 0], ah[f], bl[jn][0], bl[jn][1]);
                    mma_bf16(acc[f][jn * 2 + 1], ah[f], bl[jn][2], bl[jn][3]);
                }
        }
        __syncthreads();
    }
#undef LOAD_TILE

    float* outp = g_mu_part + ((size_t)b * SPLIT + s) * CC * KK;
#pragma unroll
    for (int f = 0; f < 2; f++) {
        int row = c0 + wm + f * 16 + (lane >> 2);
#pragma unroll
        for (int j8 = 0; j8 < 4; j8++) {
            int col = wn + j8 * 8 + (lane & 3) * 2;
            *reinterpret_cast<float2*>(&outp[(size_t)row * KK + col])       = {acc[f][j8][0], acc[f][j8][1]};
            *reinterpret_cast<float2*>(&outp[(size_t)(row + 8) * KK + col]) = {acc[f][j8][2], acc[f][j8][3]};
        }
    }
}

// ---------------------------------------------------------------------------
// Reduce split-K partials + l2-normalize
// ---------------------------------------------------------------------------
__global__ void reduce_l2norm_kernel(float* __restrict__ out_mu) {
    const int bk = blockIdx.x;
    const int b = bk >> 6, k = bk & 63;
    const int tid = threadIdx.x;

    float* mub = g_mu + (size_t)b * CC * KK;
    const float* part = g_mu_part + (size_t)b * SPLIT * CC * KK;

    float s2 = 0.f;
    for (int c = tid; c < CC; c += 128) {
        float v = 0.f;
#pragma unroll
        for (int s = 0; s < SPLIT; s++)
            v += part[(size_t)s * CC * KK + (size_t)c * KK + k];
        mub[(size_t)c * KK + k] = v;
        s2 += v * v;
    }
    __shared__ float red[128];
    red[tid] = s2; __syncthreads();
    for (int st = 64; st > 0; st >>= 1) {
        if (tid < st) red[tid] += red[tid + st];
        __syncthreads();
    }
    float scale = 1.f / (1e-6f + sqrtf(red[0]));
    for (int c = tid; c < CC; c += 128) {
        size_t idx = (size_t)b * CC * KK + (size_t)c * KK + k;
        float v = mub[(size_t)c * KK + k] * scale;
        __nv_bfloat16 h, l; split_val(v, h, l);
        g_muhi[idx] = h; g_mulo[idx] = l;
        if (out_mu) out_mu[idx] = v;
    }
}

// ---------------------------------------------------------------------------
// Reconstruction (mma.sync): xr = relu(mu @ z^T) -> splits  (3-stage ring)
// ---------------------------------------------------------------------------
#define RP 40
#define PIPE_WAIT_SYNC(IT, NT)                                   \
    if ((IT) + 2 < (NT)) { asm volatile("cp.async.wait_group 1;"); } \
    else                 { asm volatile("cp.async.wait_group 0;"); } \
    __syncthreads();

__global__ __launch_bounds__(256) void recon_mma_kernel() {
    const int b  = blockIdx.z;
    const int c0 = blockIdx.y * 128;
    const int n0 = blockIdx.x * 128;
    const int tid  = threadIdx.x;
    const int lane = tid & 31;
    const int wid  = tid >> 5;
    const int wm   = (wid & 1) * 64;
    const int wn   = (wid >> 1) * 32;

    __shared__ __nv_bfloat16 As[3][128 * RP];
    __shared__ __nv_bfloat16 Bs[3][128 * RP];

    const __nv_bfloat16* Mh = g_muhi + (size_t)b * CC * KK;
    const __nv_bfloat16* Ml = g_mulo + (size_t)b * CC * KK;
    const __nv_bfloat16* Zh = g_zhi  + (size_t)b * HW * KK;
    const __nv_bfloat16* Zl = g_zlo  + (size_t)b * HW * KK;

    float acc[4][4][4];
#pragma unroll
    for (int i = 0; i < 4; i++)
#pragma unroll
        for (int j = 0; j < 4; j++)
#pragma unroll
            for (int q = 0; q < 4; q++) acc[i][j][q] = 0.f;

    const uint32_t sA0 = smem_u32(As[0]);
    const uint32_t sB0 = smem_u32(Bs[0]);
    const uint32_t ssz = 128 * RP * 2;

    const int aq0 = tid, aq1 = tid + 256;
    const int ar0 = aq0 >> 2, ac0 = (aq0 & 3) * 8;
    const int ar1 = aq1 >> 2, ac1 = (aq1 & 3) * 8;

    const int NT = 6;
#define LOAD_TILE(IT, BUF) do {                                                   \
        int pass = (IT) >> 1, k0 = ((IT) & 1) * 32;                               \
        const __nv_bfloat16* Ap = (pass == 1) ? Ml : Mh;                          \
        const __nv_bfloat16* Bp = (pass == 2) ? Zl : Zh;                          \
        uint32_t sa = sA0 + (BUF) * ssz, sb = sB0 + (BUF) * ssz;                  \
        cp_async16(sa + (ar0 * RP + ac0) * 2, Ap + (size_t)(c0 + ar0) * KK + k0 + ac0); \
        cp_async16(sa + (ar1 * RP + ac1) * 2, Ap + (size_t)(c0 + ar1) * KK + k0 + ac1); \
        cp_async16(sb + (ar0 * RP + ac0) * 2, Bp + (size_t)(n0 + ar0) * KK + k0 + ac0); \
        cp_async16(sb + (ar1 * RP + ac1) * 2, Bp + (size_t)(n0 + ar1) * KK + k0 + ac1); \
        asm volatile("cp.async.commit_group;");                                   \
    } while (0)

    LOAD_TILE(0, 0);
    LOAD_TILE(1, 1);
    int buf = 0;
    for (int it = 0; it < NT; ++it) {
        PIPE_WAIT_SYNC(it, NT);
        if (it + 2 < NT) {
            int nb = buf + 2; if (nb >= 3) nb -= 3;
            LOAD_TILE(it + 2, nb);
        }
        const uint32_t sa = sA0 + buf * ssz;
        const uint32_t sb = sB0 + buf * ssz;
#pragma unroll
        for (int kk = 0; kk < 32; kk += 16) {
            uint32_t a[4][4], bfr[2][4];
#pragma unroll
            for (int im = 0; im < 4; im++) {
                uint32_t addr = sa + (((wm + im * 16 + (lane & 15)) * RP) + kk + ((lane >> 4) << 3)) * 2;
                ldsm_x4(a[im][0], a[im][1], a[im][2], a[im][3], addr);
            }
#pragma unroll
            for (int jn = 0; jn < 2; jn++) {
                uint32_t addr = sb + (((wn + jn * 16 + (lane & 7) + ((lane >> 4) << 3)) * RP)
                                      + kk + ((lane >> 3) & 1) * 8) * 2;
                ldsm_x4(bfr[jn][0], bfr[jn][1], bfr[jn][2], bfr[jn][3], addr);
            }
#pragma unroll
            for (int im = 0; im < 4; im++)
#pragma unroll
                for (int jn = 0; jn < 2; jn++) {
                    mma_bf16(acc[im][jn * 2 + 0], a[im], bfr[jn][0], bfr[jn][1]);
                    mma_bf16(acc[im][jn * 2 + 1], a[im], bfr[jn][2], bfr[jn][3]);
                }
        }
        if (++buf == 3) buf = 0;
    }
#undef LOAD_TILE

    __nv_bfloat16* Oh = g_xrhi + (size_t)b * CC * HW;
    __nv_bfloat16* Ol = g_xrlo + (size_t)b * CC * HW;
#pragma unroll
    for (int im = 0; im < 4; im++) {
        int row = c0 + wm + im * 16 + (lane >> 2);
#pragma unroll
        for (int j8 = 0; j8 < 4; j8++) {
            int col = n0 + wn + j8 * 8 + (lane & 3) * 2;
            __nv_bfloat16 h0, h1, h2, h3, l0, l1, l2, l3;
            split_val(fmaxf(acc[im][j8][0], 0.f), h0, l0);
            split_val(fmaxf(acc[im][j8][1], 0.f), h1, l1);
            split_val(fmaxf(acc[im][j8][2], 0.f), h2, l2);
            split_val(fmaxf(acc[im][j8][3], 0.f), h3, l3);
            *reinterpret_cast<__nv_bfloat162*>(&Oh[(size_t)row * HW + col]) = __nv_bfloat162{h0, h1};
            *reinterpret_cast<__nv_bfloat162*>(&Ol[(size_t)row * HW + col]) = __nv_bfloat162{l0, l1};
            *reinterpret_cast<__nv_bfloat162*>(&Oh[(size_t)(row + 8) * HW + col]) = __nv_bfloat162{h2, h3};
            *reinterpret_cast<__nv_bfloat162*>(&Ol[(size_t)(row + 8) * HW + col]) = __nv_bfloat162{l2, l3};
        }
    }
}

// ---------------------------------------------------------------------------
// BatchNorm stats / final / z-transpose
// ---------------------------------------------------------------------------
__global__ void bn_stats_kernel(const float* __restrict__ gamma,
                                const float* __restrict__ beta) {
    const int o = blockIdx.x;
    const int tid = threadIdx.x;
    float s = 0.f, s2 = 0.f;
    for (int b = 0; b < BB; b++) {
        const float* p = g_buf1 + (size_t)b * CC * HW + (size_t)o * HW;
        for (int n = tid; n < HW; n += 256) {
            float v = p[n];
            s += v; s2 = fmaf(v, v, s2);
        }
    }
    __shared__ float r1[256], r2[256];
    r1[tid] = s; r2[tid] = s2; __syncthreads();
    for (int st = 128; st > 0; st >>= 1) {
        if (tid < st) { r1[tid] += r1[tid + st]; r2[tid] += r2[tid + st]; }
        __syncthreads();
    }
    if (tid == 0) {
        const float invM = 1.f / (float)(BB * HW);
        float mean = r1[0] * invM;
        float var  = r2[0] * invM - mean * mean;
        float sc = gamma[o] * rsqrtf(var + 1e-5f);
        g_scale[o] = sc;
        g_shift[o] = beta[o] - mean * sc;
    }
}

__global__ void final_kernel(const float* __restrict__ x, float* __restrict__ out) {
    const int b = blockIdx.z, o = blockIdx.y;
    const size_t base = (size_t)b * CC * HW + (size_t)o * HW
                      + (size_t)blockIdx.x * 1024 + (size_t)threadIdx.x * 4;
    const float sc = g_scale[o], sh = g_shift[o];
    float4 v2 = *reinterpret_cast<const float4*>(&g_buf1[base]);
    float4 vx = *reinterpret_cast<const float4*>(&x[base]);
    float4 r;
    r.x = fmaxf(fmaf(v2.x, sc, sh) + vx.x, 0.f);
    r.y = fmaxf(fmaf(v2.y, sc, sh) + vx.y, 0.f);
    r.z = fmaxf(fmaf(v2.z, sc, sh) + vx.z, 0.f);
    r.w = fmaxf(fmaf(v2.w, sc, sh) + vx.w, 0.f);
    *reinterpret_cast<float4*>(&out[base]) = r;
}

__global__ void zt_kernel(float* __restrict__ zt) {
    const int b  = blockIdx.z;
    const int n0 = blockIdx.x * 32;
    const int k0 = blockIdx.y * 32;
    __shared__ float t[32][33];
    const int tx = threadIdx.x, ty = threadIdx.y;
    const float* zb = g_z + (size_t)b * HW * KK;
#pragma unroll
    for (int c = 0; c < 32; c += 8)
        t[ty + c][tx] = zb[(size_t)(n0 + ty + c) * KK + k0 + tx];
    __syncthreads();
    float* ztb = zt + (size_t)b * KK * HW;
#pragma unroll
    for (int c = 0; c < 32; c += 8)
        ztb[(size_t)(k0 + ty + c) * HW + n0 + tx] = t[tx][ty + c];
}

// ---------------------------------------------------------------------------
// Launch
// ---------------------------------------------------------------------------
extern "C" void kernel_launch(void* const* d_in, const int* in_sizes, int n_in,
                              void* d_out, int out_size) {
    const float* x     = (const float*)d_in[0];
    const float* w1    = (const float*)d_in[1];
    const float* b1    = (const float*)d_in[2];
    const float* w2    = (const float*)d_in[3];
    const float* gamma = (const float*)d_in[4];
    const float* beta  = (const float*)d_in[5];
    const float* mu_in = (const float*)d_in[6];

    float* out    = (float*)d_out;
    float* out_mu = out + (size_t)BB * CC * HW;
    float* out_zt = out_mu + (size_t)BB * CC * KK;

    static int smem_set = 0;
    if (!smem_set) {
        cudaFuncSetAttribute(conv_mma_kernel, cudaFuncAttributeMaxDynamicSharedMemorySize, CONV_SMEM);
        smem_set = 1;
    }

    split_w_kernel<<<CC * CC / 256, 256>>>(w1, w2);
    split_x_kernel<<<(BB * CC * HW) / (256 * 4), 256>>>(x);
    copymu_kernel<<<dim3(CC * KK / 256, BB), 256>>>(mu_in);

    // conv1 -> xf splits
    conv_mma_kernel<<<dim3(HW / 128, CC / 128, BB), 256, CONV_SMEM>>>(b1, 0);

    for (int s = 0; s < 3; s++) {
        estep_mma_kernel<<<dim3(HW / 128, BB), 256>>>(s == 2 ? 1 : 0);
        mstep_mma_kernel<<<dim3(CC / 128, SPLIT, BB), 256>>>();
        reduce_l2norm_kernel<<<BB * KK, 128>>>(s == 2 ? out_mu : nullptr);
    }

    recon_mma_kernel<<<dim3(HW / 128, CC / 128, BB), 256>>>();

    // conv2 -> g_buf1 fp32
    conv_mma_kernel<<<dim3(HW / 128, CC / 128, BB), 256, CONV_SMEM>>>(nullptr, 1);

    bn_stats_kernel<<<CC, 256>>>(gamma, beta);
    final_kernel<<<dim3(HW / 1024, CC, BB), 256>>>(x, out);
    zt_kernel<<<dim3(HW / 32, KK / 32, BB), dim3(32, 8)>>>(out_zt);
}